// round 1
// baseline (speedup 1.0000x reference)
#include <cuda_runtime.h>
#include <math.h>
#include <stdio.h>

#define Bt 32
#define Sq 1024
#define Hd 512
#define MPROJ (Bt * Sq)

#define BM 128
#define BN 128
#define BK 8
#define TM 8
#define TN 8
#define PAD 4

// ---- scratch (device globals; no allocations allowed) ----
__device__ float g_Q[(size_t)MPROJ * Hd];
__device__ float g_K[(size_t)MPROJ * Hd];
__device__ float g_V[(size_t)MPROJ * Hd];
__device__ float g_E[(size_t)Bt * Sq * Sq];
__device__ float g_rowsum[MPROJ];
__device__ float g_denom[Bt];

// ============================================================
// C[z] = alpha * A[z](MxK) * B[z](NxK)^T + bias   (K contiguous in both)
// All of M,N divisible by 128; K divisible by 8.
// ============================================================
__global__ __launch_bounds__(256) void gemm_tn(
    const float* __restrict__ A, const float* __restrict__ B,
    const float* __restrict__ bias, float* __restrict__ C,
    int M, int N, int K, float alpha,
    size_t sA, size_t sB, size_t sC)
{
    __shared__ float As[BK][BM + PAD];
    __shared__ float Bs[BK][BN + PAD];
    A += (size_t)blockIdx.z * sA;
    B += (size_t)blockIdx.z * sB;
    C += (size_t)blockIdx.z * sC;

    const int bm = blockIdx.y * BM;
    const int bn = blockIdx.x * BN;
    const int tid = threadIdx.x;

    const int lrow = tid >> 1;        // 0..127
    const int lk   = (tid & 1) * 4;   // 0 or 4
    const int tm = (tid >> 4) * TM;
    const int tn = (tid & 15) * TN;

    const float* Ag = A + (size_t)(bm + lrow) * K + lk;
    const float* Bg = B + (size_t)(bn + lrow) * K + lk;

    float acc[TM][TN];
#pragma unroll
    for (int i = 0; i < TM; i++)
#pragma unroll
        for (int j = 0; j < TN; j++) acc[i][j] = 0.f;

    for (int k0 = 0; k0 < K; k0 += BK) {
        float4 av = *(const float4*)(Ag + k0);
        float4 bv = *(const float4*)(Bg + k0);
        __syncthreads();
        As[lk + 0][lrow] = av.x; As[lk + 1][lrow] = av.y;
        As[lk + 2][lrow] = av.z; As[lk + 3][lrow] = av.w;
        Bs[lk + 0][lrow] = bv.x; Bs[lk + 1][lrow] = bv.y;
        Bs[lk + 2][lrow] = bv.z; Bs[lk + 3][lrow] = bv.w;
        __syncthreads();
#pragma unroll
        for (int kk = 0; kk < BK; kk++) {
            float4 a0 = *(const float4*)&As[kk][tm];
            float4 a1 = *(const float4*)&As[kk][tm + 4];
            float4 b0 = *(const float4*)&Bs[kk][tn];
            float4 b1 = *(const float4*)&Bs[kk][tn + 4];
            float a[8] = {a0.x, a0.y, a0.z, a0.w, a1.x, a1.y, a1.z, a1.w};
            float b[8] = {b0.x, b0.y, b0.z, b0.w, b1.x, b1.y, b1.z, b1.w};
#pragma unroll
            for (int i = 0; i < 8; i++)
#pragma unroll
                for (int j = 0; j < 8; j++)
                    acc[i][j] += a[i] * b[j];
        }
    }

#pragma unroll
    for (int i = 0; i < TM; i++) {
        float4 o0, o1;
        float* cp = C + (size_t)(bm + tm + i) * N + bn + tn;
        float vv[8];
#pragma unroll
        for (int j = 0; j < 8; j++) {
            float v = acc[i][j] * alpha;
            if (bias) v += bias[bn + tn + j];
            vv[j] = v;
        }
        o0 = make_float4(vv[0], vv[1], vv[2], vv[3]);
        o1 = make_float4(vv[4], vv[5], vv[6], vv[7]);
        *(float4*)(cp)     = o0;
        *(float4*)(cp + 4) = o1;
    }
}

// ============================================================
// C[z] = (A[z](MxK) * B[z](KxN)) * (1/denom[z])
// ============================================================
__global__ __launch_bounds__(256) void gemm_nn_div(
    const float* __restrict__ A, const float* __restrict__ B,
    const float* __restrict__ denom, float* __restrict__ C,
    int M, int N, int K,
    size_t sA, size_t sB, size_t sC)
{
    __shared__ float As[BK][BM + PAD];
    __shared__ float Bs[BK][BN + PAD];
    A += (size_t)blockIdx.z * sA;
    B += (size_t)blockIdx.z * sB;
    C += (size_t)blockIdx.z * sC;

    const int bm = blockIdx.y * BM;
    const int bn = blockIdx.x * BN;
    const int tid = threadIdx.x;

    const int larow = tid >> 1;       // A tile: 128 rows x 8 k
    const int lak   = (tid & 1) * 4;
    const int lbrow = tid >> 5;       // B tile: 8 rows x 128 n
    const int lbcol = (tid & 31) * 4;
    const int tm = (tid >> 4) * TM;
    const int tn = (tid & 15) * TN;

    const float* Ag = A + (size_t)(bm + larow) * K + lak;

    float acc[TM][TN];
#pragma unroll
    for (int i = 0; i < TM; i++)
#pragma unroll
        for (int j = 0; j < TN; j++) acc[i][j] = 0.f;

    for (int k0 = 0; k0 < K; k0 += BK) {
        float4 av = *(const float4*)(Ag + k0);
        float4 bv = *(const float4*)(B + (size_t)(k0 + lbrow) * N + bn + lbcol);
        __syncthreads();
        As[lak + 0][larow] = av.x; As[lak + 1][larow] = av.y;
        As[lak + 2][larow] = av.z; As[lak + 3][larow] = av.w;
        *(float4*)&Bs[lbrow][lbcol] = bv;
        __syncthreads();
#pragma unroll
        for (int kk = 0; kk < BK; kk++) {
            float4 a0 = *(const float4*)&As[kk][tm];
            float4 a1 = *(const float4*)&As[kk][tm + 4];
            float4 b0 = *(const float4*)&Bs[kk][tn];
            float4 b1 = *(const float4*)&Bs[kk][tn + 4];
            float a[8] = {a0.x, a0.y, a0.z, a0.w, a1.x, a1.y, a1.z, a1.w};
            float b[8] = {b0.x, b0.y, b0.z, b0.w, b1.x, b1.y, b1.z, b1.w};
#pragma unroll
            for (int i = 0; i < 8; i++)
#pragma unroll
                for (int j = 0; j < 8; j++)
                    acc[i][j] += a[i] * b[j];
        }
    }

    const float inv = 1.0f / denom[blockIdx.z];
#pragma unroll
    for (int i = 0; i < TM; i++) {
        float* cp = C + (size_t)(bm + tm + i) * N + bn + tn;
        float4 o0 = make_float4(acc[i][0] * inv, acc[i][1] * inv,
                                acc[i][2] * inv, acc[i][3] * inv);
        float4 o1 = make_float4(acc[i][4] * inv, acc[i][5] * inv,
                                acc[i][6] * inv, acc[i][7] * inv);
        *(float4*)(cp)     = o0;
        *(float4*)(cp + 4) = o1;
    }
}

// ============================================================
// Per-row softmax over E (in place), multiply by mask, emit row sums.
// One block (256 threads) per row of 1024 elements.
// ============================================================
__global__ __launch_bounds__(256) void softmax_mask(
    const float* __restrict__ mask, float* __restrict__ E,
    float* __restrict__ rowsum)
{
    const int row = blockIdx.x;                 // 0 .. B*S-1
    const size_t off = (size_t)row * Sq;
    const int t = threadIdx.x;
    __shared__ float red[8];

    float4 v = ((const float4*)(E + off))[t];

    // ---- row max ----
    float m = fmaxf(fmaxf(v.x, v.y), fmaxf(v.z, v.w));
#pragma unroll
    for (int o = 16; o; o >>= 1) m = fmaxf(m, __shfl_xor_sync(0xffffffffu, m, o));
    if ((t & 31) == 0) red[t >> 5] = m;
    __syncthreads();
    m = red[0];
#pragma unroll
    for (int i = 1; i < 8; i++) m = fmaxf(m, red[i]);
    __syncthreads();

    // ---- exp & sum ----
    float e0 = expf(v.x - m), e1 = expf(v.y - m);
    float e2 = expf(v.z - m), e3 = expf(v.w - m);
    float s = e0 + e1 + e2 + e3;
#pragma unroll
    for (int o = 16; o; o >>= 1) s += __shfl_xor_sync(0xffffffffu, s, o);
    if ((t & 31) == 0) red[t >> 5] = s;
    __syncthreads();
    float stot = red[0];
#pragma unroll
    for (int i = 1; i < 8; i++) stot += red[i];
    __syncthreads();

    const float inv = 1.0f / stot;
    float4 mk = ((const float4*)(mask + off))[t];
    float4 a;
    a.x = e0 * inv * mk.x;
    a.y = e1 * inv * mk.y;
    a.z = e2 * inv * mk.z;
    a.w = e3 * inv * mk.w;
    ((float4*)(E + off))[t] = a;

    // ---- row sum of A ----
    float rs = a.x + a.y + a.z + a.w;
#pragma unroll
    for (int o = 16; o; o >>= 1) rs += __shfl_xor_sync(0xffffffffu, rs, o);
    if ((t & 31) == 0) red[t >> 5] = rs;
    __syncthreads();
    if (t == 0) {
        float tot = 0.f;
#pragma unroll
        for (int i = 0; i < 8; i++) tot += red[i];
        rowsum[row] = tot;
    }
}

// ============================================================
// denom[b] = sum of 1024 row sums (deterministic, no fp atomics)
// ============================================================
__global__ __launch_bounds__(256) void reduce_denom(
    const float* __restrict__ rowsum, float* __restrict__ denom)
{
    const int b = blockIdx.x;
    const int t = threadIdx.x;
    __shared__ float red[8];
    float s = 0.f;
    for (int i = t; i < Sq; i += 256) s += rowsum[(size_t)b * Sq + i];
#pragma unroll
    for (int o = 16; o; o >>= 1) s += __shfl_xor_sync(0xffffffffu, s, o);
    if ((t & 31) == 0) red[t >> 5] = s;
    __syncthreads();
    if (t == 0) {
        float tot = 0.f;
#pragma unroll
        for (int i = 0; i < 8; i++) tot += red[i];
        denom[b] = tot;
    }
}

// ============================================================
// launch
// ============================================================
extern "C" void kernel_launch(void* const* d_in, const int* in_sizes, int n_in,
                              void* d_out, int out_size)
{
    const float* x    = (const float*)d_in[0];
    const float* mask = (const float*)d_in[1];
    const float* Wq   = (const float*)d_in[2];
    const float* bq   = (const float*)d_in[3];
    const float* Wk   = (const float*)d_in[4];
    const float* bk   = (const float*)d_in[5];
    const float* Wv   = (const float*)d_in[6];
    const float* bv   = (const float*)d_in[7];
    float* out = (float*)d_out;

    float *Q, *K, *V, *E, *rs, *dn;
    cudaGetSymbolAddress((void**)&Q,  g_Q);
    cudaGetSymbolAddress((void**)&K,  g_K);
    cudaGetSymbolAddress((void**)&V,  g_V);
    cudaGetSymbolAddress((void**)&E,  g_E);
    cudaGetSymbolAddress((void**)&rs, g_rowsum);
    cudaGetSymbolAddress((void**)&dn, g_denom);

    // 1) Q/K/V projections: [32768,512] = x[32768,512] @ W[512,512]^T + b
    dim3 gp(Hd / BN, MPROJ / BM, 1);
    gemm_tn<<<gp, 256>>>(x, Wq, bq, Q, MPROJ, Hd, Hd, 1.0f, 0, 0, 0);
    gemm_tn<<<gp, 256>>>(x, Wk, bk, K, MPROJ, Hd, Hd, 1.0f, 0, 0, 0);
    gemm_tn<<<gp, 256>>>(x, Wv, bv, V, MPROJ, Hd, Hd, 1.0f, 0, 0, 0);

    // 2) energy: per batch E = Q @ K^T / sqrt(H)
    const float alpha = 1.0f / sqrtf((float)Hd);
    dim3 ge(Sq / BN, Sq / BM, Bt);
    gemm_tn<<<ge, 256>>>(Q, K, nullptr, E, Sq, Sq, Hd, alpha,
                         (size_t)Sq * Hd, (size_t)Sq * Hd, (size_t)Sq * Sq);

    // 3) softmax + mask (in place on E), per-row sums
    softmax_mask<<<MPROJ, 256>>>(mask, E, rs);

    // 4) per-batch denom
    reduce_denom<<<Bt, 256>>>(rs, dn);

    // 5) out = (A @ V) / denom
    dim3 go(Hd / BN, Sq / BM, Bt);
    gemm_nn_div<<<go, 256>>>(E, V, dn, out, Sq, Hd, Sq,
                             (size_t)Sq * Sq, (size_t)Sq * Hd, (size_t)Sq * Hd);
}

// round 6
// speedup vs baseline: 2.2287x; 2.2287x over previous
#include <cuda_runtime.h>
#include <cuda_bf16.h>
#include <math.h>
#include <stdint.h>

#define Bt 32
#define Sq 1024
#define Hd 512
#define MPROJ (Bt * Sq)

// ---------------- helpers ----------------
__device__ __forceinline__ uint32_t smem_u32(const void* p) {
    uint32_t a;
    asm("{ .reg .u64 t; cvta.to.shared.u64 t, %1; cvt.u32.u64 %0, t; }" : "=r"(a) : "l"(p));
    return a;
}
__device__ __forceinline__ void cp16(uint32_t dst, const void* src) {
    asm volatile("cp.async.cg.shared.global [%0], [%1], 16;" :: "r"(dst), "l"(src));
}
__device__ __forceinline__ void mma16816(float* d, const uint32_t* a, const uint32_t* b) {
    asm volatile(
        "mma.sync.aligned.m16n8k16.row.col.f32.bf16.bf16.f32 "
        "{%0,%1,%2,%3}, {%4,%5,%6,%7}, {%8,%9}, {%0,%1,%2,%3};"
        : "+f"(d[0]), "+f"(d[1]), "+f"(d[2]), "+f"(d[3])
        : "r"(a[0]), "r"(a[1]), "r"(a[2]), "r"(a[3]), "r"(b[0]), "r"(b[1]));
}

// ---------------- scratch (device globals) ----------------
__device__ __nv_bfloat16 g_xhi[(size_t)MPROJ * Hd], g_xlo[(size_t)MPROJ * Hd];
__device__ __nv_bfloat16 g_Wqhi[Hd * Hd], g_Wqlo[Hd * Hd];
__device__ __nv_bfloat16 g_Wkhi[Hd * Hd], g_Wklo[Hd * Hd];
__device__ __nv_bfloat16 g_Wvhi[Hd * Hd], g_Wvlo[Hd * Hd];
__device__ __nv_bfloat16 g_Qhi[(size_t)MPROJ * Hd], g_Qlo[(size_t)MPROJ * Hd];
__device__ __nv_bfloat16 g_Khi[(size_t)MPROJ * Hd], g_Klo[(size_t)MPROJ * Hd];
__device__ float        g_Vf[(size_t)MPROJ * Hd];
__device__ __nv_bfloat16 g_Vthi[(size_t)MPROJ * Hd], g_Vtlo[(size_t)MPROJ * Hd];
__device__ float        g_E[(size_t)Bt * Sq * Sq];
__device__ __nv_bfloat16 g_Ahi[(size_t)Bt * Sq * Sq], g_Alo[(size_t)Bt * Sq * Sq];
__device__ float g_rowsum[MPROJ];
__device__ float g_denom[Bt];

// ---------------- bf16x3 HMMA GEMM ----------------
// C[z][m][n] = scale * sum_k A[z][m][k] * B[z][n][k]   (A,B split hi/lo bf16, K-major)
// Tile: BM=128, BN=256, BK=32. 8 warps, warp tile 64x64.
// Smem per chunk buffer (b32 units, rows padded to 20 b32 = 80 B):
//   Ahi 128x20 = 2560 | Alo 2560 | Bhi 256x20 = 5120 | Blo 5120  -> 15360 b32 = 61440 B
#define BUF32 15360u
#define DYN_BYTES (2u * 61440u)

__device__ __forceinline__ void stage_chunk(
    uint32_t sbase, int t,
    const __nv_bfloat16* __restrict__ Ah, const __nv_bfloat16* __restrict__ Al,
    const __nv_bfloat16* __restrict__ Bh, const __nv_bfloat16* __restrict__ Bl,
    int K, int k0)
{
#pragma unroll
    for (int it = 0; it < 12; ++it) {
        int idx = t + (it << 8);                 // 0..3071 (16B chunks)
        const __nv_bfloat16* src;
        uint32_t dst;
        int row;
        if (it < 2)      { row = idx >> 2;          src = Ah; dst = sbase; }
        else if (it < 4) { row = (idx - 512) >> 2;  src = Al; dst = sbase + 10240u; }
        else if (it < 8) { row = (idx - 1024) >> 2; src = Bh; dst = sbase + 20480u; }
        else             { row = (idx - 2048) >> 2; src = Bl; dst = sbase + 40960u; }
        int ch = idx & 3;
        cp16(dst + (uint32_t)row * 80u + (ch << 4),
             src + (size_t)row * K + k0 + (ch << 3));
    }
}

__global__ void __launch_bounds__(256, 1) gemm_bf16x3(
    const __nv_bfloat16* __restrict__ Ahi, const __nv_bfloat16* __restrict__ Alo, size_t sAz,
    const __nv_bfloat16* __restrict__ Bhi, const __nv_bfloat16* __restrict__ Blo, size_t sBz,
    int K, float alpha, const float* __restrict__ bias, const float* __restrict__ denom,
    int mode,  // 0: fp32 out (*alpha + bias), 1: bf16 hi/lo out (*alpha + bias), 2: fp32 * (1/denom[z])
    float* __restrict__ Cf, __nv_bfloat16* __restrict__ Chi, __nv_bfloat16* __restrict__ Clo,
    size_t sCz, int ldc)
{
    extern __shared__ __align__(16) char dyn[];
    const int t = threadIdx.x;
    const int bm = blockIdx.y << 7;      // *128
    const int bn = blockIdx.x << 8;      // *256
    const int z = blockIdx.z;

    const __nv_bfloat16* pAh = Ahi + (size_t)z * sAz + (size_t)bm * K;
    const __nv_bfloat16* pAl = Alo + (size_t)z * sAz + (size_t)bm * K;
    const __nv_bfloat16* pBh = Bhi + (size_t)z * sBz + (size_t)bn * K;
    const __nv_bfloat16* pBl = Blo + (size_t)z * sBz + (size_t)bn * K;

    const uint32_t sb = smem_u32(dyn);
    const uint32_t* S32 = (const uint32_t*)dyn;

    const int lane = t & 31, warp = t >> 5;
    const int wm = (warp & 1) << 6;      // 0 / 64
    const int wn = (warp >> 1) << 6;     // 0 / 64 / 128 / 192
    const int g = lane >> 2, q = lane & 3;

    float acc[4][8][4];
#pragma unroll
    for (int i = 0; i < 4; i++)
#pragma unroll
        for (int j = 0; j < 8; j++)
#pragma unroll
            for (int k = 0; k < 4; k++) acc[i][j][k] = 0.f;

    const int NC = K >> 5;

    stage_chunk(sb, t, pAh, pAl, pBh, pBl, K, 0);
    asm volatile("cp.async.commit_group;");

    for (int c = 0; c < NC; ++c) {
        if (c + 1 < NC) {
            stage_chunk(sb + ((c + 1) & 1) * 61440u, t, pAh, pAl, pBh, pBl, K, (c + 1) << 5);
            asm volatile("cp.async.commit_group;");
            asm volatile("cp.async.wait_group 1;" ::: "memory");
        } else {
            asm volatile("cp.async.wait_group 0;" ::: "memory");
        }
        __syncthreads();

        const uint32_t* Ah32 = S32 + (c & 1) * BUF32;
        const uint32_t* Al32 = Ah32 + 2560;
        const uint32_t* Bh32 = Ah32 + 5120;
        const uint32_t* Bl32 = Ah32 + 10240;

#pragma unroll
        for (int ks = 0; ks < 2; ++ks) {
            const int cb = (ks << 3) + q;
            uint32_t ah[4][4], al[4][4], bh[8][2], bl[8][2];
#pragma unroll
            for (int i = 0; i < 4; ++i) {
                const uint32_t* p = Ah32 + (wm + (i << 4) + g) * 20 + cb;
                ah[i][0] = p[0]; ah[i][1] = p[160]; ah[i][2] = p[4]; ah[i][3] = p[164];
            }
#pragma unroll
            for (int j = 0; j < 8; ++j) {
                const uint32_t* p = Bh32 + (wn + (j << 3) + g) * 20 + cb;
                bh[j][0] = p[0]; bh[j][1] = p[4];
            }
#pragma unroll
            for (int i = 0; i < 4; ++i)
#pragma unroll
                for (int j = 0; j < 8; ++j)
                    mma16816(acc[i][j], ah[i], bh[j]);
#pragma unroll
            for (int i = 0; i < 4; ++i) {
                const uint32_t* p = Al32 + (wm + (i << 4) + g) * 20 + cb;
                al[i][0] = p[0]; al[i][1] = p[160]; al[i][2] = p[4]; al[i][3] = p[164];
            }
#pragma unroll
            for (int i = 0; i < 4; ++i)
#pragma unroll
                for (int j = 0; j < 8; ++j)
                    mma16816(acc[i][j], al[i], bh[j]);
#pragma unroll
            for (int j = 0; j < 8; ++j) {
                const uint32_t* p = Bl32 + (wn + (j << 3) + g) * 20 + cb;
                bl[j][0] = p[0]; bl[j][1] = p[4];
            }
#pragma unroll
            for (int i = 0; i < 4; ++i)
#pragma unroll
                for (int j = 0; j < 8; ++j)
                    mma16816(acc[i][j], ah[i], bl[j]);
        }
        __syncthreads();
    }

    // ---- epilogue ----
    const float sc = (mode == 2) ? (1.0f / denom[z]) : alpha;
    const size_t zoff = (size_t)z * sCz;
#pragma unroll
    for (int i = 0; i < 4; ++i) {
#pragma unroll
        for (int j = 0; j < 8; ++j) {
            const int r = bm + wm + (i << 4) + g;
            const int cix = bn + wn + (j << 3) + (q << 1);
            float v0 = acc[i][j][0] * sc, v1 = acc[i][j][1] * sc;
            float v2 = acc[i][j][2] * sc, v3 = acc[i][j][3] * sc;
            if (bias && mode != 2) {
                const float b0 = bias[cix], b1 = bias[cix + 1];
                v0 += b0; v1 += b1; v2 += b0; v3 += b1;
            }
            const size_t o0 = zoff + (size_t)r * ldc + cix;
            const size_t o1 = zoff + (size_t)(r + 8) * ldc + cix;
            if (mode == 1) {
                __nv_bfloat16 h0 = __float2bfloat16(v0), h1 = __float2bfloat16(v1);
                __nv_bfloat16 h2 = __float2bfloat16(v2), h3 = __float2bfloat16(v3);
                __nv_bfloat162 hp0; hp0.x = h0; hp0.y = h1;
                __nv_bfloat162 hp1; hp1.x = h2; hp1.y = h3;
                __nv_bfloat162 lp0, lp1;
                lp0.x = __float2bfloat16(v0 - __bfloat162float(h0));
                lp0.y = __float2bfloat16(v1 - __bfloat162float(h1));
                lp1.x = __float2bfloat16(v2 - __bfloat162float(h2));
                lp1.y = __float2bfloat16(v3 - __bfloat162float(h3));
                *(__nv_bfloat162*)(Chi + o0) = hp0;
                *(__nv_bfloat162*)(Chi + o1) = hp1;
                *(__nv_bfloat162*)(Clo + o0) = lp0;
                *(__nv_bfloat162*)(Clo + o1) = lp1;
            } else {
                float2 f0; f0.x = v0; f0.y = v1;
                float2 f1; f1.x = v2; f1.y = v3;
                *(float2*)(Cf + o0) = f0;
                *(float2*)(Cf + o1) = f1;
            }
        }
    }
}

// ---------------- aux kernels ----------------
__global__ __launch_bounds__(256) void convert_split(
    const float* __restrict__ src, __nv_bfloat16* __restrict__ hi,
    __nv_bfloat16* __restrict__ lo, int n4)
{
    int i = blockIdx.x * 256 + threadIdx.x;
    if (i >= n4) return;
    float4 v = ((const float4*)src)[i];
    __nv_bfloat16 h0 = __float2bfloat16(v.x), h1 = __float2bfloat16(v.y);
    __nv_bfloat16 h2 = __float2bfloat16(v.z), h3 = __float2bfloat16(v.w);
    __nv_bfloat162 hp0; hp0.x = h0; hp0.y = h1;
    __nv_bfloat162 hp1; hp1.x = h2; hp1.y = h3;
    __nv_bfloat162 lp0, lp1;
    lp0.x = __float2bfloat16(v.x - __bfloat162float(h0));
    lp0.y = __float2bfloat16(v.y - __bfloat162float(h1));
    lp1.x = __float2bfloat16(v.z - __bfloat162float(h2));
    lp1.y = __float2bfloat16(v.w - __bfloat162float(h3));
    ((__nv_bfloat162*)hi)[2 * i] = hp0; ((__nv_bfloat162*)hi)[2 * i + 1] = hp1;
    ((__nv_bfloat162*)lo)[2 * i] = lp0; ((__nv_bfloat162*)lo)[2 * i + 1] = lp1;
}

// Vt[b][h][s] = V[b*1024+s][h], split hi/lo
__global__ __launch_bounds__(256) void transpose_split(
    const float* __restrict__ V, __nv_bfloat16* __restrict__ Vthi,
    __nv_bfloat16* __restrict__ Vtlo)
{
    __shared__ float tile[32][33];
    const int b = blockIdx.z;
    const int s0 = blockIdx.x << 5, h0 = blockIdx.y << 5;
    const int tx = threadIdx.x & 31, ty = threadIdx.x >> 5;  // 32x8
    const float* Vb = V + (size_t)b * Sq * Hd;
#pragma unroll
    for (int dy = 0; dy < 32; dy += 8)
        tile[ty + dy][tx] = Vb[(size_t)(s0 + ty + dy) * Hd + h0 + tx];
    __syncthreads();
    __nv_bfloat16* Hb = Vthi + (size_t)b * Hd * Sq;
    __nv_bfloat16* Lb = Vtlo + (size_t)b * Hd * Sq;
#pragma unroll
    for (int dy = 0; dy < 32; dy += 8) {
        int h = h0 + ty + dy;
        float v = tile[tx][ty + dy];
        __nv_bfloat16 hi = __float2bfloat16(v);
        Hb[(size_t)h * Sq + s0 + tx] = hi;
        Lb[(size_t)h * Sq + s0 + tx] = __float2bfloat16(v - __bfloat162float(hi));
    }
}

// softmax over E rows, * mask, emit A as bf16 hi/lo + per-row sums
__global__ __launch_bounds__(256) void softmax_mask(
    const float* __restrict__ mask, const float* __restrict__ E,
    __nv_bfloat16* __restrict__ Ahi, __nv_bfloat16* __restrict__ Alo,
    float* __restrict__ rowsum)
{
    const int row = blockIdx.x;
    const size_t off = (size_t)row * Sq;
    const int t = threadIdx.x;
    __shared__ float red[8];

    float4 v = ((const float4*)(E + off))[t];
    float m = fmaxf(fmaxf(v.x, v.y), fmaxf(v.z, v.w));
#pragma unroll
    for (int o = 16; o; o >>= 1) m = fmaxf(m, __shfl_xor_sync(0xffffffffu, m, o));
    if ((t & 31) == 0) red[t >> 5] = m;
    __syncthreads();
    m = red[0];
#pragma unroll
    for (int i = 1; i < 8; i++) m = fmaxf(m, red[i]);
    __syncthreads();

    float e0 = expf(v.x - m), e1 = expf(v.y - m);
    float e2 = expf(v.z - m), e3 = expf(v.w - m);
    float s = e0 + e1 + e2 + e3;
#pragma unroll
    for (int o = 16; o; o >>= 1) s += __shfl_xor_sync(0xffffffffu, s, o);
    if ((t & 31) == 0) red[t >> 5] = s;
    __syncthreads();
    float stot = red[0];
#pragma unroll
    for (int i = 1; i < 8; i++) stot += red[i];
    __syncthreads();

    const float inv = 1.0f / stot;
    float4 mk = ((const float4*)(mask + off))[t];
    float a0 = e0 * inv * mk.x, a1 = e1 * inv * mk.y;
    float a2 = e2 * inv * mk.z, a3 = e3 * inv * mk.w;

    __nv_bfloat16 h0 = __float2bfloat16(a0), h1 = __float2bfloat16(a1);
    __nv_bfloat16 h2 = __float2bfloat16(a2), h3 = __float2bfloat16(a3);
    __nv_bfloat162 hp0; hp0.x = h0; hp0.y = h1;
    __nv_bfloat162 hp1; hp1.x = h2; hp1.y = h3;
    __nv_bfloat162 lp0, lp1;
    lp0.x = __float2bfloat16(a0 - __bfloat162float(h0));
    lp0.y = __float2bfloat16(a1 - __bfloat162float(h1));
    lp1.x = __float2bfloat16(a2 - __bfloat162float(h2));
    lp1.y = __float2bfloat16(a3 - __bfloat162float(h3));
    ((__nv_bfloat162*)(Ahi + off))[2 * t] = hp0;
    ((__nv_bfloat162*)(Ahi + off))[2 * t + 1] = hp1;
    ((__nv_bfloat162*)(Alo + off))[2 * t] = lp0;
    ((__nv_bfloat162*)(Alo + off))[2 * t + 1] = lp1;

    float rs = a0 + a1 + a2 + a3;
#pragma unroll
    for (int o = 16; o; o >>= 1) rs += __shfl_xor_sync(0xffffffffu, rs, o);
    if ((t & 31) == 0) red[t >> 5] = rs;
    __syncthreads();
    if (t == 0) {
        float tot = 0.f;
#pragma unroll
        for (int i = 0; i < 8; i++) tot += red[i];
        rowsum[row] = tot;
    }
}

__global__ __launch_bounds__(256) void reduce_denom(
    const float* __restrict__ rowsum, float* __restrict__ denom)
{
    const int b = blockIdx.x;
    const int t = threadIdx.x;
    __shared__ float red[8];
    float s = 0.f;
    for (int i = t; i < Sq; i += 256) s += rowsum[(size_t)b * Sq + i];
#pragma unroll
    for (int o = 16; o; o >>= 1) s += __shfl_xor_sync(0xffffffffu, s, o);
    if ((t & 31) == 0) red[t >> 5] = s;
    __syncthreads();
    if (t == 0) {
        float tot = 0.f;
#pragma unroll
        for (int i = 0; i < 8; i++) tot += red[i];
        denom[b] = tot;
    }
}

// ---------------- launch ----------------
extern "C" void kernel_launch(void* const* d_in, const int* in_sizes, int n_in,
                              void* d_out, int out_size)
{
    const float* x    = (const float*)d_in[0];
    const float* mask = (const float*)d_in[1];
    const float* Wq   = (const float*)d_in[2];
    const float* bq   = (const float*)d_in[3];
    const float* Wk   = (const float*)d_in[4];
    const float* bk   = (const float*)d_in[5];
    const float* Wv   = (const float*)d_in[6];
    const float* bv   = (const float*)d_in[7];
    float* out = (float*)d_out;

    __nv_bfloat16 *xhi, *xlo, *Wqhi, *Wqlo, *Wkhi, *Wklo, *Wvhi, *Wvlo;
    __nv_bfloat16 *Qhi, *Qlo, *Khi, *Klo, *Vthi, *Vtlo, *Ahi, *Alo;
    float *Vf, *E, *rs, *dn;
    cudaGetSymbolAddress((void**)&xhi, g_xhi);   cudaGetSymbolAddress((void**)&xlo, g_xlo);
    cudaGetSymbolAddress((void**)&Wqhi, g_Wqhi); cudaGetSymbolAddress((void**)&Wqlo, g_Wqlo);
    cudaGetSymbolAddress((void**)&Wkhi, g_Wkhi); cudaGetSymbolAddress((void**)&Wklo, g_Wklo);
    cudaGetSymbolAddress((void**)&Wvhi, g_Wvhi); cudaGetSymbolAddress((void**)&Wvlo, g_Wvlo);
    cudaGetSymbolAddress((void**)&Qhi, g_Qhi);   cudaGetSymbolAddress((void**)&Qlo, g_Qlo);
    cudaGetSymbolAddress((void**)&Khi, g_Khi);   cudaGetSymbolAddress((void**)&Klo, g_Klo);
    cudaGetSymbolAddress((void**)&Vf, g_Vf);
    cudaGetSymbolAddress((void**)&Vthi, g_Vthi); cudaGetSymbolAddress((void**)&Vtlo, g_Vtlo);
    cudaGetSymbolAddress((void**)&E, g_E);
    cudaGetSymbolAddress((void**)&Ahi, g_Ahi);   cudaGetSymbolAddress((void**)&Alo, g_Alo);
    cudaGetSymbolAddress((void**)&rs, g_rowsum); cudaGetSymbolAddress((void**)&dn, g_denom);

    cudaFuncSetAttribute(gemm_bf16x3, cudaFuncAttributeMaxDynamicSharedMemorySize, DYN_BYTES);

    // 0) splits
    convert_split<<<(MPROJ * Hd / 4 + 255) / 256, 256>>>(x, xhi, xlo, MPROJ * Hd / 4);
    convert_split<<<(Hd * Hd / 4 + 255) / 256, 256>>>(Wq, Wqhi, Wqlo, Hd * Hd / 4);
    convert_split<<<(Hd * Hd / 4 + 255) / 256, 256>>>(Wk, Wkhi, Wklo, Hd * Hd / 4);
    convert_split<<<(Hd * Hd / 4 + 255) / 256, 256>>>(Wv, Wvhi, Wvlo, Hd * Hd / 4);

    // 1) projections  M=32768 N=512 K=512   (BN=256 -> grid.x = 2)
    dim3 gp(Hd / 256, MPROJ / 128, 1);
    gemm_bf16x3<<<gp, 256, DYN_BYTES>>>(xhi, xlo, 0, Wqhi, Wqlo, 0, Hd, 1.0f, bq, nullptr,
                                        1, nullptr, Qhi, Qlo, 0, Hd);
    gemm_bf16x3<<<gp, 256, DYN_BYTES>>>(xhi, xlo, 0, Wkhi, Wklo, 0, Hd, 1.0f, bk, nullptr,
                                        1, nullptr, Khi, Klo, 0, Hd);
    gemm_bf16x3<<<gp, 256, DYN_BYTES>>>(xhi, xlo, 0, Wvhi, Wvlo, 0, Hd, 1.0f, bv, nullptr,
                                        0, Vf, nullptr, nullptr, 0, Hd);

    // 2) V transpose + split
    transpose_split<<<dim3(Sq / 32, Hd / 32, Bt), 256>>>(Vf, Vthi, Vtlo);

    // 3) energy  per batch M=N=1024 K=512, alpha = 1/sqrt(H)
    dim3 ge(Sq / 256, Sq / 128, Bt);
    gemm_bf16x3<<<ge, 256, DYN_BYTES>>>(Qhi, Qlo, (size_t)Sq * Hd, Khi, Klo, (size_t)Sq * Hd,
                                        Hd, 1.0f / sqrtf((float)Hd), nullptr, nullptr,
                                        0, E, nullptr, nullptr, (size_t)Sq * Sq, Sq);

    // 4) softmax + mask -> A hi/lo + rowsums
    softmax_mask<<<MPROJ, 256>>>(mask, E, Ahi, Alo, rs);
    reduce_denom<<<Bt, 256>>>(rs, dn);

    // 5) out = (A @ V) / denom   per batch M=1024 N=512 K=1024
    dim3 go(Hd / 256, Sq / 128, Bt);
    gemm_bf16x3<<<go, 256, DYN_BYTES>>>(Ahi, Alo, (size_t)Sq * Sq, Vthi, Vtlo, (size_t)Hd * Sq,
                                        Sq, 1.0f, nullptr, dn,
                                        2, out, nullptr, nullptr, (size_t)Sq * Hd, Hd);
}

// round 8
// speedup vs baseline: 2.2685x; 1.0178x over previous
#include <cuda_runtime.h>
#include <cuda_bf16.h>
#include <math.h>
#include <stdint.h>

#define Bt 32
#define Sq 1024
#define Hd 512
#define MPROJ (Bt * Sq)

// ---------------- helpers ----------------
__device__ __forceinline__ uint32_t smem_u32(const void* p) {
    uint32_t a;
    asm("{ .reg .u64 t; cvta.to.shared.u64 t, %1; cvt.u32.u64 %0, t; }" : "=r"(a) : "l"(p));
    return a;
}
__device__ __forceinline__ void cp16(uint32_t dst, const void* src) {
    asm volatile("cp.async.cg.shared.global [%0], [%1], 16;" :: "r"(dst), "l"(src));
}
__device__ __forceinline__ void mma16816(float* d, const uint32_t* a, const uint32_t* b) {
    asm volatile(
        "mma.sync.aligned.m16n8k16.row.col.f32.bf16.bf16.f32 "
        "{%0,%1,%2,%3}, {%4,%5,%6,%7}, {%8,%9}, {%0,%1,%2,%3};"
        : "+f"(d[0]), "+f"(d[1]), "+f"(d[2]), "+f"(d[3])
        : "r"(a[0]), "r"(a[1]), "r"(a[2]), "r"(a[3]), "r"(b[0]), "r"(b[1]));
}
__device__ __forceinline__ void ldsm4(uint32_t addr, uint32_t* r) {
    asm volatile("ldmatrix.sync.aligned.m8n8.x4.shared.b16 {%0,%1,%2,%3}, [%4];"
                 : "=r"(r[0]), "=r"(r[1]), "=r"(r[2]), "=r"(r[3]) : "r"(addr));
}

// ---------------- scratch (device globals) ----------------
__device__ __nv_bfloat16 g_xhi[(size_t)MPROJ * Hd], g_xlo[(size_t)MPROJ * Hd];
__device__ __nv_bfloat16 g_Wqhi[Hd * Hd], g_Wqlo[Hd * Hd];
__device__ __nv_bfloat16 g_Wkhi[Hd * Hd], g_Wklo[Hd * Hd];
__device__ __nv_bfloat16 g_Wvhi[Hd * Hd], g_Wvlo[Hd * Hd];
__device__ __nv_bfloat16 g_Qhi[(size_t)MPROJ * Hd], g_Qlo[(size_t)MPROJ * Hd];
__device__ __nv_bfloat16 g_Khi[(size_t)MPROJ * Hd], g_Klo[(size_t)MPROJ * Hd];
__device__ float        g_Vf[(size_t)MPROJ * Hd];
__device__ __nv_bfloat16 g_Vthi[(size_t)MPROJ * Hd], g_Vtlo[(size_t)MPROJ * Hd];
__device__ float        g_E[(size_t)Bt * Sq * Sq];
__device__ __nv_bfloat16 g_Ahi[(size_t)Bt * Sq * Sq], g_Alo[(size_t)Bt * Sq * Sq];
__device__ float g_rowsum[MPROJ];
__device__ float g_denom[Bt];

// ---------------- bf16x3 HMMA GEMM ----------------
// C[z][m][n] = scale * sum_k A[z][m][k] * B[z][n][k]   (A,B split hi/lo bf16, K-major)
// Tile: BM=128, BN=256, BK=32. 8 warps, warp tile 64x64.
// Smem per chunk buffer (rows padded to 20 b32 = 80 B):
//   Ahi 128x20 | Alo | Bhi 256x20 | Blo  -> 15360 b32 = 61440 B
#define BUF32 15360u
#define DYN_BYTES (2u * 61440u)

__device__ __forceinline__ void stage_chunk(
    uint32_t sbase, int t,
    const __nv_bfloat16* __restrict__ Ah, const __nv_bfloat16* __restrict__ Al,
    const __nv_bfloat16* __restrict__ Bh, const __nv_bfloat16* __restrict__ Bl,
    int K, int k0)
{
#pragma unroll
    for (int it = 0; it < 12; ++it) {
        int idx = t + (it << 8);                 // 0..3071 (16B chunks)
        const __nv_bfloat16* src;
        uint32_t dst;
        int row;
        if (it < 2)      { row = idx >> 2;          src = Ah; dst = sbase; }
        else if (it < 4) { row = (idx - 512) >> 2;  src = Al; dst = sbase + 10240u; }
        else if (it < 8) { row = (idx - 1024) >> 2; src = Bh; dst = sbase + 20480u; }
        else             { row = (idx - 2048) >> 2; src = Bl; dst = sbase + 40960u; }
        int ch = idx & 3;
        cp16(dst + (uint32_t)row * 80u + (ch << 4),
             src + (size_t)row * K + k0 + (ch << 3));
    }
}

__global__ void __launch_bounds__(256, 1) gemm_bf16x3(
    const __nv_bfloat16* __restrict__ Ahi, const __nv_bfloat16* __restrict__ Alo, size_t sAz,
    const __nv_bfloat16* __restrict__ Bhi, const __nv_bfloat16* __restrict__ Blo, size_t sBz,
    int K, float alpha, const float* __restrict__ bias, const float* __restrict__ denom,
    int mode,  // 0: fp32 out (*alpha + bias), 1: bf16 hi/lo out (*alpha + bias), 2: fp32 * (1/denom[z])
    float* __restrict__ Cf, __nv_bfloat16* __restrict__ Chi, __nv_bfloat16* __restrict__ Clo,
    size_t sCz, int ldc)
{
    extern __shared__ __align__(16) char dyn[];
    const int t = threadIdx.x;
    const int bm = blockIdx.y << 7;      // *128
    const int bn = blockIdx.x << 8;      // *256
    const int z = blockIdx.z;

    const __nv_bfloat16* pAh = Ahi + (size_t)z * sAz + (size_t)bm * K;
    const __nv_bfloat16* pAl = Alo + (size_t)z * sAz + (size_t)bm * K;
    const __nv_bfloat16* pBh = Bhi + (size_t)z * sBz + (size_t)bn * K;
    const __nv_bfloat16* pBl = Blo + (size_t)z * sBz + (size_t)bn * K;

    const uint32_t sb = smem_u32(dyn);

    const int lane = t & 31, warp = t >> 5;
    const int wm = (warp & 1) << 6;      // 0 / 64
    const int wn = (warp >> 1) << 6;     // 0 / 64 / 128 / 192
    const int g = lane >> 2, q = lane & 3;

    // ldmatrix per-thread address components (byte offsets within a tile)
    //   A x4 (16x16): row = lane%16, k-half = lane/16
    const uint32_t aoff = (uint32_t)(lane & 15) * 80u + (uint32_t)(lane >> 4) * 16u;
    //   B x4 (two n8 x k16): n = (lane&7) + ((lane>>4)&1)*8, k-half = (lane>>3)&1
    const uint32_t boff = ((uint32_t)((lane & 7) + ((lane >> 4) & 1) * 8)) * 80u
                        + ((uint32_t)((lane >> 3) & 1)) * 16u;

    float acc[4][8][4];
#pragma unroll
    for (int i = 0; i < 4; i++)
#pragma unroll
        for (int j = 0; j < 8; j++)
#pragma unroll
            for (int k = 0; k < 4; k++) acc[i][j][k] = 0.f;

    const int NC = K >> 5;

    stage_chunk(sb, t, pAh, pAl, pBh, pBl, K, 0);
    asm volatile("cp.async.commit_group;");

    for (int c = 0; c < NC; ++c) {
        if (c + 1 < NC) {
            stage_chunk(sb + ((c + 1) & 1) * 61440u, t, pAh, pAl, pBh, pBl, K, (c + 1) << 5);
            asm volatile("cp.async.commit_group;");
            asm volatile("cp.async.wait_group 1;" ::: "memory");
        } else {
            asm volatile("cp.async.wait_group 0;" ::: "memory");
        }
        __syncthreads();

        const uint32_t bufA = sb + (c & 1) * 61440u;   // Ahi
        const uint32_t aA = bufA + (uint32_t)wm * 80u + aoff;
        const uint32_t aB = bufA + 20480u + (uint32_t)wn * 80u + boff;

#pragma unroll
        for (int ks = 0; ks < 2; ++ks) {
            const uint32_t kb = (uint32_t)ks << 5;      // ks*32 bytes
            uint32_t ah[4][4], al[4][4], bh[8][2], bl[8][2];
#pragma unroll
            for (int i = 0; i < 4; ++i)
                ldsm4(aA + (uint32_t)(i << 4) * 80u + kb, ah[i]);
#pragma unroll
            for (int jp = 0; jp < 4; ++jp)
                ldsm4(aB + (uint32_t)(jp << 4) * 80u + kb, &bh[jp << 1][0]);
#pragma unroll
            for (int i = 0; i < 4; ++i)
#pragma unroll
                for (int j = 0; j < 8; ++j)
                    mma16816(acc[i][j], ah[i], bh[j]);
#pragma unroll
            for (int i = 0; i < 4; ++i)
                ldsm4(aA + 10240u + (uint32_t)(i << 4) * 80u + kb, al[i]);
#pragma unroll
            for (int i = 0; i < 4; ++i)
#pragma unroll
                for (int j = 0; j < 8; ++j)
                    mma16816(acc[i][j], al[i], bh[j]);
#pragma unroll
            for (int jp = 0; jp < 4; ++jp)
                ldsm4(aB + 20480u + (uint32_t)(jp << 4) * 80u + kb, &bl[jp << 1][0]);
#pragma unroll
            for (int i = 0; i < 4; ++i)
#pragma unroll
                for (int j = 0; j < 8; ++j)
                    mma16816(acc[i][j], ah[i], bl[j]);
        }
        __syncthreads();
    }

    // ---- epilogue ----
    const float sc = (mode == 2) ? (1.0f / denom[z]) : alpha;
    const size_t zoff = (size_t)z * sCz;
#pragma unroll
    for (int i = 0; i < 4; ++i) {
#pragma unroll
        for (int j = 0; j < 8; ++j) {
            const int r = bm + wm + (i << 4) + g;
            const int cix = bn + wn + (j << 3) + (q << 1);
            float v0 = acc[i][j][0] * sc, v1 = acc[i][j][1] * sc;
            float v2 = acc[i][j][2] * sc, v3 = acc[i][j][3] * sc;
            if (bias && mode != 2) {
                const float b0 = bias[cix], b1 = bias[cix + 1];
                v0 += b0; v1 += b1; v2 += b0; v3 += b1;
            }
            const size_t o0 = zoff + (size_t)r * ldc + cix;
            const size_t o1 = zoff + (size_t)(r + 8) * ldc + cix;
            if (mode == 1) {
                __nv_bfloat16 h0 = __float2bfloat16(v0), h1 = __float2bfloat16(v1);
                __nv_bfloat16 h2 = __float2bfloat16(v2), h3 = __float2bfloat16(v3);
                __nv_bfloat162 hp0; hp0.x = h0; hp0.y = h1;
                __nv_bfloat162 hp1; hp1.x = h2; hp1.y = h3;
                __nv_bfloat162 lp0, lp1;
                lp0.x = __float2bfloat16(v0 - __bfloat162float(h0));
                lp0.y = __float2bfloat16(v1 - __bfloat162float(h1));
                lp1.x = __float2bfloat16(v2 - __bfloat162float(h2));
                lp1.y = __float2bfloat16(v3 - __bfloat162float(h3));
                *(__nv_bfloat162*)(Chi + o0) = hp0;
                *(__nv_bfloat162*)(Chi + o1) = hp1;
                *(__nv_bfloat162*)(Clo + o0) = lp0;
                *(__nv_bfloat162*)(Clo + o1) = lp1;
            } else {
                float2 f0; f0.x = v0; f0.y = v1;
                float2 f1; f1.x = v2; f1.y = v3;
                *(float2*)(Cf + o0) = f0;
                *(float2*)(Cf + o1) = f1;
            }
        }
    }
}

// ---------------- aux kernels ----------------
__global__ __launch_bounds__(256) void convert_split(
    const float* __restrict__ src, __nv_bfloat16* __restrict__ hi,
    __nv_bfloat16* __restrict__ lo, int n4)
{
    int i = blockIdx.x * 256 + threadIdx.x;
    if (i >= n4) return;
    float4 v = ((const float4*)src)[i];
    __nv_bfloat16 h0 = __float2bfloat16(v.x), h1 = __float2bfloat16(v.y);
    __nv_bfloat16 h2 = __float2bfloat16(v.z), h3 = __float2bfloat16(v.w);
    __nv_bfloat162 hp0; hp0.x = h0; hp0.y = h1;
    __nv_bfloat162 hp1; hp1.x = h2; hp1.y = h3;
    __nv_bfloat162 lp0, lp1;
    lp0.x = __float2bfloat16(v.x - __bfloat162float(h0));
    lp0.y = __float2bfloat16(v.y - __bfloat162float(h1));
    lp1.x = __float2bfloat16(v.z - __bfloat162float(h2));
    lp1.y = __float2bfloat16(v.w - __bfloat162float(h3));
    ((__nv_bfloat162*)hi)[2 * i] = hp0; ((__nv_bfloat162*)hi)[2 * i + 1] = hp1;
    ((__nv_bfloat162*)lo)[2 * i] = lp0; ((__nv_bfloat162*)lo)[2 * i + 1] = lp1;
}

// Vt[b][h][s] = V[b*1024+s][h], split hi/lo
__global__ __launch_bounds__(256) void transpose_split(
    const float* __restrict__ V, __nv_bfloat16* __restrict__ Vthi,
    __nv_bfloat16* __restrict__ Vtlo)
{
    __shared__ float tile[32][33];
    const int b = blockIdx.z;
    const int s0 = blockIdx.x << 5, h0 = blockIdx.y << 5;
    const int tx = threadIdx.x & 31, ty = threadIdx.x >> 5;  // 32x8
    const float* Vb = V + (size_t)b * Sq * Hd;
#pragma unroll
    for (int dy = 0; dy < 32; dy += 8)
        tile[ty + dy][tx] = Vb[(size_t)(s0 + ty + dy) * Hd + h0 + tx];
    __syncthreads();
    __nv_bfloat16* Hb = Vthi + (size_t)b * Hd * Sq;
    __nv_bfloat16* Lb = Vtlo + (size_t)b * Hd * Sq;
#pragma unroll
    for (int dy = 0; dy < 32; dy += 8) {
        int h = h0 + ty + dy;
        float v = tile[tx][ty + dy];
        __nv_bfloat16 hi = __float2bfloat16(v);
        Hb[(size_t)h * Sq + s0 + tx] = hi;
        Lb[(size_t)h * Sq + s0 + tx] = __float2bfloat16(v - __bfloat162float(hi));
    }
}

// softmax over E rows, * mask, emit A as bf16 hi/lo + per-row sums
__global__ __launch_bounds__(256) void softmax_mask(
    const float* __restrict__ mask, const float* __restrict__ E,
    __nv_bfloat16* __restrict__ Ahi, __nv_bfloat16* __restrict__ Alo,
    float* __restrict__ rowsum)
{
    const int row = blockIdx.x;
    const size_t off = (size_t)row * Sq;
    const int t = threadIdx.x;
    __shared__ float red[8];

    float4 v = ((const float4*)(E + off))[t];
    float m = fmaxf(fmaxf(v.x, v.y), fmaxf(v.z, v.w));
#pragma unroll
    for (int o = 16; o; o >>= 1) m = fmaxf(m, __shfl_xor_sync(0xffffffffu, m, o));
    if ((t & 31) == 0) red[t >> 5] = m;
    __syncthreads();
    m = red[0];
#pragma unroll
    for (int i = 1; i < 8; i++) m = fmaxf(m, red[i]);
    __syncthreads();

    float e0 = expf(v.x - m), e1 = expf(v.y - m);
    float e2 = expf(v.z - m), e3 = expf(v.w - m);
    float s = e0 + e1 + e2 + e3;
#pragma unroll
    for (int o = 16; o; o >>= 1) s += __shfl_xor_sync(0xffffffffu, s, o);
    if ((t & 31) == 0) red[t >> 5] = s;
    __syncthreads();
    float stot = red[0];
#pragma unroll
    for (int i = 1; i < 8; i++) stot += red[i];
    __syncthreads();

    const float inv = 1.0f / stot;
    float4 mk = ((const float4*)(mask + off))[t];
    float a0 = e0 * inv * mk.x, a1 = e1 * inv * mk.y;
    float a2 = e2 * inv * mk.z, a3 = e3 * inv * mk.w;

    __nv_bfloat16 h0 = __float2bfloat16(a0), h1 = __float2bfloat16(a1);
    __nv_bfloat16 h2 = __float2bfloat16(a2), h3 = __float2bfloat16(a3);
    __nv_bfloat162 hp0; hp0.x = h0; hp0.y = h1;
    __nv_bfloat162 hp1; hp1.x = h2; hp1.y = h3;
    __nv_bfloat162 lp0, lp1;
    lp0.x = __float2bfloat16(a0 - __bfloat162float(h0));
    lp0.y = __float2bfloat16(a1 - __bfloat162float(h1));
    lp1.x = __float2bfloat16(a2 - __bfloat162float(h2));
    lp1.y = __float2bfloat16(a3 - __bfloat162float(h3));
    ((__nv_bfloat162*)(Ahi + off))[2 * t] = hp0;
    ((__nv_bfloat162*)(Ahi + off))[2 * t + 1] = hp1;
    ((__nv_bfloat162*)(Alo + off))[2 * t] = lp0;
    ((__nv_bfloat162*)(Alo + off))[2 * t + 1] = lp1;

    float rs = a0 + a1 + a2 + a3;
#pragma unroll
    for (int o = 16; o; o >>= 1) rs += __shfl_xor_sync(0xffffffffu, rs, o);
    if ((t & 31) == 0) red[t >> 5] = rs;
    __syncthreads();
    if (t == 0) {
        float tot = 0.f;
#pragma unroll
        for (int i = 0; i < 8; i++) tot += red[i];
        rowsum[row] = tot;
    }
}

__global__ __launch_bounds__(256) void reduce_denom(
    const float* __restrict__ rowsum, float* __restrict__ denom)
{
    const int b = blockIdx.x;
    const int t = threadIdx.x;
    __shared__ float red[8];
    float s = 0.f;
    for (int i = t; i < Sq; i += 256) s += rowsum[(size_t)b * Sq + i];
#pragma unroll
    for (int o = 16; o; o >>= 1) s += __shfl_xor_sync(0xffffffffu, s, o);
    if ((t & 31) == 0) red[t >> 5] = s;
    __syncthreads();
    if (t == 0) {
        float tot = 0.f;
#pragma unroll
        for (int i = 0; i < 8; i++) tot += red[i];
        denom[b] = tot;
    }
}

// ---------------- launch ----------------
extern "C" void kernel_launch(void* const* d_in, const int* in_sizes, int n_in,
                              void* d_out, int out_size)
{
    const float* x    = (const float*)d_in[0];
    const float* mask = (const float*)d_in[1];
    const float* Wq   = (const float*)d_in[2];
    const float* bq   = (const float*)d_in[3];
    const float* Wk   = (const float*)d_in[4];
    const float* bk   = (const float*)d_in[5];
    const float* Wv   = (const float*)d_in[6];
    const float* bv   = (const float*)d_in[7];
    float* out = (float*)d_out;

    __nv_bfloat16 *xhi, *xlo, *Wqhi, *Wqlo, *Wkhi, *Wklo, *Wvhi, *Wvlo;
    __nv_bfloat16 *Qhi, *Qlo, *Khi, *Klo, *Vthi, *Vtlo, *Ahi, *Alo;
    float *Vf, *E, *rs, *dn;
    cudaGetSymbolAddress((void**)&xhi, g_xhi);   cudaGetSymbolAddress((void**)&xlo, g_xlo);
    cudaGetSymbolAddress((void**)&Wqhi, g_Wqhi); cudaGetSymbolAddress((void**)&Wqlo, g_Wqlo);
    cudaGetSymbolAddress((void**)&Wkhi, g_Wkhi); cudaGetSymbolAddress((void**)&Wklo, g_Wklo);
    cudaGetSymbolAddress((void**)&Wvhi, g_Wvhi); cudaGetSymbolAddress((void**)&Wvlo, g_Wvlo);
    cudaGetSymbolAddress((void**)&Qhi, g_Qhi);   cudaGetSymbolAddress((void**)&Qlo, g_Qlo);
    cudaGetSymbolAddress((void**)&Khi, g_Khi);   cudaGetSymbolAddress((void**)&Klo, g_Klo);
    cudaGetSymbolAddress((void**)&Vf, g_Vf);
    cudaGetSymbolAddress((void**)&Vthi, g_Vthi); cudaGetSymbolAddress((void**)&Vtlo, g_Vtlo);
    cudaGetSymbolAddress((void**)&E, g_E);
    cudaGetSymbolAddress((void**)&Ahi, g_Ahi);   cudaGetSymbolAddress((void**)&Alo, g_Alo);
    cudaGetSymbolAddress((void**)&rs, g_rowsum); cudaGetSymbolAddress((void**)&dn, g_denom);

    cudaFuncSetAttribute(gemm_bf16x3, cudaFuncAttributeMaxDynamicSharedMemorySize, DYN_BYTES);

    // 0) splits
    convert_split<<<(MPROJ * Hd / 4 + 255) / 256, 256>>>(x, xhi, xlo, MPROJ * Hd / 4);
    convert_split<<<(Hd * Hd / 4 + 255) / 256, 256>>>(Wq, Wqhi, Wqlo, Hd * Hd / 4);
    convert_split<<<(Hd * Hd / 4 + 255) / 256, 256>>>(Wk, Wkhi, Wklo, Hd * Hd / 4);
    convert_split<<<(Hd * Hd / 4 + 255) / 256, 256>>>(Wv, Wvhi, Wvlo, Hd * Hd / 4);

    // 1) projections  M=32768 N=512 K=512   (BN=256 -> grid.x = 2)
    dim3 gp(Hd / 256, MPROJ / 128, 1);
    gemm_bf16x3<<<gp, 256, DYN_BYTES>>>(xhi, xlo, 0, Wqhi, Wqlo, 0, Hd, 1.0f, bq, nullptr,
                                        1, nullptr, Qhi, Qlo, 0, Hd);
    gemm_bf16x3<<<gp, 256, DYN_BYTES>>>(xhi, xlo, 0, Wkhi, Wklo, 0, Hd, 1.0f, bk, nullptr,
                                        1, nullptr, Khi, Klo, 0, Hd);
    gemm_bf16x3<<<gp, 256, DYN_BYTES>>>(xhi, xlo, 0, Wvhi, Wvlo, 0, Hd, 1.0f, bv, nullptr,
                                        0, Vf, nullptr, nullptr, 0, Hd);

    // 2) V transpose + split
    transpose_split<<<dim3(Sq / 32, Hd / 32, Bt), 256>>>(Vf, Vthi, Vtlo);

    // 3) energy  per batch M=N=1024 K=512, alpha = 1/sqrt(H)
    dim3 ge(Sq / 256, Sq / 128, Bt);
    gemm_bf16x3<<<ge, 256, DYN_BYTES>>>(Qhi, Qlo, (size_t)Sq * Hd, Khi, Klo, (size_t)Sq * Hd,
                                        Hd, 1.0f / sqrtf((float)Hd), nullptr, nullptr,
                                        0, E, nullptr, nullptr, (size_t)Sq * Sq, Sq);

    // 4) softmax + mask -> A hi/lo + rowsums
    softmax_mask<<<MPROJ, 256>>>(mask, E, Ahi, Alo, rs);
    reduce_denom<<<Bt, 256>>>(rs, dn);

    // 5) out = (A @ V) / denom   per batch M=1024 N=512 K=1024
    dim3 go(Hd / 256, Sq / 128, Bt);
    gemm_bf16x3<<<go, 256, DYN_BYTES>>>(Ahi, Alo, (size_t)Sq * Sq, Vthi, Vtlo, (size_t)Hd * Sq,
                                        Sq, 1.0f, nullptr, dn,
                                        2, out, nullptr, nullptr, (size_t)Sq * Hd, Hd);
}

// round 9
// speedup vs baseline: 2.5954x; 1.1441x over previous
#include <cuda_runtime.h>
#include <cuda_bf16.h>
#include <math.h>
#include <stdint.h>

#define Bt 32
#define Sq 1024
#define Hd 512
#define MPROJ (Bt * Sq)

// ---------------- helpers ----------------
__device__ __forceinline__ uint32_t smem_u32(const void* p) {
    uint32_t a;
    asm("{ .reg .u64 t; cvta.to.shared.u64 t, %1; cvt.u32.u64 %0, t; }" : "=r"(a) : "l"(p));
    return a;
}
__device__ __forceinline__ void cp16(uint32_t dst, const void* src) {
    asm volatile("cp.async.cg.shared.global [%0], [%1], 16;" :: "r"(dst), "l"(src));
}
__device__ __forceinline__ void mma16816(float* d, const uint32_t* a, const uint32_t* b) {
    asm volatile(
        "mma.sync.aligned.m16n8k16.row.col.f32.bf16.bf16.f32 "
        "{%0,%1,%2,%3}, {%4,%5,%6,%7}, {%8,%9}, {%0,%1,%2,%3};"
        : "+f"(d[0]), "+f"(d[1]), "+f"(d[2]), "+f"(d[3])
        : "r"(a[0]), "r"(a[1]), "r"(a[2]), "r"(a[3]), "r"(b[0]), "r"(b[1]));
}
__device__ __forceinline__ void ldsm4(uint32_t addr, uint32_t* r) {
    asm volatile("ldmatrix.sync.aligned.m8n8.x4.shared.b16 {%0,%1,%2,%3}, [%4];"
                 : "=r"(r[0]), "=r"(r[1]), "=r"(r[2]), "=r"(r[3]) : "r"(addr));
}

// ---------------- scratch (device globals) ----------------
__device__ __nv_bfloat16 g_xhi[(size_t)MPROJ * Hd], g_xlo[(size_t)MPROJ * Hd];
__device__ __nv_bfloat16 g_Wqhi[Hd * Hd], g_Wqlo[Hd * Hd];
__device__ __nv_bfloat16 g_Wkhi[Hd * Hd], g_Wklo[Hd * Hd];
__device__ __nv_bfloat16 g_Wvhi[Hd * Hd], g_Wvlo[Hd * Hd];
__device__ __nv_bfloat16 g_Qhi[(size_t)MPROJ * Hd], g_Qlo[(size_t)MPROJ * Hd];
__device__ __nv_bfloat16 g_Khi[(size_t)MPROJ * Hd], g_Klo[(size_t)MPROJ * Hd];
__device__ float        g_Vf[(size_t)MPROJ * Hd];
__device__ __nv_bfloat16 g_Vthi[(size_t)MPROJ * Hd], g_Vtlo[(size_t)MPROJ * Hd];
__device__ float        g_E[(size_t)Bt * Sq * Sq];
__device__ __nv_bfloat16 g_Ahi[(size_t)Bt * Sq * Sq], g_Alo[(size_t)Bt * Sq * Sq];
__device__ float g_rowsum[MPROJ];
__device__ float g_denom[Bt];

// ---------------- bf16x3 HMMA GEMM ----------------
// C[z][m][n] = scale * sum_k A[z][m][k] * B[z][n][k]   (A,B split hi/lo bf16, K-major)
// Tile: BM=128, BN=128, BK=32. 8 warps, warp tile 64x32. 2 CTAs/SM.
// Smem per stage (rows padded to 20 b32 = 80 B):
//   Ahi 128x80B | Alo | Bhi | Blo  -> 40960 B; double buffered = 81920 B
#define STG_BYTES 40960u
#define TILE_BYTES 10240u
#define DYN_BYTES (2u * STG_BYTES)

__device__ __forceinline__ void stage_chunk(
    uint32_t sbase, int t,
    const __nv_bfloat16* __restrict__ Ah, const __nv_bfloat16* __restrict__ Al,
    const __nv_bfloat16* __restrict__ Bh, const __nv_bfloat16* __restrict__ Bl,
    int K, int k0)
{
#pragma unroll
    for (int it = 0; it < 8; ++it) {
        // idx = t + it*256; tile = it>>1 (const), within = ((it&1)<<8)+t
        const int tile = it >> 1;
        const int within = ((it & 1) << 8) + t;   // 0..511
        const int row = within >> 2, ch = within & 3;
        const __nv_bfloat16* src =
            (tile == 0) ? Ah : (tile == 1) ? Al : (tile == 2) ? Bh : Bl;
        cp16(sbase + (uint32_t)tile * TILE_BYTES + (uint32_t)row * 80u + (ch << 4),
             src + (size_t)row * K + k0 + (ch << 3));
    }
}

__global__ void __launch_bounds__(256, 2) gemm_bf16x3(
    const __nv_bfloat16* __restrict__ Ahi, const __nv_bfloat16* __restrict__ Alo, size_t sAz,
    const __nv_bfloat16* __restrict__ Bhi, const __nv_bfloat16* __restrict__ Blo, size_t sBz,
    int K, float alpha, const float* __restrict__ bias, const float* __restrict__ denom,
    int mode,  // 0: fp32 out (*alpha + bias), 1: bf16 hi/lo out (*alpha + bias), 2: fp32 * (1/denom[z])
    float* __restrict__ Cf, __nv_bfloat16* __restrict__ Chi, __nv_bfloat16* __restrict__ Clo,
    size_t sCz, int ldc)
{
    extern __shared__ __align__(16) char dyn[];
    const int t = threadIdx.x;
    const int bm = blockIdx.y << 7;      // *128
    const int bn = blockIdx.x << 7;      // *128
    const int z = blockIdx.z;

    const __nv_bfloat16* pAh = Ahi + (size_t)z * sAz + (size_t)bm * K;
    const __nv_bfloat16* pAl = Alo + (size_t)z * sAz + (size_t)bm * K;
    const __nv_bfloat16* pBh = Bhi + (size_t)z * sBz + (size_t)bn * K;
    const __nv_bfloat16* pBl = Blo + (size_t)z * sBz + (size_t)bn * K;

    const uint32_t sb = smem_u32(dyn);

    const int lane = t & 31, warp = t >> 5;
    const int wm = (warp & 1) << 6;      // 0 / 64
    const int wn = (warp >> 1) << 5;     // 0 / 32 / 64 / 96
    const int g = lane >> 2, q = lane & 3;

    // ldmatrix per-thread address components (byte offsets within a tile)
    //   A x4 (16x16): row = lane%16, k-half = lane/16
    const uint32_t aoff = (uint32_t)(lane & 15) * 80u + (uint32_t)(lane >> 4) * 16u;
    //   B x4 (two n8 x k16): n = (lane&7) + ((lane>>4)&1)*8, k-half = (lane>>3)&1
    const uint32_t boff = ((uint32_t)((lane & 7) + ((lane >> 4) & 1) * 8)) * 80u
                        + ((uint32_t)((lane >> 3) & 1)) * 16u;

    float acc[4][4][4];
#pragma unroll
    for (int i = 0; i < 4; i++)
#pragma unroll
        for (int j = 0; j < 4; j++)
#pragma unroll
            for (int k = 0; k < 4; k++) acc[i][j][k] = 0.f;

    const int NC = K >> 5;

    stage_chunk(sb, t, pAh, pAl, pBh, pBl, K, 0);
    asm volatile("cp.async.commit_group;");

    for (int c = 0; c < NC; ++c) {
        if (c + 1 < NC) {
            stage_chunk(sb + ((c + 1) & 1) * STG_BYTES, t, pAh, pAl, pBh, pBl, K, (c + 1) << 5);
            asm volatile("cp.async.commit_group;");
            asm volatile("cp.async.wait_group 1;" ::: "memory");
        } else {
            asm volatile("cp.async.wait_group 0;" ::: "memory");
        }
        __syncthreads();

        const uint32_t bufA = sb + (c & 1) * STG_BYTES;          // Ahi
        const uint32_t aA = bufA + (uint32_t)wm * 80u + aoff;
        const uint32_t aB = bufA + 2u * TILE_BYTES + (uint32_t)wn * 80u + boff;

#pragma unroll
        for (int ks = 0; ks < 2; ++ks) {
            const uint32_t kb = (uint32_t)ks << 5;      // ks*32 bytes
            uint32_t ah[4][4], al[4][4], bh[4][2], bl[4][2];
            // pass 1: Ahi x Bhi
#pragma unroll
            for (int i = 0; i < 4; ++i)
                ldsm4(aA + (uint32_t)(i << 4) * 80u + kb, ah[i]);
#pragma unroll
            for (int jp = 0; jp < 2; ++jp)
                ldsm4(aB + (uint32_t)(jp << 4) * 80u + kb, &bh[jp << 1][0]);
#pragma unroll
            for (int i = 0; i < 4; ++i)
#pragma unroll
                for (int j = 0; j < 4; ++j)
                    mma16816(acc[i][j], ah[i], bh[j]);
            // pass 2: Ahi x Blo
#pragma unroll
            for (int jp = 0; jp < 2; ++jp)
                ldsm4(aB + TILE_BYTES + (uint32_t)(jp << 4) * 80u + kb, &bl[jp << 1][0]);
#pragma unroll
            for (int i = 0; i < 4; ++i)
#pragma unroll
                for (int j = 0; j < 4; ++j)
                    mma16816(acc[i][j], ah[i], bl[j]);
            // pass 3: Alo x Bhi
#pragma unroll
            for (int i = 0; i < 4; ++i)
                ldsm4(aA + TILE_BYTES + (uint32_t)(i << 4) * 80u + kb, al[i]);
#pragma unroll
            for (int i = 0; i < 4; ++i)
#pragma unroll
                for (int j = 0; j < 4; ++j)
                    mma16816(acc[i][j], al[i], bh[j]);
        }
        __syncthreads();
    }

    // ---- epilogue ----
    const float sc = (mode == 2) ? (1.0f / denom[z]) : alpha;
    const size_t zoff = (size_t)z * sCz;
#pragma unroll
    for (int i = 0; i < 4; ++i) {
#pragma unroll
        for (int j = 0; j < 4; ++j) {
            const int r = bm + wm + (i << 4) + g;
            const int cix = bn + wn + (j << 3) + (q << 1);
            float v0 = acc[i][j][0] * sc, v1 = acc[i][j][1] * sc;
            float v2 = acc[i][j][2] * sc, v3 = acc[i][j][3] * sc;
            if (bias && mode != 2) {
                const float b0 = bias[cix], b1 = bias[cix + 1];
                v0 += b0; v1 += b1; v2 += b0; v3 += b1;
            }
            const size_t o0 = zoff + (size_t)r * ldc + cix;
            const size_t o1 = zoff + (size_t)(r + 8) * ldc + cix;
            if (mode == 1) {
                __nv_bfloat16 h0 = __float2bfloat16(v0), h1 = __float2bfloat16(v1);
                __nv_bfloat16 h2 = __float2bfloat16(v2), h3 = __float2bfloat16(v3);
                __nv_bfloat162 hp0; hp0.x = h0; hp0.y = h1;
                __nv_bfloat162 hp1; hp1.x = h2; hp1.y = h3;
                __nv_bfloat162 lp0, lp1;
                lp0.x = __float2bfloat16(v0 - __bfloat162float(h0));
                lp0.y = __float2bfloat16(v1 - __bfloat162float(h1));
                lp1.x = __float2bfloat16(v2 - __bfloat162float(h2));
                lp1.y = __float2bfloat16(v3 - __bfloat162float(h3));
                *(__nv_bfloat162*)(Chi + o0) = hp0;
                *(__nv_bfloat162*)(Chi + o1) = hp1;
                *(__nv_bfloat162*)(Clo + o0) = lp0;
                *(__nv_bfloat162*)(Clo + o1) = lp1;
            } else {
                float2 f0; f0.x = v0; f0.y = v1;
                float2 f1; f1.x = v2; f1.y = v3;
                *(float2*)(Cf + o0) = f0;
                *(float2*)(Cf + o1) = f1;
            }
        }
    }
}

// ---------------- aux kernels ----------------
__global__ __launch_bounds__(256) void convert_split(
    const float* __restrict__ src, __nv_bfloat16* __restrict__ hi,
    __nv_bfloat16* __restrict__ lo, int n4)
{
    int i = blockIdx.x * 256 + threadIdx.x;
    if (i >= n4) return;
    float4 v = ((const float4*)src)[i];
    __nv_bfloat16 h0 = __float2bfloat16(v.x), h1 = __float2bfloat16(v.y);
    __nv_bfloat16 h2 = __float2bfloat16(v.z), h3 = __float2bfloat16(v.w);
    __nv_bfloat162 hp0; hp0.x = h0; hp0.y = h1;
    __nv_bfloat162 hp1; hp1.x = h2; hp1.y = h3;
    __nv_bfloat162 lp0, lp1;
    lp0.x = __float2bfloat16(v.x - __bfloat162float(h0));
    lp0.y = __float2bfloat16(v.y - __bfloat162float(h1));
    lp1.x = __float2bfloat16(v.z - __bfloat162float(h2));
    lp1.y = __float2bfloat16(v.w - __bfloat162float(h3));
    ((__nv_bfloat162*)hi)[2 * i] = hp0; ((__nv_bfloat162*)hi)[2 * i + 1] = hp1;
    ((__nv_bfloat162*)lo)[2 * i] = lp0; ((__nv_bfloat162*)lo)[2 * i + 1] = lp1;
}

// Vt[b][h][s] = V[b*1024+s][h], split hi/lo
__global__ __launch_bounds__(256) void transpose_split(
    const float* __restrict__ V, __nv_bfloat16* __restrict__ Vthi,
    __nv_bfloat16* __restrict__ Vtlo)
{
    __shared__ float tile[32][33];
    const int b = blockIdx.z;
    const int s0 = blockIdx.x << 5, h0 = blockIdx.y << 5;
    const int tx = threadIdx.x & 31, ty = threadIdx.x >> 5;  // 32x8
    const float* Vb = V + (size_t)b * Sq * Hd;
#pragma unroll
    for (int dy = 0; dy < 32; dy += 8)
        tile[ty + dy][tx] = Vb[(size_t)(s0 + ty + dy) * Hd + h0 + tx];
    __syncthreads();
    __nv_bfloat16* Hb = Vthi + (size_t)b * Hd * Sq;
    __nv_bfloat16* Lb = Vtlo + (size_t)b * Hd * Sq;
#pragma unroll
    for (int dy = 0; dy < 32; dy += 8) {
        int h = h0 + ty + dy;
        float v = tile[tx][ty + dy];
        __nv_bfloat16 hi = __float2bfloat16(v);
        Hb[(size_t)h * Sq + s0 + tx] = hi;
        Lb[(size_t)h * Sq + s0 + tx] = __float2bfloat16(v - __bfloat162float(hi));
    }
}

// softmax over E rows, * mask, emit A as bf16 hi/lo + per-row sums
__global__ __launch_bounds__(256) void softmax_mask(
    const float* __restrict__ mask, const float* __restrict__ E,
    __nv_bfloat16* __restrict__ Ahi, __nv_bfloat16* __restrict__ Alo,
    float* __restrict__ rowsum)
{
    const int row = blockIdx.x;
    const size_t off = (size_t)row * Sq;
    const int t = threadIdx.x;
    __shared__ float red[8];

    float4 v = ((const float4*)(E + off))[t];
    float m = fmaxf(fmaxf(v.x, v.y), fmaxf(v.z, v.w));
#pragma unroll
    for (int o = 16; o; o >>= 1) m = fmaxf(m, __shfl_xor_sync(0xffffffffu, m, o));
    if ((t & 31) == 0) red[t >> 5] = m;
    __syncthreads();
    m = red[0];
#pragma unroll
    for (int i = 1; i < 8; i++) m = fmaxf(m, red[i]);
    __syncthreads();

    float e0 = expf(v.x - m), e1 = expf(v.y - m);
    float e2 = expf(v.z - m), e3 = expf(v.w - m);
    float s = e0 + e1 + e2 + e3;
#pragma unroll
    for (int o = 16; o; o >>= 1) s += __shfl_xor_sync(0xffffffffu, s, o);
    if ((t & 31) == 0) red[t >> 5] = s;
    __syncthreads();
    float stot = red[0];
#pragma unroll
    for (int i = 1; i < 8; i++) stot += red[i];
    __syncthreads();

    const float inv = 1.0f / stot;
    float4 mk = ((const float4*)(mask + off))[t];
    float a0 = e0 * inv * mk.x, a1 = e1 * inv * mk.y;
    float a2 = e2 * inv * mk.z, a3 = e3 * inv * mk.w;

    __nv_bfloat16 h0 = __float2bfloat16(a0), h1 = __float2bfloat16(a1);
    __nv_bfloat16 h2 = __float2bfloat16(a2), h3 = __float2bfloat16(a3);
    __nv_bfloat162 hp0; hp0.x = h0; hp0.y = h1;
    __nv_bfloat162 hp1; hp1.x = h2; hp1.y = h3;
    __nv_bfloat162 lp0, lp1;
    lp0.x = __float2bfloat16(a0 - __bfloat162float(h0));
    lp0.y = __float2bfloat16(a1 - __bfloat162float(h1));
    lp1.x = __float2bfloat16(a2 - __bfloat162float(h2));
    lp1.y = __float2bfloat16(a3 - __bfloat162float(h3));
    ((__nv_bfloat162*)(Ahi + off))[2 * t] = hp0;
    ((__nv_bfloat162*)(Ahi + off))[2 * t + 1] = hp1;
    ((__nv_bfloat162*)(Alo + off))[2 * t] = lp0;
    ((__nv_bfloat162*)(Alo + off))[2 * t + 1] = lp1;

    float rs = a0 + a1 + a2 + a3;
#pragma unroll
    for (int o = 16; o; o >>= 1) rs += __shfl_xor_sync(0xffffffffu, rs, o);
    if ((t & 31) == 0) red[t >> 5] = rs;
    __syncthreads();
    if (t == 0) {
        float tot = 0.f;
#pragma unroll
        for (int i = 0; i < 8; i++) tot += red[i];
        rowsum[row] = tot;
    }
}

__global__ __launch_bounds__(256) void reduce_denom(
    const float* __restrict__ rowsum, float* __restrict__ denom)
{
    const int b = blockIdx.x;
    const int t = threadIdx.x;
    __shared__ float red[8];
    float s = 0.f;
    for (int i = t; i < Sq; i += 256) s += rowsum[(size_t)b * Sq + i];
#pragma unroll
    for (int o = 16; o; o >>= 1) s += __shfl_xor_sync(0xffffffffu, s, o);
    if ((t & 31) == 0) red[t >> 5] = s;
    __syncthreads();
    if (t == 0) {
        float tot = 0.f;
#pragma unroll
        for (int i = 0; i < 8; i++) tot += red[i];
        denom[b] = tot;
    }
}

// ---------------- launch ----------------
extern "C" void kernel_launch(void* const* d_in, const int* in_sizes, int n_in,
                              void* d_out, int out_size)
{
    const float* x    = (const float*)d_in[0];
    const float* mask = (const float*)d_in[1];
    const float* Wq   = (const float*)d_in[2];
    const float* bq   = (const float*)d_in[3];
    const float* Wk   = (const float*)d_in[4];
    const float* bk   = (const float*)d_in[5];
    const float* Wv   = (const float*)d_in[6];
    const float* bv   = (const float*)d_in[7];
    float* out = (float*)d_out;

    __nv_bfloat16 *xhi, *xlo, *Wqhi, *Wqlo, *Wkhi, *Wklo, *Wvhi, *Wvlo;
    __nv_bfloat16 *Qhi, *Qlo, *Khi, *Klo, *Vthi, *Vtlo, *Ahi, *Alo;
    float *Vf, *E, *rs, *dn;
    cudaGetSymbolAddress((void**)&xhi, g_xhi);   cudaGetSymbolAddress((void**)&xlo, g_xlo);
    cudaGetSymbolAddress((void**)&Wqhi, g_Wqhi); cudaGetSymbolAddress((void**)&Wqlo, g_Wqlo);
    cudaGetSymbolAddress((void**)&Wkhi, g_Wkhi); cudaGetSymbolAddress((void**)&Wklo, g_Wklo);
    cudaGetSymbolAddress((void**)&Wvhi, g_Wvhi); cudaGetSymbolAddress((void**)&Wvlo, g_Wvlo);
    cudaGetSymbolAddress((void**)&Qhi, g_Qhi);   cudaGetSymbolAddress((void**)&Qlo, g_Qlo);
    cudaGetSymbolAddress((void**)&Khi, g_Khi);   cudaGetSymbolAddress((void**)&Klo, g_Klo);
    cudaGetSymbolAddress((void**)&Vf, g_Vf);
    cudaGetSymbolAddress((void**)&Vthi, g_Vthi); cudaGetSymbolAddress((void**)&Vtlo, g_Vtlo);
    cudaGetSymbolAddress((void**)&E, g_E);
    cudaGetSymbolAddress((void**)&Ahi, g_Ahi);   cudaGetSymbolAddress((void**)&Alo, g_Alo);
    cudaGetSymbolAddress((void**)&rs, g_rowsum); cudaGetSymbolAddress((void**)&dn, g_denom);

    cudaFuncSetAttribute(gemm_bf16x3, cudaFuncAttributeMaxDynamicSharedMemorySize, DYN_BYTES);

    // 0) splits
    convert_split<<<(MPROJ * Hd / 4 + 255) / 256, 256>>>(x, xhi, xlo, MPROJ * Hd / 4);
    convert_split<<<(Hd * Hd / 4 + 255) / 256, 256>>>(Wq, Wqhi, Wqlo, Hd * Hd / 4);
    convert_split<<<(Hd * Hd / 4 + 255) / 256, 256>>>(Wk, Wkhi, Wklo, Hd * Hd / 4);
    convert_split<<<(Hd * Hd / 4 + 255) / 256, 256>>>(Wv, Wvhi, Wvlo, Hd * Hd / 4);

    // 1) projections  M=32768 N=512 K=512   (BN=128 -> grid.x = 4)
    dim3 gp(Hd / 128, MPROJ / 128, 1);
    gemm_bf16x3<<<gp, 256, DYN_BYTES>>>(xhi, xlo, 0, Wqhi, Wqlo, 0, Hd, 1.0f, bq, nullptr,
                                        1, nullptr, Qhi, Qlo, 0, Hd);
    gemm_bf16x3<<<gp, 256, DYN_BYTES>>>(xhi, xlo, 0, Wkhi, Wklo, 0, Hd, 1.0f, bk, nullptr,
                                        1, nullptr, Khi, Klo, 0, Hd);
    gemm_bf16x3<<<gp, 256, DYN_BYTES>>>(xhi, xlo, 0, Wvhi, Wvlo, 0, Hd, 1.0f, bv, nullptr,
                                        0, Vf, nullptr, nullptr, 0, Hd);

    // 2) V transpose + split
    transpose_split<<<dim3(Sq / 32, Hd / 32, Bt), 256>>>(Vf, Vthi, Vtlo);

    // 3) energy  per batch M=N=1024 K=512, alpha = 1/sqrt(H)
    dim3 ge(Sq / 128, Sq / 128, Bt);
    gemm_bf16x3<<<ge, 256, DYN_BYTES>>>(Qhi, Qlo, (size_t)Sq * Hd, Khi, Klo, (size_t)Sq * Hd,
                                        Hd, 1.0f / sqrtf((float)Hd), nullptr, nullptr,
                                        0, E, nullptr, nullptr, (size_t)Sq * Sq, Sq);

    // 4) softmax + mask -> A hi/lo + rowsums
    softmax_mask<<<MPROJ, 256>>>(mask, E, Ahi, Alo, rs);
    reduce_denom<<<Bt, 256>>>(rs, dn);

    // 5) out = (A @ V) / denom   per batch M=1024 N=512 K=1024
    dim3 go(Hd / 128, Sq / 128, Bt);
    gemm_bf16x3<<<go, 256, DYN_BYTES>>>(Ahi, Alo, (size_t)Sq * Sq, Vthi, Vtlo, (size_t)Hd * Sq,
                                        Sq, 1.0f, nullptr, dn,
                                        2, out, nullptr, nullptr, (size_t)Sq * Hd, Hd);
}

// round 10
// speedup vs baseline: 3.5858x; 1.3816x over previous
#include <cuda_runtime.h>
#include <cuda_fp16.h>
#include <math.h>
#include <stdint.h>

#define Bt 32
#define Sq 1024
#define Hd 512
#define MPROJ (Bt * Sq)

// ---------------- helpers ----------------
__device__ __forceinline__ uint32_t smem_u32(const void* p) {
    uint32_t a;
    asm("{ .reg .u64 t; cvta.to.shared.u64 t, %1; cvt.u32.u64 %0, t; }" : "=r"(a) : "l"(p));
    return a;
}
__device__ __forceinline__ void cp16(uint32_t dst, const void* src) {
    asm volatile("cp.async.cg.shared.global [%0], [%1], 16;" :: "r"(dst), "l"(src));
}
__device__ __forceinline__ void mma16816(float* d, const uint32_t* a, const uint32_t* b) {
    asm volatile(
        "mma.sync.aligned.m16n8k16.row.col.f32.f16.f16.f32 "
        "{%0,%1,%2,%3}, {%4,%5,%6,%7}, {%8,%9}, {%0,%1,%2,%3};"
        : "+f"(d[0]), "+f"(d[1]), "+f"(d[2]), "+f"(d[3])
        : "r"(a[0]), "r"(a[1]), "r"(a[2]), "r"(a[3]), "r"(b[0]), "r"(b[1]));
}
__device__ __forceinline__ void ldsm4(uint32_t addr, uint32_t* r) {
    asm volatile("ldmatrix.sync.aligned.m8n8.x4.shared.b16 {%0,%1,%2,%3}, [%4];"
                 : "=r"(r[0]), "=r"(r[1]), "=r"(r[2]), "=r"(r[3]) : "r"(addr));
}

// ---------------- scratch (device globals) ----------------
__device__ __half g_xh[(size_t)MPROJ * Hd];
__device__ __half g_Wqhi[Hd * Hd], g_Wqlo[Hd * Hd];
__device__ __half g_Wkhi[Hd * Hd], g_Wklo[Hd * Hd];
__device__ __half g_Wvhi[Hd * Hd], g_Wvlo[Hd * Hd];
__device__ __half g_Qh[(size_t)MPROJ * Hd];
__device__ __half g_Khi[(size_t)MPROJ * Hd], g_Klo[(size_t)MPROJ * Hd];
__device__ float  g_Vf[(size_t)MPROJ * Hd];
__device__ __half g_Vthi[(size_t)MPROJ * Hd], g_Vtlo[(size_t)MPROJ * Hd];
__device__ float  g_E[(size_t)Bt * Sq * Sq];
__device__ __half g_Af[(size_t)Bt * Sq * Sq];
__device__ float g_rowsum[MPROJ];
__device__ float g_denom[Bt];

// ---------------- fp16 2-pass HMMA GEMM ----------------
// C[z][m][n] = scale * sum_k A[z][m][k] * (Bhi+Blo)[z][n][k]   (K-major, fp16)
// Tile: BM=128, BN=128, BK=32. 8 warps, warp tile 64x32. 2 CTAs/SM.
// Smem per stage (rows padded 80 B): A 10240 | Bhi 10240 | Blo 10240 = 30720 B
#define TILE_BYTES 10240u
#define STG_BYTES 30720u
#define DYN_BYTES (2u * STG_BYTES)

__device__ __forceinline__ void stage_chunk(
    uint32_t sbase, int t,
    const __half* __restrict__ A,
    const __half* __restrict__ Bh, const __half* __restrict__ Bl,
    int K, int k0)
{
#pragma unroll
    for (int it = 0; it < 6; ++it) {
        const int tile = it >> 1;
        const int within = ((it & 1) << 8) + t;   // 0..511
        const int row = within >> 2, ch = within & 3;
        const __half* src = (tile == 0) ? A : (tile == 1) ? Bh : Bl;
        cp16(sbase + (uint32_t)tile * TILE_BYTES + (uint32_t)row * 80u + (ch << 4),
             src + (size_t)row * K + k0 + (ch << 3));
    }
}

__global__ void __launch_bounds__(256, 2) gemm_f16x2(
    const __half* __restrict__ A, size_t sAz,
    const __half* __restrict__ Bhi, const __half* __restrict__ Blo, size_t sBz,
    int K, float alpha, const float* __restrict__ bias, const float* __restrict__ denom,
    int mode,  // 0: fp32 out, 1: fp16 single out, 2: fp32 * (1/denom[z]), 3: fp16 hi/lo out
    float* __restrict__ Cf, __half* __restrict__ Chi, __half* __restrict__ Clo,
    size_t sCz, int ldc)
{
    extern __shared__ __align__(16) char dyn[];
    const int t = threadIdx.x;
    const int bm = blockIdx.y << 7;
    const int bn = blockIdx.x << 7;
    const int z = blockIdx.z;

    const __half* pA  = A   + (size_t)z * sAz + (size_t)bm * K;
    const __half* pBh = Bhi + (size_t)z * sBz + (size_t)bn * K;
    const __half* pBl = Blo + (size_t)z * sBz + (size_t)bn * K;

    const uint32_t sb = smem_u32(dyn);

    const int lane = t & 31, warp = t >> 5;
    const int wm = (warp & 1) << 6;      // 0 / 64
    const int wn = (warp >> 1) << 5;     // 0 / 32 / 64 / 96
    const int g = lane >> 2, q = lane & 3;

    //   A x4 (16x16): row = lane%16, k-half = lane/16
    const uint32_t aoff = (uint32_t)(lane & 15) * 80u + (uint32_t)(lane >> 4) * 16u;
    //   B x4 (two n8 x k16): n = (lane&7) + ((lane>>4)&1)*8, k-half = (lane>>3)&1
    const uint32_t boff = ((uint32_t)((lane & 7) + ((lane >> 4) & 1) * 8)) * 80u
                        + ((uint32_t)((lane >> 3) & 1)) * 16u;

    float acc[4][4][4];
#pragma unroll
    for (int i = 0; i < 4; i++)
#pragma unroll
        for (int j = 0; j < 4; j++)
#pragma unroll
            for (int k = 0; k < 4; k++) acc[i][j][k] = 0.f;

    const int NC = K >> 5;

    stage_chunk(sb, t, pA, pBh, pBl, K, 0);
    asm volatile("cp.async.commit_group;");

    for (int c = 0; c < NC; ++c) {
        if (c + 1 < NC) {
            stage_chunk(sb + ((c + 1) & 1) * STG_BYTES, t, pA, pBh, pBl, K, (c + 1) << 5);
            asm volatile("cp.async.commit_group;");
            asm volatile("cp.async.wait_group 1;" ::: "memory");
        } else {
            asm volatile("cp.async.wait_group 0;" ::: "memory");
        }
        __syncthreads();

        const uint32_t bufA = sb + (c & 1) * STG_BYTES;
        const uint32_t aA = bufA + (uint32_t)wm * 80u + aoff;
        const uint32_t aB = bufA + TILE_BYTES + (uint32_t)wn * 80u + boff;

#pragma unroll
        for (int ks = 0; ks < 2; ++ks) {
            const uint32_t kb = (uint32_t)ks << 5;
            uint32_t ah[4][4], bh[4][2], bl[4][2];
#pragma unroll
            for (int i = 0; i < 4; ++i)
                ldsm4(aA + (uint32_t)(i << 4) * 80u + kb, ah[i]);
#pragma unroll
            for (int jp = 0; jp < 2; ++jp)
                ldsm4(aB + (uint32_t)(jp << 4) * 80u + kb, &bh[jp << 1][0]);
#pragma unroll
            for (int i = 0; i < 4; ++i)
#pragma unroll
                for (int j = 0; j < 4; ++j)
                    mma16816(acc[i][j], ah[i], bh[j]);
#pragma unroll
            for (int jp = 0; jp < 2; ++jp)
                ldsm4(aB + TILE_BYTES + (uint32_t)(jp << 4) * 80u + kb, &bl[jp << 1][0]);
#pragma unroll
            for (int i = 0; i < 4; ++i)
#pragma unroll
                for (int j = 0; j < 4; ++j)
                    mma16816(acc[i][j], ah[i], bl[j]);
        }
        __syncthreads();
    }

    // ---- epilogue ----
    const float sc = (mode == 2) ? (1.0f / denom[z]) : alpha;
    const size_t zoff = (size_t)z * sCz;
#pragma unroll
    for (int i = 0; i < 4; ++i) {
#pragma unroll
        for (int j = 0; j < 4; ++j) {
            const int r = bm + wm + (i << 4) + g;
            const int cix = bn + wn + (j << 3) + (q << 1);
            float v0 = acc[i][j][0] * sc, v1 = acc[i][j][1] * sc;
            float v2 = acc[i][j][2] * sc, v3 = acc[i][j][3] * sc;
            if (bias && mode != 2) {
                const float b0 = bias[cix], b1 = bias[cix + 1];
                v0 += b0; v1 += b1; v2 += b0; v3 += b1;
            }
            const size_t o0 = zoff + (size_t)r * ldc + cix;
            const size_t o1 = zoff + (size_t)(r + 8) * ldc + cix;
            if (mode == 1) {
                *(__half2*)(Chi + o0) = __floats2half2_rn(v0, v1);
                *(__half2*)(Chi + o1) = __floats2half2_rn(v2, v3);
            } else if (mode == 3) {
                __half h0 = __float2half(v0), h1 = __float2half(v1);
                __half h2 = __float2half(v2), h3 = __float2half(v3);
                __half2 hp0; hp0.x = h0; hp0.y = h1;
                __half2 hp1; hp1.x = h2; hp1.y = h3;
                __half2 lp0, lp1;
                lp0.x = __float2half(v0 - __half2float(h0));
                lp0.y = __float2half(v1 - __half2float(h1));
                lp1.x = __float2half(v2 - __half2float(h2));
                lp1.y = __float2half(v3 - __half2float(h3));
                *(__half2*)(Chi + o0) = hp0;
                *(__half2*)(Chi + o1) = hp1;
                *(__half2*)(Clo + o0) = lp0;
                *(__half2*)(Clo + o1) = lp1;
            } else {
                float2 f0; f0.x = v0; f0.y = v1;
                float2 f1; f1.x = v2; f1.y = v3;
                *(float2*)(Cf + o0) = f0;
                *(float2*)(Cf + o1) = f1;
            }
        }
    }
}

// ---------------- aux kernels ----------------
__global__ __launch_bounds__(256) void convert_f16(
    const float* __restrict__ src, __half* __restrict__ dst, int n4)
{
    int i = blockIdx.x * 256 + threadIdx.x;
    if (i >= n4) return;
    float4 v = ((const float4*)src)[i];
    ((__half2*)dst)[2 * i]     = __floats2half2_rn(v.x, v.y);
    ((__half2*)dst)[2 * i + 1] = __floats2half2_rn(v.z, v.w);
}

__global__ __launch_bounds__(256) void convert_split_f16(
    const float* __restrict__ src, __half* __restrict__ hi,
    __half* __restrict__ lo, int n4)
{
    int i = blockIdx.x * 256 + threadIdx.x;
    if (i >= n4) return;
    float4 v = ((const float4*)src)[i];
    __half h0 = __float2half(v.x), h1 = __float2half(v.y);
    __half h2 = __float2half(v.z), h3 = __float2half(v.w);
    __half2 hp0; hp0.x = h0; hp0.y = h1;
    __half2 hp1; hp1.x = h2; hp1.y = h3;
    __half2 lp0, lp1;
    lp0.x = __float2half(v.x - __half2float(h0));
    lp0.y = __float2half(v.y - __half2float(h1));
    lp1.x = __float2half(v.z - __half2float(h2));
    lp1.y = __float2half(v.w - __half2float(h3));
    ((__half2*)hi)[2 * i] = hp0; ((__half2*)hi)[2 * i + 1] = hp1;
    ((__half2*)lo)[2 * i] = lp0; ((__half2*)lo)[2 * i + 1] = lp1;
}

// Vt[b][h][s] = V[b*1024+s][h], split hi/lo fp16
__global__ __launch_bounds__(256) void transpose_split(
    const float* __restrict__ V, __half* __restrict__ Vthi,
    __half* __restrict__ Vtlo)
{
    __shared__ float tile[32][33];
    const int b = blockIdx.z;
    const int s0 = blockIdx.x << 5, h0 = blockIdx.y << 5;
    const int tx = threadIdx.x & 31, ty = threadIdx.x >> 5;  // 32x8
    const float* Vb = V + (size_t)b * Sq * Hd;
#pragma unroll
    for (int dy = 0; dy < 32; dy += 8)
        tile[ty + dy][tx] = Vb[(size_t)(s0 + ty + dy) * Hd + h0 + tx];
    __syncthreads();
    __half* Hb = Vthi + (size_t)b * Hd * Sq;
    __half* Lb = Vtlo + (size_t)b * Hd * Sq;
#pragma unroll
    for (int dy = 0; dy < 32; dy += 8) {
        int h = h0 + ty + dy;
        float v = tile[tx][ty + dy];
        __half hi = __float2half(v);
        Hb[(size_t)h * Sq + s0 + tx] = hi;
        Lb[(size_t)h * Sq + s0 + tx] = __float2half(v - __half2float(hi));
    }
}

// softmax over E rows, * mask, emit A as fp16 + per-row sums
__global__ __launch_bounds__(256) void softmax_mask(
    const float* __restrict__ mask, const float* __restrict__ E,
    __half* __restrict__ Af, float* __restrict__ rowsum)
{
    const int row = blockIdx.x;
    const size_t off = (size_t)row * Sq;
    const int t = threadIdx.x;
    __shared__ float red[8];

    float4 v = ((const float4*)(E + off))[t];
    float m = fmaxf(fmaxf(v.x, v.y), fmaxf(v.z, v.w));
#pragma unroll
    for (int o = 16; o; o >>= 1) m = fmaxf(m, __shfl_xor_sync(0xffffffffu, m, o));
    if ((t & 31) == 0) red[t >> 5] = m;
    __syncthreads();
    m = red[0];
#pragma unroll
    for (int i = 1; i < 8; i++) m = fmaxf(m, red[i]);
    __syncthreads();

    float e0 = expf(v.x - m), e1 = expf(v.y - m);
    float e2 = expf(v.z - m), e3 = expf(v.w - m);
    float s = e0 + e1 + e2 + e3;
#pragma unroll
    for (int o = 16; o; o >>= 1) s += __shfl_xor_sync(0xffffffffu, s, o);
    if ((t & 31) == 0) red[t >> 5] = s;
    __syncthreads();
    float stot = red[0];
#pragma unroll
    for (int i = 1; i < 8; i++) stot += red[i];
    __syncthreads();

    const float inv = 1.0f / stot;
    float4 mk = ((const float4*)(mask + off))[t];
    float a0 = e0 * inv * mk.x, a1 = e1 * inv * mk.y;
    float a2 = e2 * inv * mk.z, a3 = e3 * inv * mk.w;

    ((__half2*)(Af + off))[2 * t]     = __floats2half2_rn(a0, a1);
    ((__half2*)(Af + off))[2 * t + 1] = __floats2half2_rn(a2, a3);

    float rs = a0 + a1 + a2 + a3;
#pragma unroll
    for (int o = 16; o; o >>= 1) rs += __shfl_xor_sync(0xffffffffu, rs, o);
    if ((t & 31) == 0) red[t >> 5] = rs;
    __syncthreads();
    if (t == 0) {
        float tot = 0.f;
#pragma unroll
        for (int i = 0; i < 8; i++) tot += red[i];
        rowsum[row] = tot;
    }
}

__global__ __launch_bounds__(256) void reduce_denom(
    const float* __restrict__ rowsum, float* __restrict__ denom)
{
    const int b = blockIdx.x;
    const int t = threadIdx.x;
    __shared__ float red[8];
    float s = 0.f;
    for (int i = t; i < Sq; i += 256) s += rowsum[(size_t)b * Sq + i];
#pragma unroll
    for (int o = 16; o; o >>= 1) s += __shfl_xor_sync(0xffffffffu, s, o);
    if ((t & 31) == 0) red[t >> 5] = s;
    __syncthreads();
    if (t == 0) {
        float tot = 0.f;
#pragma unroll
        for (int i = 0; i < 8; i++) tot += red[i];
        denom[b] = tot;
    }
}

// ---------------- launch ----------------
extern "C" void kernel_launch(void* const* d_in, const int* in_sizes, int n_in,
                              void* d_out, int out_size)
{
    const float* x    = (const float*)d_in[0];
    const float* mask = (const float*)d_in[1];
    const float* Wq   = (const float*)d_in[2];
    const float* bq   = (const float*)d_in[3];
    const float* Wk   = (const float*)d_in[4];
    const float* bk   = (const float*)d_in[5];
    const float* Wv   = (const float*)d_in[6];
    const float* bv   = (const float*)d_in[7];
    float* out = (float*)d_out;

    __half *xh, *Wqhi, *Wqlo, *Wkhi, *Wklo, *Wvhi, *Wvlo;
    __half *Qh, *Khi, *Klo, *Vthi, *Vtlo, *Af;
    float *Vf, *E, *rs, *dn;
    cudaGetSymbolAddress((void**)&xh, g_xh);
    cudaGetSymbolAddress((void**)&Wqhi, g_Wqhi); cudaGetSymbolAddress((void**)&Wqlo, g_Wqlo);
    cudaGetSymbolAddress((void**)&Wkhi, g_Wkhi); cudaGetSymbolAddress((void**)&Wklo, g_Wklo);
    cudaGetSymbolAddress((void**)&Wvhi, g_Wvhi); cudaGetSymbolAddress((void**)&Wvlo, g_Wvlo);
    cudaGetSymbolAddress((void**)&Qh, g_Qh);
    cudaGetSymbolAddress((void**)&Khi, g_Khi);   cudaGetSymbolAddress((void**)&Klo, g_Klo);
    cudaGetSymbolAddress((void**)&Vf, g_Vf);
    cudaGetSymbolAddress((void**)&Vthi, g_Vthi); cudaGetSymbolAddress((void**)&Vtlo, g_Vtlo);
    cudaGetSymbolAddress((void**)&E, g_E);
    cudaGetSymbolAddress((void**)&Af, g_Af);
    cudaGetSymbolAddress((void**)&rs, g_rowsum); cudaGetSymbolAddress((void**)&dn, g_denom);

    cudaFuncSetAttribute(gemm_f16x2, cudaFuncAttributeMaxDynamicSharedMemorySize, DYN_BYTES);

    // 0) conversions
    convert_f16<<<(MPROJ * Hd / 4 + 255) / 256, 256>>>(x, xh, MPROJ * Hd / 4);
    convert_split_f16<<<(Hd * Hd / 4 + 255) / 256, 256>>>(Wq, Wqhi, Wqlo, Hd * Hd / 4);
    convert_split_f16<<<(Hd * Hd / 4 + 255) / 256, 256>>>(Wk, Wkhi, Wklo, Hd * Hd / 4);
    convert_split_f16<<<(Hd * Hd / 4 + 255) / 256, 256>>>(Wv, Wvhi, Wvlo, Hd * Hd / 4);

    // 1) projections  M=32768 N=512 K=512
    dim3 gp(Hd / 128, MPROJ / 128, 1);
    gemm_f16x2<<<gp, 256, DYN_BYTES>>>(xh, 0, Wqhi, Wqlo, 0, Hd, 1.0f, bq, nullptr,
                                       1, nullptr, Qh, nullptr, 0, Hd);
    gemm_f16x2<<<gp, 256, DYN_BYTES>>>(xh, 0, Wkhi, Wklo, 0, Hd, 1.0f, bk, nullptr,
                                       3, nullptr, Khi, Klo, 0, Hd);
    gemm_f16x2<<<gp, 256, DYN_BYTES>>>(xh, 0, Wvhi, Wvlo, 0, Hd, 1.0f, bv, nullptr,
                                       0, Vf, nullptr, nullptr, 0, Hd);

    // 2) V transpose + split
    transpose_split<<<dim3(Sq / 32, Hd / 32, Bt), 256>>>(Vf, Vthi, Vtlo);

    // 3) energy  per batch M=N=1024 K=512, alpha = 1/sqrt(H)
    dim3 ge(Sq / 128, Sq / 128, Bt);
    gemm_f16x2<<<ge, 256, DYN_BYTES>>>(Qh, (size_t)Sq * Hd, Khi, Klo, (size_t)Sq * Hd,
                                       Hd, 1.0f / sqrtf((float)Hd), nullptr, nullptr,
                                       0, E, nullptr, nullptr, (size_t)Sq * Sq, Sq);

    // 4) softmax + mask -> A fp16 + rowsums
    softmax_mask<<<MPROJ, 256>>>(mask, E, Af, rs);
    reduce_denom<<<Bt, 256>>>(rs, dn);

    // 5) out = (A @ V) / denom   per batch M=1024 N=512 K=1024
    dim3 go(Hd / 128, Sq / 128, Bt);
    gemm_f16x2<<<go, 256, DYN_BYTES>>>(Af, (size_t)Sq * Sq, Vthi, Vtlo, (size_t)Hd * Sq,
                                       Sq, 1.0f, nullptr, dn,
                                       2, out, nullptr, nullptr, (size_t)Sq * Hd, Hd);
}

// round 12
// speedup vs baseline: 4.3374x; 1.2096x over previous
#include <cuda_runtime.h>
#include <cuda_fp16.h>
#include <math.h>
#include <stdint.h>

#define Bt 32
#define Sq 1024
#define Hd 512
#define MPROJ (Bt * Sq)

// ---------------- helpers ----------------
__device__ __forceinline__ uint32_t smem_u32(const void* p) {
    uint32_t a;
    asm("{ .reg .u64 t; cvta.to.shared.u64 t, %1; cvt.u32.u64 %0, t; }" : "=r"(a) : "l"(p));
    return a;
}
__device__ __forceinline__ void cp16(uint32_t dst, const void* src) {
    asm volatile("cp.async.cg.shared.global [%0], [%1], 16;" :: "r"(dst), "l"(src));
}
__device__ __forceinline__ void mma16816(float* d, const uint32_t* a, const uint32_t* b) {
    asm volatile(
        "mma.sync.aligned.m16n8k16.row.col.f32.f16.f16.f32 "
        "{%0,%1,%2,%3}, {%4,%5,%6,%7}, {%8,%9}, {%0,%1,%2,%3};"
        : "+f"(d[0]), "+f"(d[1]), "+f"(d[2]), "+f"(d[3])
        : "r"(a[0]), "r"(a[1]), "r"(a[2]), "r"(a[3]), "r"(b[0]), "r"(b[1]));
}
__device__ __forceinline__ void ldsm4(uint32_t addr, uint32_t* r) {
    asm volatile("ldmatrix.sync.aligned.m8n8.x4.shared.b16 {%0,%1,%2,%3}, [%4];"
                 : "=r"(r[0]), "=r"(r[1]), "=r"(r[2]), "=r"(r[3]) : "r"(addr));
}

// ---------------- scratch (device globals) ----------------
__device__ __half g_xh[(size_t)MPROJ * Hd];
__device__ __half g_Wqhi[Hd * Hd], g_Wqlo[Hd * Hd];
__device__ __half g_Wkhi[Hd * Hd], g_Wklo[Hd * Hd];
__device__ __half g_Wvhi[Hd * Hd], g_Wvlo[Hd * Hd];
__device__ __half g_Qh[(size_t)MPROJ * Hd];
__device__ __half g_Kh[(size_t)MPROJ * Hd];
__device__ float  g_Vf[(size_t)MPROJ * Hd];
__device__ __half g_Vth[(size_t)MPROJ * Hd];
__device__ float  g_E[(size_t)Bt * Sq * Sq];
__device__ __half g_Af[(size_t)Bt * Sq * Sq];
__device__ float g_rowsum[MPROJ];
__device__ float g_denom[Bt];

// ---------------- fp16 HMMA GEMM (NPASS = 1 or 2 for B hi/lo) ----------------
// C[z][m][n] = scale * sum_k A[z][m][k] * (Bhi[+Blo])[z][n][k]   (K-major, fp16)
// Tile: BM=128, BN=128, BK=32. 8 warps, warp tile 64x32. 2 CTAs/SM.
// Smem per stage (rows padded 80 B): A | Bhi [| Blo], tiles of 10240 B.
#define TILE_BYTES 10240u

template <int NPASS>
__device__ __forceinline__ void stage_chunk(
    uint32_t sbase, int t,
    const __half* __restrict__ A,
    const __half* __restrict__ Bh, const __half* __restrict__ Bl,
    int K, int k0)
{
#pragma unroll
    for (int it = 0; it < 2 * (NPASS + 1); ++it) {
        const int tile = it >> 1;
        const int within = ((it & 1) << 8) + t;   // 0..511
        const int row = within >> 2, ch = within & 3;
        const __half* src = (tile == 0) ? A : (tile == 1) ? Bh : Bl;
        cp16(sbase + (uint32_t)tile * TILE_BYTES + (uint32_t)row * 80u + (ch << 4),
             src + (size_t)row * K + k0 + (ch << 3));
    }
}

template <int NPASS>
__global__ void __launch_bounds__(256, 2) gemm_f16(
    const __half* __restrict__ A, size_t sAz,
    const __half* __restrict__ Bhi, const __half* __restrict__ Blo, size_t sBz,
    int K, float alpha, const float* __restrict__ bias, const float* __restrict__ denom,
    int mode,  // 0: fp32 out, 1: fp16 single out, 2: fp32 * (1/denom[z])
    float* __restrict__ Cf, __half* __restrict__ Ch,
    size_t sCz, int ldc)
{
    extern __shared__ __align__(16) char dyn[];
    const uint32_t STG = (uint32_t)(NPASS + 1) * TILE_BYTES;
    const int t = threadIdx.x;
    const int bm = blockIdx.y << 7;
    const int bn = blockIdx.x << 7;
    const int z = blockIdx.z;

    const __half* pA  = A   + (size_t)z * sAz + (size_t)bm * K;
    const __half* pBh = Bhi + (size_t)z * sBz + (size_t)bn * K;
    const __half* pBl = (NPASS == 2) ? (Blo + (size_t)z * sBz + (size_t)bn * K) : nullptr;

    const uint32_t sb = smem_u32(dyn);

    const int lane = t & 31, warp = t >> 5;
    const int wm = (warp & 1) << 6;      // 0 / 64
    const int wn = (warp >> 1) << 5;     // 0 / 32 / 64 / 96
    const int g = lane >> 2, q = lane & 3;

    //   A x4 (16x16): row = lane%16, k-half = lane/16
    const uint32_t aoff = (uint32_t)(lane & 15) * 80u + (uint32_t)(lane >> 4) * 16u;
    //   B x4 (two n8 x k16): n = (lane&7) + ((lane>>4)&1)*8, k-half = (lane>>3)&1
    const uint32_t boff = ((uint32_t)((lane & 7) + ((lane >> 4) & 1) * 8)) * 80u
                        + ((uint32_t)((lane >> 3) & 1)) * 16u;

    float acc[4][4][4];
#pragma unroll
    for (int i = 0; i < 4; i++)
#pragma unroll
        for (int j = 0; j < 4; j++)
#pragma unroll
            for (int k = 0; k < 4; k++) acc[i][j][k] = 0.f;

    const int NC = K >> 5;

    stage_chunk<NPASS>(sb, t, pA, pBh, pBl, K, 0);
    asm volatile("cp.async.commit_group;");

    for (int c = 0; c < NC; ++c) {
        if (c + 1 < NC) {
            stage_chunk<NPASS>(sb + ((c + 1) & 1) * STG, t, pA, pBh, pBl, K, (c + 1) << 5);
            asm volatile("cp.async.commit_group;");
            asm volatile("cp.async.wait_group 1;" ::: "memory");
        } else {
            asm volatile("cp.async.wait_group 0;" ::: "memory");
        }
        __syncthreads();

        const uint32_t bufA = sb + (c & 1) * STG;
        const uint32_t aA = bufA + (uint32_t)wm * 80u + aoff;
        const uint32_t aB = bufA + TILE_BYTES + (uint32_t)wn * 80u + boff;

#pragma unroll
        for (int ks = 0; ks < 2; ++ks) {
            const uint32_t kb = (uint32_t)ks << 5;
            uint32_t ah[4][4], bh[4][2];
#pragma unroll
            for (int i = 0; i < 4; ++i)
                ldsm4(aA + (uint32_t)(i << 4) * 80u + kb, ah[i]);
#pragma unroll
            for (int jp = 0; jp < 2; ++jp)
                ldsm4(aB + (uint32_t)(jp << 4) * 80u + kb, &bh[jp << 1][0]);
#pragma unroll
            for (int i = 0; i < 4; ++i)
#pragma unroll
                for (int j = 0; j < 4; ++j)
                    mma16816(acc[i][j], ah[i], bh[j]);
            if (NPASS == 2) {
                uint32_t bl[4][2];
#pragma unroll
                for (int jp = 0; jp < 2; ++jp)
                    ldsm4(aB + TILE_BYTES + (uint32_t)(jp << 4) * 80u + kb, &bl[jp << 1][0]);
#pragma unroll
                for (int i = 0; i < 4; ++i)
#pragma unroll
                    for (int j = 0; j < 4; ++j)
                        mma16816(acc[i][j], ah[i], bl[j]);
            }
        }
        __syncthreads();
    }

    // ---- epilogue ----
    const float sc = (mode == 2) ? (1.0f / denom[z]) : alpha;
    const size_t zoff = (size_t)z * sCz;
#pragma unroll
    for (int i = 0; i < 4; ++i) {
#pragma unroll
        for (int j = 0; j < 4; ++j) {
            const int r = bm + wm + (i << 4) + g;
            const int cix = bn + wn + (j << 3) + (q << 1);
            float v0 = acc[i][j][0] * sc, v1 = acc[i][j][1] * sc;
            float v2 = acc[i][j][2] * sc, v3 = acc[i][j][3] * sc;
            if (bias && mode != 2) {
                const float b0 = bias[cix], b1 = bias[cix + 1];
                v0 += b0; v1 += b1; v2 += b0; v3 += b1;
            }
            const size_t o0 = zoff + (size_t)r * ldc + cix;
            const size_t o1 = zoff + (size_t)(r + 8) * ldc + cix;
            if (mode == 1) {
                *(__half2*)(Ch + o0) = __floats2half2_rn(v0, v1);
                *(__half2*)(Ch + o1) = __floats2half2_rn(v2, v3);
            } else {
                float2 f0; f0.x = v0; f0.y = v1;
                float2 f1; f1.x = v2; f1.y = v3;
                *(float2*)(Cf + o0) = f0;
                *(float2*)(Cf + o1) = f1;
            }
        }
    }
}

// ---------------- aux kernels ----------------
__global__ __launch_bounds__(256) void convert_f16(
    const float* __restrict__ src, __half* __restrict__ dst, int n4)
{
    int i = blockIdx.x * 256 + threadIdx.x;
    if (i >= n4) return;
    float4 v = ((const float4*)src)[i];
    ((__half2*)dst)[2 * i]     = __floats2half2_rn(v.x, v.y);
    ((__half2*)dst)[2 * i + 1] = __floats2half2_rn(v.z, v.w);
}

__global__ __launch_bounds__(256) void convert_split_f16(
    const float* __restrict__ src, __half* __restrict__ hi,
    __half* __restrict__ lo, int n4)
{
    int i = blockIdx.x * 256 + threadIdx.x;
    if (i >= n4) return;
    float4 v = ((const float4*)src)[i];
    __half h0 = __float2half(v.x), h1 = __float2half(v.y);
    __half h2 = __float2half(v.z), h3 = __float2half(v.w);
    __half2 hp0; hp0.x = h0; hp0.y = h1;
    __half2 hp1; hp1.x = h2; hp1.y = h3;
    __half2 lp0, lp1;
    lp0.x = __float2half(v.x - __half2float(h0));
    lp0.y = __float2half(v.y - __half2float(h1));
    lp1.x = __float2half(v.z - __half2float(h2));
    lp1.y = __float2half(v.w - __half2float(h3));
    ((__half2*)hi)[2 * i] = hp0; ((__half2*)hi)[2 * i + 1] = hp1;
    ((__half2*)lo)[2 * i] = lp0; ((__half2*)lo)[2 * i + 1] = lp1;
}

// Vt[b][h][s] = V[b*1024+s][h], fp16
__global__ __launch_bounds__(256) void transpose_f16(
    const float* __restrict__ V, __half* __restrict__ Vth)
{
    __shared__ float tile[32][33];
    const int b = blockIdx.z;
    const int s0 = blockIdx.x << 5, h0 = blockIdx.y << 5;
    const int tx = threadIdx.x & 31, ty = threadIdx.x >> 5;  // 32x8
    const float* Vb = V + (size_t)b * Sq * Hd;
#pragma unroll
    for (int dy = 0; dy < 32; dy += 8)
        tile[ty + dy][tx] = Vb[(size_t)(s0 + ty + dy) * Hd + h0 + tx];
    __syncthreads();
    __half* Hb = Vth + (size_t)b * Hd * Sq;
#pragma unroll
    for (int dy = 0; dy < 32; dy += 8) {
        int h = h0 + ty + dy;
        Hb[(size_t)h * Sq + s0 + tx] = __float2half(tile[tx][ty + dy]);
    }
}

// softmax over E rows, * mask, emit A as fp16 + per-row sums
__global__ __launch_bounds__(256) void softmax_mask(
    const float* __restrict__ mask, const float* __restrict__ E,
    __half* __restrict__ Af, float* __restrict__ rowsum)
{
    const int row = blockIdx.x;
    const size_t off = (size_t)row * Sq;
    const int t = threadIdx.x;
    __shared__ float red[8];

    float4 v = ((const float4*)(E + off))[t];
    float m = fmaxf(fmaxf(v.x, v.y), fmaxf(v.z, v.w));
#pragma unroll
    for (int o = 16; o; o >>= 1) m = fmaxf(m, __shfl_xor_sync(0xffffffffu, m, o));
    if ((t & 31) == 0) red[t >> 5] = m;
    __syncthreads();
    m = red[0];
#pragma unroll
    for (int i = 1; i < 8; i++) m = fmaxf(m, red[i]);
    __syncthreads();

    float e0 = expf(v.x - m), e1 = expf(v.y - m);
    float e2 = expf(v.z - m), e3 = expf(v.w - m);
    float s = e0 + e1 + e2 + e3;
#pragma unroll
    for (int o = 16; o; o >>= 1) s += __shfl_xor_sync(0xffffffffu, s, o);
    if ((t & 31) == 0) red[t >> 5] = s;
    __syncthreads();
    float stot = red[0];
#pragma unroll
    for (int i = 1; i < 8; i++) stot += red[i];
    __syncthreads();

    const float inv = 1.0f / stot;
    float4 mk = ((const float4*)(mask + off))[t];
    float a0 = e0 * inv * mk.x, a1 = e1 * inv * mk.y;
    float a2 = e2 * inv * mk.z, a3 = e3 * inv * mk.w;

    ((__half2*)(Af + off))[2 * t]     = __floats2half2_rn(a0, a1);
    ((__half2*)(Af + off))[2 * t + 1] = __floats2half2_rn(a2, a3);

    float rs = a0 + a1 + a2 + a3;
#pragma unroll
    for (int o = 16; o; o >>= 1) rs += __shfl_xor_sync(0xffffffffu, rs, o);
    if ((t & 31) == 0) red[t >> 5] = rs;
    __syncthreads();
    if (t == 0) {
        float tot = 0.f;
#pragma unroll
        for (int i = 0; i < 8; i++) tot += red[i];
        rowsum[row] = tot;
    }
}

__global__ __launch_bounds__(256) void reduce_denom(
    const float* __restrict__ rowsum, float* __restrict__ denom)
{
    const int b = blockIdx.x;
    const int t = threadIdx.x;
    __shared__ float red[8];
    float s = 0.f;
    for (int i = t; i < Sq; i += 256) s += rowsum[(size_t)b * Sq + i];
#pragma unroll
    for (int o = 16; o; o >>= 1) s += __shfl_xor_sync(0xffffffffu, s, o);
    if ((t & 31) == 0) red[t >> 5] = s;
    __syncthreads();
    if (t == 0) {
        float tot = 0.f;
#pragma unroll
        for (int i = 0; i < 8; i++) tot += red[i];
        denom[b] = tot;
    }
}

// ---------------- launch ----------------
extern "C" void kernel_launch(void* const* d_in, const int* in_sizes, int n_in,
                              void* d_out, int out_size)
{
    const float* x    = (const float*)d_in[0];
    const float* mask = (const float*)d_in[1];
    const float* Wq   = (const float*)d_in[2];
    const float* bq   = (const float*)d_in[3];
    const float* Wk   = (const float*)d_in[4];
    const float* bk   = (const float*)d_in[5];
    const float* Wv   = (const float*)d_in[6];
    const float* bv   = (const float*)d_in[7];
    float* out = (float*)d_out;

    __half *xh, *Wqhi, *Wqlo, *Wkhi, *Wklo, *Wvhi, *Wvlo;
    __half *Qh, *Kh, *Vth, *Af;
    float *Vf, *E, *rs, *dn;
    cudaGetSymbolAddress((void**)&xh, g_xh);
    cudaGetSymbolAddress((void**)&Wqhi, g_Wqhi); cudaGetSymbolAddress((void**)&Wqlo, g_Wqlo);
    cudaGetSymbolAddress((void**)&Wkhi, g_Wkhi); cudaGetSymbolAddress((void**)&Wklo, g_Wklo);
    cudaGetSymbolAddress((void**)&Wvhi, g_Wvhi); cudaGetSymbolAddress((void**)&Wvlo, g_Wvlo);
    cudaGetSymbolAddress((void**)&Qh, g_Qh);
    cudaGetSymbolAddress((void**)&Kh, g_Kh);
    cudaGetSymbolAddress((void**)&Vf, g_Vf);
    cudaGetSymbolAddress((void**)&Vth, g_Vth);
    cudaGetSymbolAddress((void**)&E, g_E);
    cudaGetSymbolAddress((void**)&Af, g_Af);
    cudaGetSymbolAddress((void**)&rs, g_rowsum); cudaGetSymbolAddress((void**)&dn, g_denom);

    const uint32_t DYN2 = 2u * 3u * TILE_BYTES;   // 2-pass: 61440
    const uint32_t DYN1 = 2u * 2u * TILE_BYTES;   // 1-pass: 40960
    cudaFuncSetAttribute(gemm_f16<2>, cudaFuncAttributeMaxDynamicSharedMemorySize, DYN2);
    cudaFuncSetAttribute(gemm_f16<1>, cudaFuncAttributeMaxDynamicSharedMemorySize, DYN1);

    // 0) conversions
    convert_f16<<<(MPROJ * Hd / 4 + 255) / 256, 256>>>(x, xh, MPROJ * Hd / 4);
    convert_split_f16<<<(Hd * Hd / 4 + 255) / 256, 256>>>(Wq, Wqhi, Wqlo, Hd * Hd / 4);
    convert_split_f16<<<(Hd * Hd / 4 + 255) / 256, 256>>>(Wk, Wkhi, Wklo, Hd * Hd / 4);
    convert_split_f16<<<(Hd * Hd / 4 + 255) / 256, 256>>>(Wv, Wvhi, Wvlo, Hd * Hd / 4);

    // 1) projections  M=32768 N=512 K=512  (2-pass: W hi/lo)
    dim3 gp(Hd / 128, MPROJ / 128, 1);
    gemm_f16<2><<<gp, 256, DYN2>>>(xh, 0, Wqhi, Wqlo, 0, Hd, 1.0f, bq, nullptr,
                                   1, nullptr, Qh, 0, Hd);
    gemm_f16<2><<<gp, 256, DYN2>>>(xh, 0, Wkhi, Wklo, 0, Hd, 1.0f, bk, nullptr,
                                   1, nullptr, Kh, 0, Hd);
    gemm_f16<2><<<gp, 256, DYN2>>>(xh, 0, Wvhi, Wvlo, 0, Hd, 1.0f, bv, nullptr,
                                   0, Vf, nullptr, 0, Hd);

    // 2) V transpose
    transpose_f16<<<dim3(Sq / 32, Hd / 32, Bt), 256>>>(Vf, Vth);

    // 3) energy  per batch M=N=1024 K=512 (1-pass), alpha = 1/sqrt(H)
    dim3 ge(Sq / 128, Sq / 128, Bt);
    gemm_f16<1><<<ge, 256, DYN1>>>(Qh, (size_t)Sq * Hd, Kh, nullptr, (size_t)Sq * Hd,
                                   Hd, 1.0f / sqrtf((float)Hd), nullptr, nullptr,
                                   0, E, nullptr, (size_t)Sq * Sq, Sq);

    // 4) softmax + mask -> A fp16 + rowsums
    softmax_mask<<<MPROJ, 256>>>(mask, E, Af, rs);
    reduce_denom<<<Bt, 256>>>(rs, dn);

    // 5) out = (A @ V) / denom   per batch M=1024 N=512 K=1024 (1-pass)
    dim3 go(Hd / 128, Sq / 128, Bt);
    gemm_f16<1><<<go, 256, DYN1>>>(Af, (size_t)Sq * Sq, Vth, nullptr, (size_t)Hd * Sq,
                                   Sq, 1.0f, nullptr, dn,
                                   2, out, nullptr, (size_t)Sq * Hd, Hd);
}

// round 13
// speedup vs baseline: 5.6996x; 1.3141x over previous
#include <cuda_runtime.h>
#include <cuda_fp16.h>
#include <math.h>
#include <stdint.h>

#define Bt 32
#define Sq 1024
#define Hd 512
#define MPROJ (Bt * Sq)

// ---------------- helpers ----------------
__device__ __forceinline__ uint32_t smem_u32(const void* p) {
    uint32_t a;
    asm("{ .reg .u64 t; cvta.to.shared.u64 t, %1; cvt.u32.u64 %0, t; }" : "=r"(a) : "l"(p));
    return a;
}
__device__ __forceinline__ void cp16(uint32_t dst, const void* src) {
    asm volatile("cp.async.cg.shared.global [%0], [%1], 16;" :: "r"(dst), "l"(src));
}
__device__ __forceinline__ void mma16816(float* d, const uint32_t* a, const uint32_t* b) {
    asm volatile(
        "mma.sync.aligned.m16n8k16.row.col.f32.f16.f16.f32 "
        "{%0,%1,%2,%3}, {%4,%5,%6,%7}, {%8,%9}, {%0,%1,%2,%3};"
        : "+f"(d[0]), "+f"(d[1]), "+f"(d[2]), "+f"(d[3])
        : "r"(a[0]), "r"(a[1]), "r"(a[2]), "r"(a[3]), "r"(b[0]), "r"(b[1]));
}
__device__ __forceinline__ void ldsm4(uint32_t addr, uint32_t* r) {
    asm volatile("ldmatrix.sync.aligned.m8n8.x4.shared.b16 {%0,%1,%2,%3}, [%4];"
                 : "=r"(r[0]), "=r"(r[1]), "=r"(r[2]), "=r"(r[3]) : "r"(addr));
}

// ---------------- scratch (device globals) ----------------
__device__ __half g_xh[(size_t)MPROJ * Hd];
__device__ __half g_Wqh[Hd * Hd], g_Wkh[Hd * Hd], g_Wvh[Hd * Hd];
__device__ __half g_Qh[(size_t)MPROJ * Hd];
__device__ __half g_Kh[(size_t)MPROJ * Hd];
__device__ __half g_Vh[(size_t)MPROJ * Hd];
__device__ __half g_Vth[(size_t)MPROJ * Hd];
__device__ float  g_E[(size_t)Bt * Sq * Sq];
__device__ __half g_Af[(size_t)Bt * Sq * Sq];
__device__ float g_rowsum[MPROJ];
__device__ float g_denom[Bt];

// ---------------- fp16 single-pass HMMA GEMM ----------------
// C[z][m][n] = scale * sum_k A[z][m][k] * B[z][n][k]   (K-major, fp16)
// Tile: BM=128, BN=128, BK=32. 8 warps, warp tile 64x32. 2 CTAs/SM.
// 3-stage cp.async pipeline. Stage (rows padded 80 B): A | B, tiles of 10240 B.
#define TILE_BYTES 10240u
#define STG_BYTES 20480u
#define NSTG 3
#define DYN_BYTES (NSTG * STG_BYTES)

__device__ __forceinline__ void stage_chunk(
    uint32_t sbase, int t,
    const __half* __restrict__ A, const __half* __restrict__ B,
    int K, int k0)
{
#pragma unroll
    for (int it = 0; it < 4; ++it) {
        const int tile = it >> 1;                 // 0: A, 1: B
        const int within = ((it & 1) << 8) + t;   // 0..511
        const int row = within >> 2, ch = within & 3;
        const __half* src = (tile == 0) ? A : B;
        cp16(sbase + (uint32_t)tile * TILE_BYTES + (uint32_t)row * 80u + (ch << 4),
             src + (size_t)row * K + k0 + (ch << 3));
    }
}

__global__ void __launch_bounds__(256, 2) gemm_f16(
    const __half* __restrict__ A, size_t sAz,
    const __half* __restrict__ B, size_t sBz,
    int K, float alpha, const float* __restrict__ bias, const float* __restrict__ denom,
    int mode,  // 0: fp32 out (*alpha + bias), 1: fp16 out (*alpha + bias), 2: fp32 * (1/denom[z])
    float* __restrict__ Cf, __half* __restrict__ Ch,
    size_t sCz, int ldc)
{
    extern __shared__ __align__(16) char dyn[];
    const int t = threadIdx.x;
    const int bm = blockIdx.y << 7;
    const int bn = blockIdx.x << 7;
    const int z = blockIdx.z;

    const __half* pA = A + (size_t)z * sAz + (size_t)bm * K;
    const __half* pB = B + (size_t)z * sBz + (size_t)bn * K;

    const uint32_t sb = smem_u32(dyn);

    const int lane = t & 31, warp = t >> 5;
    const int wm = (warp & 1) << 6;      // 0 / 64
    const int wn = (warp >> 1) << 5;     // 0 / 32 / 64 / 96
    const int g = lane >> 2, q = lane & 3;

    //   A x4 (16x16): row = lane%16, k-half = lane/16
    const uint32_t aoff = (uint32_t)(lane & 15) * 80u + (uint32_t)(lane >> 4) * 16u;
    //   B x4 (two n8 x k16): n = (lane&7) + ((lane>>4)&1)*8, k-half = (lane>>3)&1
    const uint32_t boff = ((uint32_t)((lane & 7) + ((lane >> 4) & 1) * 8)) * 80u
                        + ((uint32_t)((lane >> 3) & 1)) * 16u;

    float acc[4][4][4];
#pragma unroll
    for (int i = 0; i < 4; i++)
#pragma unroll
        for (int j = 0; j < 4; j++)
#pragma unroll
            for (int k = 0; k < 4; k++) acc[i][j][k] = 0.f;

    const int NC = K >> 5;

    // prefill NSTG-1 stages
#pragma unroll
    for (int s = 0; s < NSTG - 1; ++s) {
        stage_chunk(sb + (uint32_t)s * STG_BYTES, t, pA, pB, K, s << 5);
        asm volatile("cp.async.commit_group;");
    }

    for (int c = 0; c < NC; ++c) {
        asm volatile("cp.async.wait_group %0;" :: "n"(NSTG - 2) : "memory");
        __syncthreads();   // chunk c resident everywhere; all warps done with chunk c-1

        const int nxt = c + NSTG - 1;
        if (nxt < NC)
            stage_chunk(sb + (uint32_t)(nxt % NSTG) * STG_BYTES, t, pA, pB, K, nxt << 5);
        asm volatile("cp.async.commit_group;");

        const uint32_t buf = sb + (uint32_t)(c % NSTG) * STG_BYTES;
        const uint32_t aA = buf + (uint32_t)wm * 80u + aoff;
        const uint32_t aB = buf + TILE_BYTES + (uint32_t)wn * 80u + boff;

#pragma unroll
        for (int ks = 0; ks < 2; ++ks) {
            const uint32_t kb = (uint32_t)ks << 5;
            uint32_t ah[4][4], bh[4][2];
#pragma unroll
            for (int i = 0; i < 4; ++i)
                ldsm4(aA + (uint32_t)(i << 4) * 80u + kb, ah[i]);
#pragma unroll
            for (int jp = 0; jp < 2; ++jp)
                ldsm4(aB + (uint32_t)(jp << 4) * 80u + kb, &bh[jp << 1][0]);
#pragma unroll
            for (int i = 0; i < 4; ++i)
#pragma unroll
                for (int j = 0; j < 4; ++j)
                    mma16816(acc[i][j], ah[i], bh[j]);
        }
    }

    // ---- epilogue ----
    const float sc = (mode == 2) ? (1.0f / denom[z]) : alpha;
    const size_t zoff = (size_t)z * sCz;
#pragma unroll
    for (int i = 0; i < 4; ++i) {
#pragma unroll
        for (int j = 0; j < 4; ++j) {
            const int r = bm + wm + (i << 4) + g;
            const int cix = bn + wn + (j << 3) + (q << 1);
            float v0 = acc[i][j][0] * sc, v1 = acc[i][j][1] * sc;
            float v2 = acc[i][j][2] * sc, v3 = acc[i][j][3] * sc;
            if (bias && mode != 2) {
                const float b0 = bias[cix], b1 = bias[cix + 1];
                v0 += b0; v1 += b1; v2 += b0; v3 += b1;
            }
            const size_t o0 = zoff + (size_t)r * ldc + cix;
            const size_t o1 = zoff + (size_t)(r + 8) * ldc + cix;
            if (mode == 1) {
                *(__half2*)(Ch + o0) = __floats2half2_rn(v0, v1);
                *(__half2*)(Ch + o1) = __floats2half2_rn(v2, v3);
            } else {
                float2 f0; f0.x = v0; f0.y = v1;
                float2 f1; f1.x = v2; f1.y = v3;
                *(float2*)(Cf + o0) = f0;
                *(float2*)(Cf + o1) = f1;
            }
        }
    }
}

// ---------------- aux kernels ----------------
__global__ __launch_bounds__(256) void convert_f16(
    const float* __restrict__ src, __half* __restrict__ dst, int n4)
{
    int i = blockIdx.x * 256 + threadIdx.x;
    if (i >= n4) return;
    float4 v = ((const float4*)src)[i];
    ((__half2*)dst)[2 * i]     = __floats2half2_rn(v.x, v.y);
    ((__half2*)dst)[2 * i + 1] = __floats2half2_rn(v.z, v.w);
}

// Vt[b][h][s] = V[b*1024+s][h], fp16 -> fp16
__global__ __launch_bounds__(256) void transpose_f16(
    const __half* __restrict__ V, __half* __restrict__ Vth)
{
    __shared__ __half tile[32][40];   // 80-byte row pitch, conflict-light
    const int b = blockIdx.z;
    const int s0 = blockIdx.x << 5, h0 = blockIdx.y << 5;
    const int tx = threadIdx.x & 31, ty = threadIdx.x >> 5;  // 32x8
    const __half* Vb = V + (size_t)b * Sq * Hd;
#pragma unroll
    for (int dy = 0; dy < 32; dy += 8)
        tile[ty + dy][tx] = Vb[(size_t)(s0 + ty + dy) * Hd + h0 + tx];
    __syncthreads();
    __half* Hb = Vth + (size_t)b * Hd * Sq;
#pragma unroll
    for (int dy = 0; dy < 32; dy += 8) {
        int h = h0 + ty + dy;
        Hb[(size_t)h * Sq + s0 + tx] = tile[tx][ty + dy];
    }
}

// softmax over E rows, * mask, emit A as fp16 + per-row sums
__global__ __launch_bounds__(256) void softmax_mask(
    const float* __restrict__ mask, const float* __restrict__ E,
    __half* __restrict__ Af, float* __restrict__ rowsum)
{
    const int row = blockIdx.x;
    const size_t off = (size_t)row * Sq;
    const int t = threadIdx.x;
    __shared__ float red[8];

    float4 v = ((const float4*)(E + off))[t];
    float m = fmaxf(fmaxf(v.x, v.y), fmaxf(v.z, v.w));
#pragma unroll
    for (int o = 16; o; o >>= 1) m = fmaxf(m, __shfl_xor_sync(0xffffffffu, m, o));
    if ((t & 31) == 0) red[t >> 5] = m;
    __syncthreads();
    m = red[0];
#pragma unroll
    for (int i = 1; i < 8; i++) m = fmaxf(m, red[i]);
    __syncthreads();

    float e0 = expf(v.x - m), e1 = expf(v.y - m);
    float e2 = expf(v.z - m), e3 = expf(v.w - m);
    float s = e0 + e1 + e2 + e3;
#pragma unroll
    for (int o = 16; o; o >>= 1) s += __shfl_xor_sync(0xffffffffu, s, o);
    if ((t & 31) == 0) red[t >> 5] = s;
    __syncthreads();
    float stot = red[0];
#pragma unroll
    for (int i = 1; i < 8; i++) stot += red[i];
    __syncthreads();

    const float inv = 1.0f / stot;
    float4 mk = ((const float4*)(mask + off))[t];
    float a0 = e0 * inv * mk.x, a1 = e1 * inv * mk.y;
    float a2 = e2 * inv * mk.z, a3 = e3 * inv * mk.w;

    ((__half2*)(Af + off))[2 * t]     = __floats2half2_rn(a0, a1);
    ((__half2*)(Af + off))[2 * t + 1] = __floats2half2_rn(a2, a3);

    float rs = a0 + a1 + a2 + a3;
#pragma unroll
    for (int o = 16; o; o >>= 1) rs += __shfl_xor_sync(0xffffffffu, rs, o);
    if ((t & 31) == 0) red[t >> 5] = rs;
    __syncthreads();
    if (t == 0) {
        float tot = 0.f;
#pragma unroll
        for (int i = 0; i < 8; i++) tot += red[i];
        rowsum[row] = tot;
    }
}

__global__ __launch_bounds__(256) void reduce_denom(
    const float* __restrict__ rowsum, float* __restrict__ denom)
{
    const int b = blockIdx.x;
    const int t = threadIdx.x;
    __shared__ float red[8];
    float s = 0.f;
    for (int i = t; i < Sq; i += 256) s += rowsum[(size_t)b * Sq + i];
#pragma unroll
    for (int o = 16; o; o >>= 1) s += __shfl_xor_sync(0xffffffffu, s, o);
    if ((t & 31) == 0) red[t >> 5] = s;
    __syncthreads();
    if (t == 0) {
        float tot = 0.f;
#pragma unroll
        for (int i = 0; i < 8; i++) tot += red[i];
        denom[b] = tot;
    }
}

// ---------------- launch ----------------
extern "C" void kernel_launch(void* const* d_in, const int* in_sizes, int n_in,
                              void* d_out, int out_size)
{
    const float* x    = (const float*)d_in[0];
    const float* mask = (const float*)d_in[1];
    const float* Wq   = (const float*)d_in[2];
    const float* bq   = (const float*)d_in[3];
    const float* Wk   = (const float*)d_in[4];
    const float* bk   = (const float*)d_in[5];
    const float* Wv   = (const float*)d_in[6];
    const float* bv   = (const float*)d_in[7];
    float* out = (float*)d_out;

    __half *xh, *Wqh, *Wkh, *Wvh, *Qh, *Kh, *Vh, *Vth, *Af;
    float *E, *rs, *dn;
    cudaGetSymbolAddress((void**)&xh, g_xh);
    cudaGetSymbolAddress((void**)&Wqh, g_Wqh);
    cudaGetSymbolAddress((void**)&Wkh, g_Wkh);
    cudaGetSymbolAddress((void**)&Wvh, g_Wvh);
    cudaGetSymbolAddress((void**)&Qh, g_Qh);
    cudaGetSymbolAddress((void**)&Kh, g_Kh);
    cudaGetSymbolAddress((void**)&Vh, g_Vh);
    cudaGetSymbolAddress((void**)&Vth, g_Vth);
    cudaGetSymbolAddress((void**)&E, g_E);
    cudaGetSymbolAddress((void**)&Af, g_Af);
    cudaGetSymbolAddress((void**)&rs, g_rowsum);
    cudaGetSymbolAddress((void**)&dn, g_denom);

    cudaFuncSetAttribute(gemm_f16, cudaFuncAttributeMaxDynamicSharedMemorySize, DYN_BYTES);

    // 0) conversions (all single fp16 now)
    convert_f16<<<(MPROJ * Hd / 4 + 255) / 256, 256>>>(x, xh, MPROJ * Hd / 4);
    convert_f16<<<(Hd * Hd / 4 + 255) / 256, 256>>>(Wq, Wqh, Hd * Hd / 4);
    convert_f16<<<(Hd * Hd / 4 + 255) / 256, 256>>>(Wk, Wkh, Hd * Hd / 4);
    convert_f16<<<(Hd * Hd / 4 + 255) / 256, 256>>>(Wv, Wvh, Hd * Hd / 4);

    // 1) projections  M=32768 N=512 K=512  (single-pass, fp16 out)
    dim3 gp(Hd / 128, MPROJ / 128, 1);
    gemm_f16<<<gp, 256, DYN_BYTES>>>(xh, 0, Wqh, 0, Hd, 1.0f, bq, nullptr,
                                     1, nullptr, Qh, 0, Hd);
    gemm_f16<<<gp, 256, DYN_BYTES>>>(xh, 0, Wkh, 0, Hd, 1.0f, bk, nullptr,
                                     1, nullptr, Kh, 0, Hd);
    gemm_f16<<<gp, 256, DYN_BYTES>>>(xh, 0, Wvh, 0, Hd, 1.0f, bv, nullptr,
                                     1, nullptr, Vh, 0, Hd);

    // 2) V transpose (fp16 -> fp16)
    transpose_f16<<<dim3(Sq / 32, Hd / 32, Bt), 256>>>(Vh, Vth);

    // 3) energy  per batch M=N=1024 K=512, alpha = 1/sqrt(H)
    dim3 ge(Sq / 128, Sq / 128, Bt);
    gemm_f16<<<ge, 256, DYN_BYTES>>>(Qh, (size_t)Sq * Hd, Kh, (size_t)Sq * Hd,
                                     Hd, 1.0f / sqrtf((float)Hd), nullptr, nullptr,
                                     0, E, nullptr, (size_t)Sq * Sq, Sq);

    // 4) softmax + mask -> A fp16 + rowsums
    softmax_mask<<<MPROJ, 256>>>(mask, E, Af, rs);
    reduce_denom<<<Bt, 256>>>(rs, dn);

    // 5) out = (A @ V) / denom   per batch M=1024 N=512 K=1024
    dim3 go(Hd / 128, Sq / 128, Bt);
    gemm_f16<<<go, 256, DYN_BYTES>>>(Af, (size_t)Sq * Sq, Vth, (size_t)Hd * Sq,
                                     Sq, 1.0f, nullptr, dn,
                                     2, out, nullptr, (size_t)Sq * Hd, Hd);
}

// round 14
// speedup vs baseline: 5.9165x; 1.0381x over previous
#include <cuda_runtime.h>
#include <cuda_fp16.h>
#include <math.h>
#include <stdint.h>

#define Bt 32
#define Sq 1024
#define Hd 512
#define MPROJ (Bt * Sq)

// ---------------- helpers ----------------
__device__ __forceinline__ uint32_t smem_u32(const void* p) {
    uint32_t a;
    asm("{ .reg .u64 t; cvta.to.shared.u64 t, %1; cvt.u32.u64 %0, t; }" : "=r"(a) : "l"(p));
    return a;
}
__device__ __forceinline__ void cp16(uint32_t dst, const void* src) {
    asm volatile("cp.async.cg.shared.global [%0], [%1], 16;" :: "r"(dst), "l"(src));
}
__device__ __forceinline__ void mma16816(float* d, const uint32_t* a, const uint32_t* b) {
    asm volatile(
        "mma.sync.aligned.m16n8k16.row.col.f32.f16.f16.f32 "
        "{%0,%1,%2,%3}, {%4,%5,%6,%7}, {%8,%9}, {%0,%1,%2,%3};"
        : "+f"(d[0]), "+f"(d[1]), "+f"(d[2]), "+f"(d[3])
        : "r"(a[0]), "r"(a[1]), "r"(a[2]), "r"(a[3]), "r"(b[0]), "r"(b[1]));
}
__device__ __forceinline__ void ldsm4(uint32_t addr, uint32_t* r) {
    asm volatile("ldmatrix.sync.aligned.m8n8.x4.shared.b16 {%0,%1,%2,%3}, [%4];"
                 : "=r"(r[0]), "=r"(r[1]), "=r"(r[2]), "=r"(r[3]) : "r"(addr));
}
__device__ __forceinline__ void ldsm4t(uint32_t addr, uint32_t* r) {
    asm volatile("ldmatrix.sync.aligned.m8n8.x4.trans.shared.b16 {%0,%1,%2,%3}, [%4];"
                 : "=r"(r[0]), "=r"(r[1]), "=r"(r[2]), "=r"(r[3]) : "r"(addr));
}

// ---------------- scratch (device globals) ----------------
__device__ __half g_xh[(size_t)MPROJ * Hd];
__device__ __half g_Wqh[Hd * Hd], g_Wkh[Hd * Hd], g_Wvh[Hd * Hd];
__device__ __half g_Qh[(size_t)MPROJ * Hd];
__device__ __half g_Kh[(size_t)MPROJ * Hd];
__device__ __half g_Vh[(size_t)MPROJ * Hd];
__device__ float  g_E[(size_t)Bt * Sq * Sq];
__device__ __half g_Af[(size_t)Bt * Sq * Sq];
__device__ float g_rowsum[MPROJ];
__device__ float g_denom[Bt];

// ---------------- fp16 single-pass HMMA GEMM ----------------
// TRANSB=0: C[z][m][n] = scale * sum_k A[z][m][k] * B[z][n][k]   (B is [n][k], ldB=K)
// TRANSB=1: C[z][m][n] = scale * sum_k A[z][m][k] * B[z][k][n]   (B is [k][n], ldB=N_total)
// Tile: BM=128, BN=128, BK=64. 8 warps, warp tile 64x32. 2 CTAs/SM. 3-stage cp.async.
// Pitches: A rows (64 fp16 = 128B) padded to 144B; trans-B rows (128 fp16 = 256B) padded to 272B.
#define A_TILE 18432u                 // 128 * 144
#define B_TILE_N 18432u               // 128 * 144
#define B_TILE_T 17408u               // 64 * 272
#define NSTG 3

template <int TRANSB>
__device__ __forceinline__ void stage_chunk(
    uint32_t sbase, int t,
    const __half* __restrict__ pA, const __half* __restrict__ pB,
    int K, int ldB, int bn, int k0)
{
    // A: 128 rows x 8 16B-chunks
#pragma unroll
    for (int it = 0; it < 4; ++it) {
        const int within = (it << 8) + t;          // 0..1023
        const int row = within >> 3, ch = within & 7;
        cp16(sbase + (uint32_t)row * 144u + (ch << 4),
             pA + (size_t)row * K + k0 + (ch << 3));
    }
    if (TRANSB) {
        // B: 64 k-rows x 16 16B-chunks (128 n values)
#pragma unroll
        for (int it = 0; it < 4; ++it) {
            const int within = (it << 8) + t;
            const int row = within >> 4, ch = within & 15;
            cp16(sbase + A_TILE + (uint32_t)row * 272u + (ch << 4),
                 pB + (size_t)(k0 + row) * ldB + bn + (ch << 3));
        }
    } else {
        // B: 128 n-rows x 8 16B-chunks
#pragma unroll
        for (int it = 0; it < 4; ++it) {
            const int within = (it << 8) + t;
            const int row = within >> 3, ch = within & 7;
            cp16(sbase + A_TILE + (uint32_t)row * 144u + (ch << 4),
                 pB + (size_t)(bn + row) * ldB + k0 + (ch << 3));
        }
    }
}

template <int TRANSB>
__global__ void __launch_bounds__(256, 2) gemm_f16(
    const __half* __restrict__ A, size_t sAz,
    const __half* __restrict__ B, size_t sBz,
    int K, int ldB, float alpha, const float* __restrict__ bias,
    const float* __restrict__ denom,
    int mode,  // 0: fp32 out (*alpha + bias), 1: fp16 out (*alpha + bias), 2: fp32 * (1/denom[z])
    float* __restrict__ Cf, __half* __restrict__ Ch,
    size_t sCz, int ldc)
{
    extern __shared__ __align__(16) char dyn[];
    const uint32_t STG = A_TILE + (TRANSB ? B_TILE_T : B_TILE_N);
    const int t = threadIdx.x;
    const int bm = blockIdx.y << 7;
    const int bn = blockIdx.x << 7;
    const int z = blockIdx.z;

    const __half* pA = A + (size_t)z * sAz + (size_t)bm * K;
    const __half* pB = B + (size_t)z * sBz;

    const uint32_t sb = smem_u32(dyn);

    const int lane = t & 31, warp = t >> 5;
    const int wm = (warp & 1) << 6;      // 0 / 64
    const int wn = (warp >> 1) << 5;     // 0 / 32 / 64 / 96
    const int g = lane >> 2, q = lane & 3;

    //   A x4 (16x16): row = lane%16, k-half = lane/16
    const uint32_t aoff = (uint32_t)(lane & 15) * 144u + (uint32_t)(lane >> 4) * 16u;
    //   B non-trans x4: n = (lane&7) + ((lane>>4)&1)*8, k-half = (lane>>3)&1
    const uint32_t boff_n = ((uint32_t)((lane & 7) + ((lane >> 4) & 1) * 8)) * 144u
                          + ((uint32_t)((lane >> 3) & 1)) * 16u;
    //   B trans x4: k-row = (lane&7) + ((lane>>3)&1)*8, n-octet = (lane>>4)&1
    const uint32_t boff_t = ((uint32_t)((lane & 7) + ((lane >> 3) & 1) * 8)) * 272u
                          + ((uint32_t)((lane >> 4) & 1)) * 16u;

    float acc[4][4][4];
#pragma unroll
    for (int i = 0; i < 4; i++)
#pragma unroll
        for (int j = 0; j < 4; j++)
#pragma unroll
            for (int k = 0; k < 4; k++) acc[i][j][k] = 0.f;

    const int NC = K >> 6;

    // prefill NSTG-1 stages
#pragma unroll
    for (int s = 0; s < NSTG - 1; ++s) {
        stage_chunk<TRANSB>(sb + (uint32_t)s * STG, t, pA, pB, K, ldB, bn, s << 6);
        asm volatile("cp.async.commit_group;");
    }

    for (int c = 0; c < NC; ++c) {
        asm volatile("cp.async.wait_group %0;" :: "n"(NSTG - 2) : "memory");
        __syncthreads();   // chunk c resident; all warps done with chunk c-1

        const int nxt = c + NSTG - 1;
        if (nxt < NC)
            stage_chunk<TRANSB>(sb + (uint32_t)(nxt % NSTG) * STG, t, pA, pB, K, ldB, bn, nxt << 6);
        asm volatile("cp.async.commit_group;");

        const uint32_t buf = sb + (uint32_t)(c % NSTG) * STG;
        const uint32_t aA = buf + (uint32_t)wm * 144u + aoff;
        const uint32_t aB = TRANSB
            ? (buf + A_TILE + (uint32_t)wn * 2u + boff_t)
            : (buf + A_TILE + (uint32_t)wn * 144u + boff_n);

#pragma unroll
        for (int ks = 0; ks < 4; ++ks) {
            uint32_t ah[4][4], bh[4][2];
#pragma unroll
            for (int i = 0; i < 4; ++i)
                ldsm4(aA + (uint32_t)(i << 4) * 144u + ((uint32_t)ks << 5), ah[i]);
            if (TRANSB) {
#pragma unroll
                for (int jp = 0; jp < 2; ++jp)
                    ldsm4t(aB + ((uint32_t)jp << 5) + (uint32_t)ks * (16u * 272u),
                           &bh[jp << 1][0]);
            } else {
#pragma unroll
                for (int jp = 0; jp < 2; ++jp)
                    ldsm4(aB + (uint32_t)(jp << 4) * 144u + ((uint32_t)ks << 5),
                          &bh[jp << 1][0]);
            }
#pragma unroll
            for (int i = 0; i < 4; ++i)
#pragma unroll
                for (int j = 0; j < 4; ++j)
                    mma16816(acc[i][j], ah[i], bh[j]);
        }
    }

    // ---- epilogue ----
    const float sc = (mode == 2) ? (1.0f / denom[z]) : alpha;
    const size_t zoff = (size_t)z * sCz;
#pragma unroll
    for (int i = 0; i < 4; ++i) {
#pragma unroll
        for (int j = 0; j < 4; ++j) {
            const int r = bm + wm + (i << 4) + g;
            const int cix = bn + wn + (j << 3) + (q << 1);
            float v0 = acc[i][j][0] * sc, v1 = acc[i][j][1] * sc;
            float v2 = acc[i][j][2] * sc, v3 = acc[i][j][3] * sc;
            if (bias && mode != 2) {
                const float b0 = bias[cix], b1 = bias[cix + 1];
                v0 += b0; v1 += b1; v2 += b0; v3 += b1;
            }
            const size_t o0 = zoff + (size_t)r * ldc + cix;
            const size_t o1 = zoff + (size_t)(r + 8) * ldc + cix;
            if (mode == 1) {
                *(__half2*)(Ch + o0) = __floats2half2_rn(v0, v1);
                *(__half2*)(Ch + o1) = __floats2half2_rn(v2, v3);
            } else {
                float2 f0; f0.x = v0; f0.y = v1;
                float2 f1; f1.x = v2; f1.y = v3;
                *(float2*)(Cf + o0) = f0;
                *(float2*)(Cf + o1) = f1;
            }
        }
    }
}

// ---------------- aux kernels ----------------
__global__ __launch_bounds__(256) void convert_f16(
    const float* __restrict__ src, __half* __restrict__ dst, int n4)
{
    int i = blockIdx.x * 256 + threadIdx.x;
    if (i >= n4) return;
    float4 v = ((const float4*)src)[i];
    ((__half2*)dst)[2 * i]     = __floats2half2_rn(v.x, v.y);
    ((__half2*)dst)[2 * i + 1] = __floats2half2_rn(v.z, v.w);
}

// softmax over E rows, * mask, emit A as fp16 + per-row sums
__global__ __launch_bounds__(256) void softmax_mask(
    const float* __restrict__ mask, const float* __restrict__ E,
    __half* __restrict__ Af, float* __restrict__ rowsum)
{
    const int row = blockIdx.x;
    const size_t off = (size_t)row * Sq;
    const int t = threadIdx.x;
    __shared__ float red[8];

    float4 v = ((const float4*)(E + off))[t];
    float m = fmaxf(fmaxf(v.x, v.y), fmaxf(v.z, v.w));
#pragma unroll
    for (int o = 16; o; o >>= 1) m = fmaxf(m, __shfl_xor_sync(0xffffffffu, m, o));
    if ((t & 31) == 0) red[t >> 5] = m;
    __syncthreads();
    m = red[0];
#pragma unroll
    for (int i = 1; i < 8; i++) m = fmaxf(m, red[i]);
    __syncthreads();

    float e0 = expf(v.x - m), e1 = expf(v.y - m);
    float e2 = expf(v.z - m), e3 = expf(v.w - m);
    float s = e0 + e1 + e2 + e3;
#pragma unroll
    for (int o = 16; o; o >>= 1) s += __shfl_xor_sync(0xffffffffu, s, o);
    if ((t & 31) == 0) red[t >> 5] = s;
    __syncthreads();
    float stot = red[0];
#pragma unroll
    for (int i = 1; i < 8; i++) stot += red[i];
    __syncthreads();

    const float inv = 1.0f / stot;
    float4 mk = ((const float4*)(mask + off))[t];
    float a0 = e0 * inv * mk.x, a1 = e1 * inv * mk.y;
    float a2 = e2 * inv * mk.z, a3 = e3 * inv * mk.w;

    ((__half2*)(Af + off))[2 * t]     = __floats2half2_rn(a0, a1);
    ((__half2*)(Af + off))[2 * t + 1] = __floats2half2_rn(a2, a3);

    float rs = a0 + a1 + a2 + a3;
#pragma unroll
    for (int o = 16; o; o >>= 1) rs += __shfl_xor_sync(0xffffffffu, rs, o);
    if ((t & 31) == 0) red[t >> 5] = rs;
    __syncthreads();
    if (t == 0) {
        float tot = 0.f;
#pragma unroll
        for (int i = 0; i < 8; i++) tot += red[i];
        rowsum[row] = tot;
    }
}

__global__ __launch_bounds__(256) void reduce_denom(
    const float* __restrict__ rowsum, float* __restrict__ denom)
{
    const int b = blockIdx.x;
    const int t = threadIdx.x;
    __shared__ float red[8];
    float s = 0.f;
    for (int i = t; i < Sq; i += 256) s += rowsum[(size_t)b * Sq + i];
#pragma unroll
    for (int o = 16; o; o >>= 1) s += __shfl_xor_sync(0xffffffffu, s, o);
    if ((t & 31) == 0) red[t >> 5] = s;
    __syncthreads();
    if (t == 0) {
        float tot = 0.f;
#pragma unroll
        for (int i = 0; i < 8; i++) tot += red[i];
        denom[b] = tot;
    }
}

// ---------------- launch ----------------
extern "C" void kernel_launch(void* const* d_in, const int* in_sizes, int n_in,
                              void* d_out, int out_size)
{
    const float* x    = (const float*)d_in[0];
    const float* mask = (const float*)d_in[1];
    const float* Wq   = (const float*)d_in[2];
    const float* bq   = (const float*)d_in[3];
    const float* Wk   = (const float*)d_in[4];
    const float* bk   = (const float*)d_in[5];
    const float* Wv   = (const float*)d_in[6];
    const float* bv   = (const float*)d_in[7];
    float* out = (float*)d_out;

    __half *xh, *Wqh, *Wkh, *Wvh, *Qh, *Kh, *Vh, *Af;
    float *E, *rs, *dn;
    cudaGetSymbolAddress((void**)&xh, g_xh);
    cudaGetSymbolAddress((void**)&Wqh, g_Wqh);
    cudaGetSymbolAddress((void**)&Wkh, g_Wkh);
    cudaGetSymbolAddress((void**)&Wvh, g_Wvh);
    cudaGetSymbolAddress((void**)&Qh, g_Qh);
    cudaGetSymbolAddress((void**)&Kh, g_Kh);
    cudaGetSymbolAddress((void**)&Vh, g_Vh);
    cudaGetSymbolAddress((void**)&E, g_E);
    cudaGetSymbolAddress((void**)&Af, g_Af);
    cudaGetSymbolAddress((void**)&rs, g_rowsum);
    cudaGetSymbolAddress((void**)&dn, g_denom);

    const uint32_t DYN_N = NSTG * (A_TILE + B_TILE_N);   // 110592
    const uint32_t DYN_T = NSTG * (A_TILE + B_TILE_T);   // 107520
    cudaFuncSetAttribute(gemm_f16<0>, cudaFuncAttributeMaxDynamicSharedMemorySize, DYN_N);
    cudaFuncSetAttribute(gemm_f16<1>, cudaFuncAttributeMaxDynamicSharedMemorySize, DYN_T);

    // 0) conversions
    convert_f16<<<(MPROJ * Hd / 4 + 255) / 256, 256>>>(x, xh, MPROJ * Hd / 4);
    convert_f16<<<(Hd * Hd / 4 + 255) / 256, 256>>>(Wq, Wqh, Hd * Hd / 4);
    convert_f16<<<(Hd * Hd / 4 + 255) / 256, 256>>>(Wk, Wkh, Hd * Hd / 4);
    convert_f16<<<(Hd * Hd / 4 + 255) / 256, 256>>>(Wv, Wvh, Hd * Hd / 4);

    // 1) projections  M=32768 N=512 K=512  (single-pass, fp16 out)
    dim3 gp(Hd / 128, MPROJ / 128, 1);
    gemm_f16<0><<<gp, 256, DYN_N>>>(xh, 0, Wqh, 0, Hd, Hd, 1.0f, bq, nullptr,
                                    1, nullptr, Qh, 0, Hd);
    gemm_f16<0><<<gp, 256, DYN_N>>>(xh, 0, Wkh, 0, Hd, Hd, 1.0f, bk, nullptr,
                                    1, nullptr, Kh, 0, Hd);
    gemm_f16<0><<<gp, 256, DYN_N>>>(xh, 0, Wvh, 0, Hd, Hd, 1.0f, bv, nullptr,
                                    1, nullptr, Vh, 0, Hd);

    // 2) energy  per batch M=N=1024 K=512, alpha = 1/sqrt(H)
    dim3 ge(Sq / 128, Sq / 128, Bt);
    gemm_f16<0><<<ge, 256, DYN_N>>>(Qh, (size_t)Sq * Hd, Kh, (size_t)Sq * Hd,
                                    Hd, Hd, 1.0f / sqrtf((float)Hd), nullptr, nullptr,
                                    0, E, nullptr, (size_t)Sq * Sq, Sq);

    // 3) softmax + mask -> A fp16 + rowsums
    softmax_mask<<<MPROJ, 256>>>(mask, E, Af, rs);
    reduce_denom<<<Bt, 256>>>(rs, dn);

    // 4) out = (A @ V) / denom   per batch M=1024 N=512 K=1024
    //    B = V in natural [s][h] layout (TRANSB), ldB = Hd
    dim3 go(Hd / 128, Sq / 128, Bt);
    gemm_f16<1><<<go, 256, DYN_T>>>(Af, (size_t)Sq * Sq, Vh, (size_t)Sq * Hd,
                                    Sq, Hd, 1.0f, nullptr, dn,
                                    2, out, nullptr, (size_t)Sq * Hd, Hd);
}

// round 15
// speedup vs baseline: 6.0688x; 1.0257x over previous
#include <cuda_runtime.h>
#include <cuda_fp16.h>
#include <math.h>
#include <stdint.h>

#define Bt 32
#define Sq 1024
#define Hd 512
#define MPROJ (Bt * Sq)

// ---------------- helpers ----------------
__device__ __forceinline__ uint32_t smem_u32(const void* p) {
    uint32_t a;
    asm("{ .reg .u64 t; cvta.to.shared.u64 t, %1; cvt.u32.u64 %0, t; }" : "=r"(a) : "l"(p));
    return a;
}
__device__ __forceinline__ void cp16(uint32_t dst, const void* src) {
    asm volatile("cp.async.cg.shared.global [%0], [%1], 16;" :: "r"(dst), "l"(src));
}
__device__ __forceinline__ void mma16816(float* d, const uint32_t* a, const uint32_t* b) {
    asm volatile(
        "mma.sync.aligned.m16n8k16.row.col.f32.f16.f16.f32 "
        "{%0,%1,%2,%3}, {%4,%5,%6,%7}, {%8,%9}, {%0,%1,%2,%3};"
        : "+f"(d[0]), "+f"(d[1]), "+f"(d[2]), "+f"(d[3])
        : "r"(a[0]), "r"(a[1]), "r"(a[2]), "r"(a[3]), "r"(b[0]), "r"(b[1]));
}
__device__ __forceinline__ void ldsm4(uint32_t addr, uint32_t* r) {
    asm volatile("ldmatrix.sync.aligned.m8n8.x4.shared.b16 {%0,%1,%2,%3}, [%4];"
                 : "=r"(r[0]), "=r"(r[1]), "=r"(r[2]), "=r"(r[3]) : "r"(addr));
}
__device__ __forceinline__ void ldsm4t(uint32_t addr, uint32_t* r) {
    asm volatile("ldmatrix.sync.aligned.m8n8.x4.trans.shared.b16 {%0,%1,%2,%3}, [%4];"
                 : "=r"(r[0]), "=r"(r[1]), "=r"(r[2]), "=r"(r[3]) : "r"(addr));
}

// ---------------- scratch (device globals) ----------------
__device__ __half g_xh[(size_t)MPROJ * Hd];
__device__ __half g_Wc[3 * Hd * Hd];          // Wq | Wk | Wv (fp16)
__device__ float  g_bc[3 * Hd];               // bq | bk | bv
__device__ __half g_QKV[3 * (size_t)MPROJ * Hd];  // Q | K | V (fp16)
__device__ __half g_Eh[(size_t)Bt * Sq * Sq];
__device__ __half g_Af[(size_t)Bt * Sq * Sq];
__device__ float g_rowsum[MPROJ];
__device__ float g_denom[Bt];

// ---------------- fp16 single-pass HMMA GEMM ----------------
// TRANSB=0: C[z][m][n] = scale * sum_k A[z][m][k] * B[z][n][k]   (B is [n][k], ldB=K)
// TRANSB=1: C[z][m][n] = scale * sum_k A[z][m][k] * B[z][k][n]   (B is [k][n], ldB=N_total)
// Tile: BM=128, BN=128, BK=64. 8 warps, warp tile 64x32. 2 CTAs/SM. 3-stage cp.async.
#define A_TILE 18432u                 // 128 * 144
#define B_TILE_N 18432u               // 128 * 144
#define B_TILE_T 17408u               // 64 * 272
#define NSTG 3

template <int TRANSB>
__device__ __forceinline__ void stage_chunk(
    uint32_t sbase, int t,
    const __half* __restrict__ pA, const __half* __restrict__ pB,
    int K, int ldB, int bn, int k0)
{
#pragma unroll
    for (int it = 0; it < 4; ++it) {
        const int within = (it << 8) + t;
        const int row = within >> 3, ch = within & 7;
        cp16(sbase + (uint32_t)row * 144u + (ch << 4),
             pA + (size_t)row * K + k0 + (ch << 3));
    }
    if (TRANSB) {
#pragma unroll
        for (int it = 0; it < 4; ++it) {
            const int within = (it << 8) + t;
            const int row = within >> 4, ch = within & 15;
            cp16(sbase + A_TILE + (uint32_t)row * 272u + (ch << 4),
                 pB + (size_t)(k0 + row) * ldB + bn + (ch << 3));
        }
    } else {
#pragma unroll
        for (int it = 0; it < 4; ++it) {
            const int within = (it << 8) + t;
            const int row = within >> 3, ch = within & 7;
            cp16(sbase + A_TILE + (uint32_t)row * 144u + (ch << 4),
                 pB + (size_t)(bn + row) * ldB + k0 + (ch << 3));
        }
    }
}

template <int TRANSB>
__global__ void __launch_bounds__(256, 2) gemm_f16(
    const __half* __restrict__ A, size_t sAz,
    const __half* __restrict__ B, size_t sBz,
    int K, int ldB, float alpha, const float* __restrict__ bias, int biasz,
    const float* __restrict__ denom,
    int mode,  // 0: fp32 out (*alpha + bias), 1: fp16 out (*alpha + bias), 2: fp32 * (1/denom[z])
    float* __restrict__ Cf, __half* __restrict__ Ch,
    size_t sCz, int ldc)
{
    extern __shared__ __align__(16) char dyn[];
    const uint32_t STG = A_TILE + (TRANSB ? B_TILE_T : B_TILE_N);
    const int t = threadIdx.x;
    const int bm = blockIdx.y << 7;
    const int bn = blockIdx.x << 7;
    const int z = blockIdx.z;

    const __half* pA = A + (size_t)z * sAz + (size_t)bm * K;
    const __half* pB = B + (size_t)z * sBz;

    const uint32_t sb = smem_u32(dyn);

    const int lane = t & 31, warp = t >> 5;
    const int wm = (warp & 1) << 6;
    const int wn = (warp >> 1) << 5;
    const int g = lane >> 2, q = lane & 3;

    const uint32_t aoff = (uint32_t)(lane & 15) * 144u + (uint32_t)(lane >> 4) * 16u;
    const uint32_t boff_n = ((uint32_t)((lane & 7) + ((lane >> 4) & 1) * 8)) * 144u
                          + ((uint32_t)((lane >> 3) & 1)) * 16u;
    const uint32_t boff_t = ((uint32_t)((lane & 7) + ((lane >> 3) & 1) * 8)) * 272u
                          + ((uint32_t)((lane >> 4) & 1)) * 16u;

    float acc[4][4][4];
#pragma unroll
    for (int i = 0; i < 4; i++)
#pragma unroll
        for (int j = 0; j < 4; j++)
#pragma unroll
            for (int k = 0; k < 4; k++) acc[i][j][k] = 0.f;

    const int NC = K >> 6;

#pragma unroll
    for (int s = 0; s < NSTG - 1; ++s) {
        stage_chunk<TRANSB>(sb + (uint32_t)s * STG, t, pA, pB, K, ldB, bn, s << 6);
        asm volatile("cp.async.commit_group;");
    }

    for (int c = 0; c < NC; ++c) {
        asm volatile("cp.async.wait_group %0;" :: "n"(NSTG - 2) : "memory");
        __syncthreads();

        const int nxt = c + NSTG - 1;
        if (nxt < NC)
            stage_chunk<TRANSB>(sb + (uint32_t)(nxt % NSTG) * STG, t, pA, pB, K, ldB, bn, nxt << 6);
        asm volatile("cp.async.commit_group;");

        const uint32_t buf = sb + (uint32_t)(c % NSTG) * STG;
        const uint32_t aA = buf + (uint32_t)wm * 144u + aoff;
        const uint32_t aB = TRANSB
            ? (buf + A_TILE + (uint32_t)wn * 2u + boff_t)
            : (buf + A_TILE + (uint32_t)wn * 144u + boff_n);

#pragma unroll
        for (int ks = 0; ks < 4; ++ks) {
            uint32_t ah[4][4], bh[4][2];
#pragma unroll
            for (int i = 0; i < 4; ++i)
                ldsm4(aA + (uint32_t)(i << 4) * 144u + ((uint32_t)ks << 5), ah[i]);
            if (TRANSB) {
#pragma unroll
                for (int jp = 0; jp < 2; ++jp)
                    ldsm4t(aB + ((uint32_t)jp << 5) + (uint32_t)ks * (16u * 272u),
                           &bh[jp << 1][0]);
            } else {
#pragma unroll
                for (int jp = 0; jp < 2; ++jp)
                    ldsm4(aB + (uint32_t)(jp << 4) * 144u + ((uint32_t)ks << 5),
                          &bh[jp << 1][0]);
            }
#pragma unroll
            for (int i = 0; i < 4; ++i)
#pragma unroll
                for (int j = 0; j < 4; ++j)
                    mma16816(acc[i][j], ah[i], bh[j]);
        }
    }

    // ---- epilogue ----
    const float sc = (mode == 2) ? (1.0f / denom[z]) : alpha;
    const size_t zoff = (size_t)z * sCz;
    const float* bz = bias ? (bias + (size_t)z * biasz) : nullptr;
#pragma unroll
    for (int i = 0; i < 4; ++i) {
#pragma unroll
        for (int j = 0; j < 4; ++j) {
            const int r = bm + wm + (i << 4) + g;
            const int cix = bn + wn + (j << 3) + (q << 1);
            float v0 = acc[i][j][0] * sc, v1 = acc[i][j][1] * sc;
            float v2 = acc[i][j][2] * sc, v3 = acc[i][j][3] * sc;
            if (bz && mode != 2) {
                const float b0 = bz[cix], b1 = bz[cix + 1];
                v0 += b0; v1 += b1; v2 += b0; v3 += b1;
            }
            const size_t o0 = zoff + (size_t)r * ldc + cix;
            const size_t o1 = zoff + (size_t)(r + 8) * ldc + cix;
            if (mode == 1) {
                *(__half2*)(Ch + o0) = __floats2half2_rn(v0, v1);
                *(__half2*)(Ch + o1) = __floats2half2_rn(v2, v3);
            } else {
                float2 f0; f0.x = v0; f0.y = v1;
                float2 f1; f1.x = v2; f1.y = v3;
                *(float2*)(Cf + o0) = f0;
                *(float2*)(Cf + o1) = f1;
            }
        }
    }
}

// ---------------- aux kernels ----------------
__global__ __launch_bounds__(256) void convert_f16(
    const float* __restrict__ src, __half* __restrict__ dst, int n4)
{
    int i = blockIdx.x * 256 + threadIdx.x;
    if (i >= n4) return;
    float4 v = ((const float4*)src)[i];
    ((__half2*)dst)[2 * i]     = __floats2half2_rn(v.x, v.y);
    ((__half2*)dst)[2 * i + 1] = __floats2half2_rn(v.z, v.w);
}

// convert all 3 weight matrices (z-indexed) + biases into combined buffers
__global__ __launch_bounds__(256) void convert_w(
    const float* __restrict__ Wq, const float* __restrict__ Wk,
    const float* __restrict__ Wv,
    const float* __restrict__ bq, const float* __restrict__ bk,
    const float* __restrict__ bv,
    __half* __restrict__ Wc, float* __restrict__ bc)
{
    const int z = blockIdx.z;
    const float* src = (z == 0) ? Wq : (z == 1) ? Wk : Wv;
    __half* dst = Wc + (size_t)z * Hd * Hd;
    int i = blockIdx.x * 256 + threadIdx.x;   // 0 .. Hd*Hd/4-1
    float4 v = ((const float4*)src)[i];
    ((__half2*)dst)[2 * i]     = __floats2half2_rn(v.x, v.y);
    ((__half2*)dst)[2 * i + 1] = __floats2half2_rn(v.z, v.w);
    if (blockIdx.x == 0 && threadIdx.x < Hd / 2) {
        const float* bs = (z == 0) ? bq : (z == 1) ? bk : bv;
        ((float2*)(bc + z * Hd))[threadIdx.x] = ((const float2*)bs)[threadIdx.x];
    }
}

// softmax over E rows (fp16 in), * mask, emit A as fp16 + per-row sums
__global__ __launch_bounds__(256) void softmax_mask(
    const float* __restrict__ mask, const __half* __restrict__ Eh,
    __half* __restrict__ Af, float* __restrict__ rowsum)
{
    const int row = blockIdx.x;
    const size_t off = (size_t)row * Sq;
    const int t = threadIdx.x;
    __shared__ float red[8];

    float2 raw = ((const float2*)(Eh + off))[t];
    __half2 h01 = *(__half2*)&raw.x;
    __half2 h23 = *(__half2*)&raw.y;
    float2 f01 = __half22float2(h01), f23 = __half22float2(h23);
    float4 v; v.x = f01.x; v.y = f01.y; v.z = f23.x; v.w = f23.y;

    float m = fmaxf(fmaxf(v.x, v.y), fmaxf(v.z, v.w));
#pragma unroll
    for (int o = 16; o; o >>= 1) m = fmaxf(m, __shfl_xor_sync(0xffffffffu, m, o));
    if ((t & 31) == 0) red[t >> 5] = m;
    __syncthreads();
    m = red[0];
#pragma unroll
    for (int i = 1; i < 8; i++) m = fmaxf(m, red[i]);
    __syncthreads();

    float e0 = expf(v.x - m), e1 = expf(v.y - m);
    float e2 = expf(v.z - m), e3 = expf(v.w - m);
    float s = e0 + e1 + e2 + e3;
#pragma unroll
    for (int o = 16; o; o >>= 1) s += __shfl_xor_sync(0xffffffffu, s, o);
    if ((t & 31) == 0) red[t >> 5] = s;
    __syncthreads();
    float stot = red[0];
#pragma unroll
    for (int i = 1; i < 8; i++) stot += red[i];
    __syncthreads();

    const float inv = 1.0f / stot;
    float4 mk = ((const float4*)(mask + off))[t];
    float a0 = e0 * inv * mk.x, a1 = e1 * inv * mk.y;
    float a2 = e2 * inv * mk.z, a3 = e3 * inv * mk.w;

    ((__half2*)(Af + off))[2 * t]     = __floats2half2_rn(a0, a1);
    ((__half2*)(Af + off))[2 * t + 1] = __floats2half2_rn(a2, a3);

    float rs = a0 + a1 + a2 + a3;
#pragma unroll
    for (int o = 16; o; o >>= 1) rs += __shfl_xor_sync(0xffffffffu, rs, o);
    if ((t & 31) == 0) red[t >> 5] = rs;
    __syncthreads();
    if (t == 0) {
        float tot = 0.f;
#pragma unroll
        for (int i = 0; i < 8; i++) tot += red[i];
        rowsum[row] = tot;
    }
}

__global__ __launch_bounds__(256) void reduce_denom(
    const float* __restrict__ rowsum, float* __restrict__ denom)
{
    const int b = blockIdx.x;
    const int t = threadIdx.x;
    __shared__ float red[8];
    float s = 0.f;
    for (int i = t; i < Sq; i += 256) s += rowsum[(size_t)b * Sq + i];
#pragma unroll
    for (int o = 16; o; o >>= 1) s += __shfl_xor_sync(0xffffffffu, s, o);
    if ((t & 31) == 0) red[t >> 5] = s;
    __syncthreads();
    if (t == 0) {
        float tot = 0.f;
#pragma unroll
        for (int i = 0; i < 8; i++) tot += red[i];
        denom[b] = tot;
    }
}

// ---------------- launch ----------------
extern "C" void kernel_launch(void* const* d_in, const int* in_sizes, int n_in,
                              void* d_out, int out_size)
{
    const float* x    = (const float*)d_in[0];
    const float* mask = (const float*)d_in[1];
    const float* Wq   = (const float*)d_in[2];
    const float* bq   = (const float*)d_in[3];
    const float* Wk   = (const float*)d_in[4];
    const float* bk   = (const float*)d_in[5];
    const float* Wv   = (const float*)d_in[6];
    const float* bv   = (const float*)d_in[7];
    float* out = (float*)d_out;

    __half *xh, *Wc, *QKV, *Eh, *Af;
    float *bc, *rs, *dn;
    cudaGetSymbolAddress((void**)&xh, g_xh);
    cudaGetSymbolAddress((void**)&Wc, g_Wc);
    cudaGetSymbolAddress((void**)&bc, g_bc);
    cudaGetSymbolAddress((void**)&QKV, g_QKV);
    cudaGetSymbolAddress((void**)&Eh, g_Eh);
    cudaGetSymbolAddress((void**)&Af, g_Af);
    cudaGetSymbolAddress((void**)&rs, g_rowsum);
    cudaGetSymbolAddress((void**)&dn, g_denom);

    const __half* Qh = QKV;
    const __half* Kh = QKV + (size_t)MPROJ * Hd;
    const __half* Vh = QKV + 2 * (size_t)MPROJ * Hd;

    const uint32_t DYN_N = NSTG * (A_TILE + B_TILE_N);
    const uint32_t DYN_T = NSTG * (A_TILE + B_TILE_T);
    cudaFuncSetAttribute(gemm_f16<0>, cudaFuncAttributeMaxDynamicSharedMemorySize, DYN_N);
    cudaFuncSetAttribute(gemm_f16<1>, cudaFuncAttributeMaxDynamicSharedMemorySize, DYN_T);

    // 0) conversions: x (big) + all W/bias in one z=3 launch
    convert_f16<<<(MPROJ * Hd / 4 + 255) / 256, 256>>>(x, xh, MPROJ * Hd / 4);
    convert_w<<<dim3(Hd * Hd / 4 / 256, 1, 3), 256>>>(Wq, Wk, Wv, bq, bk, bv, Wc, bc);

    // 1) Q/K/V projections in ONE launch: z selects weight; out strided into QKV
    dim3 gp(Hd / 128, MPROJ / 128, 3);
    gemm_f16<0><<<gp, 256, DYN_N>>>(xh, 0, Wc, (size_t)Hd * Hd,
                                    Hd, Hd, 1.0f, bc, Hd, nullptr,
                                    1, nullptr, QKV, (size_t)MPROJ * Hd, Hd);

    // 2) energy  per batch M=N=1024 K=512 -> fp16 E
    dim3 ge(Sq / 128, Sq / 128, Bt);
    gemm_f16<0><<<ge, 256, DYN_N>>>(Qh, (size_t)Sq * Hd, Kh, (size_t)Sq * Hd,
                                    Hd, Hd, 1.0f / sqrtf((float)Hd), nullptr, 0, nullptr,
                                    1, nullptr, (__half*)Eh, (size_t)Sq * Sq, Sq);

    // 3) softmax + mask -> A fp16 + rowsums
    softmax_mask<<<MPROJ, 256>>>(mask, Eh, Af, rs);
    reduce_denom<<<Bt, 256>>>(rs, dn);

    // 4) out = (A @ V) / denom   per batch M=1024 N=512 K=1024 (TRANSB V)
    dim3 go(Hd / 128, Sq / 128, Bt);
    gemm_f16<1><<<go, 256, DYN_T>>>(Af, (size_t)Sq * Sq, Vh, (size_t)Sq * Hd,
                                    Sq, Hd, 1.0f, nullptr, 0, dn,
                                    2, out, nullptr, (size_t)Sq * Hd, Hd);
}

// round 16
// speedup vs baseline: 6.2662x; 1.0325x over previous
#include <cuda_runtime.h>
#include <cuda_fp16.h>
#include <math.h>
#include <stdint.h>

#define Bt 32
#define Sq 1024
#define Hd 512
#define MPROJ (Bt * Sq)

// ---------------- helpers ----------------
__device__ __forceinline__ uint32_t smem_u32(const void* p) {
    uint32_t a;
    asm("{ .reg .u64 t; cvta.to.shared.u64 t, %1; cvt.u32.u64 %0, t; }" : "=r"(a) : "l"(p));
    return a;
}
__device__ __forceinline__ void cp16(uint32_t dst, const void* src) {
    asm volatile("cp.async.cg.shared.global [%0], [%1], 16;" :: "r"(dst), "l"(src));
}
__device__ __forceinline__ void mma16816(float* d, const uint32_t* a, const uint32_t* b) {
    asm volatile(
        "mma.sync.aligned.m16n8k16.row.col.f32.f16.f16.f32 "
        "{%0,%1,%2,%3}, {%4,%5,%6,%7}, {%8,%9}, {%0,%1,%2,%3};"
        : "+f"(d[0]), "+f"(d[1]), "+f"(d[2]), "+f"(d[3])
        : "r"(a[0]), "r"(a[1]), "r"(a[2]), "r"(a[3]), "r"(b[0]), "r"(b[1]));
}
__device__ __forceinline__ void ldsm4(uint32_t addr, uint32_t* r) {
    asm volatile("ldmatrix.sync.aligned.m8n8.x4.shared.b16 {%0,%1,%2,%3}, [%4];"
                 : "=r"(r[0]), "=r"(r[1]), "=r"(r[2]), "=r"(r[3]) : "r"(addr));
}
__device__ __forceinline__ void ldsm4t(uint32_t addr, uint32_t* r) {
    asm volatile("ldmatrix.sync.aligned.m8n8.x4.trans.shared.b16 {%0,%1,%2,%3}, [%4];"
                 : "=r"(r[0]), "=r"(r[1]), "=r"(r[2]), "=r"(r[3]) : "r"(addr));
}

// ---------------- scratch (device globals) ----------------
__device__ __half g_xh[(size_t)MPROJ * Hd];
__device__ __half g_Wc[3 * Hd * Hd];          // Wq | Wk | Wv (fp16)
__device__ float  g_bc[3 * Hd];               // bq | bk | bv
__device__ __half g_QKV[3 * (size_t)MPROJ * Hd];  // Q | K | V (fp16)
__device__ __half g_Eh[(size_t)Bt * Sq * Sq];
__device__ __half g_Af[(size_t)Bt * Sq * Sq];
__device__ float g_rowsum[MPROJ];
__device__ float g_denom[Bt];

// ---------------- fp16 single-pass HMMA GEMM ----------------
// TRANSB=0: C[z][m][n] = scale * sum_k A[z][m][k] * B[z][n][k]   (B is [n][k], ldB=K)
// TRANSB=1: C[z][m][n] = scale * sum_k A[z][m][k] * B[z][k][n]   (B is [k][n], ldB=N_total)
// Tile: BM=128, BN=128, BK=64. 4 warps (128 thr), warp tile 64x64. 2 CTAs/SM.
// 3-stage cp.async. Pitches: 144B (64 fp16 rows), trans-B 272B (128 fp16 rows).
#define A_TILE 18432u                 // 128 * 144
#define B_TILE_N 18432u               // 128 * 144
#define B_TILE_T 17408u               // 64 * 272
#define NSTG 3
#define NTHR 128

template <int TRANSB>
__device__ __forceinline__ void stage_chunk(
    uint32_t sbase, int t,
    const __half* __restrict__ pA, const __half* __restrict__ pB,
    int K, int ldB, int bn, int k0)
{
#pragma unroll
    for (int it = 0; it < 8; ++it) {
        const int within = (it << 7) + t;          // 0..1023
        const int row = within >> 3, ch = within & 7;
        cp16(sbase + (uint32_t)row * 144u + (ch << 4),
             pA + (size_t)row * K + k0 + (ch << 3));
    }
    if (TRANSB) {
#pragma unroll
        for (int it = 0; it < 8; ++it) {
            const int within = (it << 7) + t;
            const int row = within >> 4, ch = within & 15;
            cp16(sbase + A_TILE + (uint32_t)row * 272u + (ch << 4),
                 pB + (size_t)(k0 + row) * ldB + bn + (ch << 3));
        }
    } else {
#pragma unroll
        for (int it = 0; it < 8; ++it) {
            const int within = (it << 7) + t;
            const int row = within >> 3, ch = within & 7;
            cp16(sbase + A_TILE + (uint32_t)row * 144u + (ch << 4),
                 pB + (size_t)(bn + row) * ldB + k0 + (ch << 3));
        }
    }
}

template <int TRANSB>
__global__ void __launch_bounds__(NTHR, 2) gemm_f16(
    const __half* __restrict__ A, size_t sAz,
    const __half* __restrict__ B, size_t sBz,
    int K, int ldB, float alpha, const float* __restrict__ bias, int biasz,
    const float* __restrict__ denom,
    int mode,  // 0: fp32 out (*alpha + bias), 1: fp16 out (*alpha + bias), 2: fp32 * (1/denom[z])
    float* __restrict__ Cf, __half* __restrict__ Ch,
    size_t sCz, int ldc)
{
    extern __shared__ __align__(16) char dyn[];
    const uint32_t STG = A_TILE + (TRANSB ? B_TILE_T : B_TILE_N);
    const int t = threadIdx.x;
    const int bm = blockIdx.y << 7;
    const int bn = blockIdx.x << 7;
    const int z = blockIdx.z;

    const __half* pA = A + (size_t)z * sAz + (size_t)bm * K;
    const __half* pB = B + (size_t)z * sBz;

    const uint32_t sb = smem_u32(dyn);

    const int lane = t & 31, warp = t >> 5;       // 4 warps
    const int wm = (warp & 1) << 6;               // 0 / 64
    const int wn = (warp >> 1) << 6;              // 0 / 64
    const int g = lane >> 2, q = lane & 3;

    const uint32_t aoff = (uint32_t)(lane & 15) * 144u + (uint32_t)(lane >> 4) * 16u;
    const uint32_t boff_n = ((uint32_t)((lane & 7) + ((lane >> 4) & 1) * 8)) * 144u
                          + ((uint32_t)((lane >> 3) & 1)) * 16u;
    const uint32_t boff_t = ((uint32_t)((lane & 7) + ((lane >> 3) & 1) * 8)) * 272u
                          + ((uint32_t)((lane >> 4) & 1)) * 16u;

    float acc[4][8][4];
#pragma unroll
    for (int i = 0; i < 4; i++)
#pragma unroll
        for (int j = 0; j < 8; j++)
#pragma unroll
            for (int k = 0; k < 4; k++) acc[i][j][k] = 0.f;

    const int NC = K >> 6;

#pragma unroll
    for (int s = 0; s < NSTG - 1; ++s) {
        stage_chunk<TRANSB>(sb + (uint32_t)s * STG, t, pA, pB, K, ldB, bn, s << 6);
        asm volatile("cp.async.commit_group;");
    }

    for (int c = 0; c < NC; ++c) {
        asm volatile("cp.async.wait_group %0;" :: "n"(NSTG - 2) : "memory");
        __syncthreads();

        const int nxt = c + NSTG - 1;
        if (nxt < NC)
            stage_chunk<TRANSB>(sb + (uint32_t)(nxt % NSTG) * STG, t, pA, pB, K, ldB, bn, nxt << 6);
        asm volatile("cp.async.commit_group;");

        const uint32_t buf = sb + (uint32_t)(c % NSTG) * STG;
        const uint32_t aA = buf + (uint32_t)wm * 144u + aoff;
        const uint32_t aB = TRANSB
            ? (buf + A_TILE + (uint32_t)wn * 2u + boff_t)
            : (buf + A_TILE + (uint32_t)wn * 144u + boff_n);

#pragma unroll
        for (int ks = 0; ks < 4; ++ks) {
            uint32_t ah[4][4], bh[8][2];
#pragma unroll
            for (int i = 0; i < 4; ++i)
                ldsm4(aA + (uint32_t)(i << 4) * 144u + ((uint32_t)ks << 5), ah[i]);
            if (TRANSB) {
#pragma unroll
                for (int jp = 0; jp < 4; ++jp)
                    ldsm4t(aB + ((uint32_t)jp << 5) + (uint32_t)ks * (16u * 272u),
                           &bh[jp << 1][0]);
            } else {
#pragma unroll
                for (int jp = 0; jp < 4; ++jp)
                    ldsm4(aB + (uint32_t)(jp << 4) * 144u + ((uint32_t)ks << 5),
                          &bh[jp << 1][0]);
            }
#pragma unroll
            for (int i = 0; i < 4; ++i)
#pragma unroll
                for (int j = 0; j < 8; ++j)
                    mma16816(acc[i][j], ah[i], bh[j]);
        }
    }

    // ---- epilogue ----
    const float sc = (mode == 2) ? (1.0f / denom[z]) : alpha;
    const size_t zoff = (size_t)z * sCz;
    const float* bz = bias ? (bias + (size_t)z * biasz) : nullptr;
#pragma unroll
    for (int i = 0; i < 4; ++i) {
#pragma unroll
        for (int j = 0; j < 8; ++j) {
            const int r = bm + wm + (i << 4) + g;
            const int cix = bn + wn + (j << 3) + (q << 1);
            float v0 = acc[i][j][0] * sc, v1 = acc[i][j][1] * sc;
            float v2 = acc[i][j][2] * sc, v3 = acc[i][j][3] * sc;
            if (bz && mode != 2) {
                const float b0 = bz[cix], b1 = bz[cix + 1];
                v0 += b0; v1 += b1; v2 += b0; v3 += b1;
            }
            const size_t o0 = zoff + (size_t)r * ldc + cix;
            const size_t o1 = zoff + (size_t)(r + 8) * ldc + cix;
            if (mode == 1) {
                *(__half2*)(Ch + o0) = __floats2half2_rn(v0, v1);
                *(__half2*)(Ch + o1) = __floats2half2_rn(v2, v3);
            } else {
                float2 f0; f0.x = v0; f0.y = v1;
                float2 f1; f1.x = v2; f1.y = v3;
                *(float2*)(Cf + o0) = f0;
                *(float2*)(Cf + o1) = f1;
            }
        }
    }
}

// ---------------- aux kernels ----------------
__global__ __launch_bounds__(256) void convert_f16(
    const float* __restrict__ src, __half* __restrict__ dst, int n4)
{
    int i = blockIdx.x * 256 + threadIdx.x;
    if (i >= n4) return;
    float4 v = ((const float4*)src)[i];
    ((__half2*)dst)[2 * i]     = __floats2half2_rn(v.x, v.y);
    ((__half2*)dst)[2 * i + 1] = __floats2half2_rn(v.z, v.w);
}

// convert all 3 weight matrices (z-indexed) + biases into combined buffers
__global__ __launch_bounds__(256) void convert_w(
    const float* __restrict__ Wq, const float* __restrict__ Wk,
    const float* __restrict__ Wv,
    const float* __restrict__ bq, const float* __restrict__ bk,
    const float* __restrict__ bv,
    __half* __restrict__ Wc, float* __restrict__ bc)
{
    const int z = blockIdx.z;
    const float* src = (z == 0) ? Wq : (z == 1) ? Wk : Wv;
    __half* dst = Wc + (size_t)z * Hd * Hd;
    int i = blockIdx.x * 256 + threadIdx.x;
    float4 v = ((const float4*)src)[i];
    ((__half2*)dst)[2 * i]     = __floats2half2_rn(v.x, v.y);
    ((__half2*)dst)[2 * i + 1] = __floats2half2_rn(v.z, v.w);
    if (blockIdx.x == 0 && threadIdx.x < Hd / 2) {
        const float* bs = (z == 0) ? bq : (z == 1) ? bk : bv;
        ((float2*)(bc + z * Hd))[threadIdx.x] = ((const float2*)bs)[threadIdx.x];
    }
}

// softmax over E rows (fp16 in), * mask, emit A as fp16 + per-row sums
// mask load hoisted to the top so its 16B/thread is in flight during reductions
__global__ __launch_bounds__(256) void softmax_mask(
    const float* __restrict__ mask, const __half* __restrict__ Eh,
    __half* __restrict__ Af, float* __restrict__ rowsum)
{
    const int row = blockIdx.x;
    const size_t off = (size_t)row * Sq;
    const int t = threadIdx.x;
    __shared__ float red[8];

    float4 mk = ((const float4*)(mask + off))[t];     // issue first (independent)
    float2 raw = ((const float2*)(Eh + off))[t];
    __half2 h01 = *(__half2*)&raw.x;
    __half2 h23 = *(__half2*)&raw.y;
    float2 f01 = __half22float2(h01), f23 = __half22float2(h23);
    float4 v; v.x = f01.x; v.y = f01.y; v.z = f23.x; v.w = f23.y;

    float m = fmaxf(fmaxf(v.x, v.y), fmaxf(v.z, v.w));
#pragma unroll
    for (int o = 16; o; o >>= 1) m = fmaxf(m, __shfl_xor_sync(0xffffffffu, m, o));
    if ((t & 31) == 0) red[t >> 5] = m;
    __syncthreads();
    m = red[0];
#pragma unroll
    for (int i = 1; i < 8; i++) m = fmaxf(m, red[i]);
    __syncthreads();

    float e0 = expf(v.x - m), e1 = expf(v.y - m);
    float e2 = expf(v.z - m), e3 = expf(v.w - m);
    float s = e0 + e1 + e2 + e3;
#pragma unroll
    for (int o = 16; o; o >>= 1) s += __shfl_xor_sync(0xffffffffu, s, o);
    if ((t & 31) == 0) red[t >> 5] = s;
    __syncthreads();
    float stot = red[0];
#pragma unroll
    for (int i = 1; i < 8; i++) stot += red[i];
    __syncthreads();

    const float inv = 1.0f / stot;
    float a0 = e0 * inv * mk.x, a1 = e1 * inv * mk.y;
    float a2 = e2 * inv * mk.z, a3 = e3 * inv * mk.w;

    ((__half2*)(Af + off))[2 * t]     = __floats2half2_rn(a0, a1);
    ((__half2*)(Af + off))[2 * t + 1] = __floats2half2_rn(a2, a3);

    float rs = a0 + a1 + a2 + a3;
#pragma unroll
    for (int o = 16; o; o >>= 1) rs += __shfl_xor_sync(0xffffffffu, rs, o);
    if ((t & 31) == 0) red[t >> 5] = rs;
    __syncthreads();
    if (t == 0) {
        float tot = 0.f;
#pragma unroll
        for (int i = 0; i < 8; i++) tot += red[i];
        rowsum[row] = tot;
    }
}

__global__ __launch_bounds__(256) void reduce_denom(
    const float* __restrict__ rowsum, float* __restrict__ denom)
{
    const int b = blockIdx.x;
    const int t = threadIdx.x;
    __shared__ float red[8];
    float s = 0.f;
    for (int i = t; i < Sq; i += 256) s += rowsum[(size_t)b * Sq + i];
#pragma unroll
    for (int o = 16; o; o >>= 1) s += __shfl_xor_sync(0xffffffffu, s, o);
    if ((t & 31) == 0) red[t >> 5] = s;
    __syncthreads();
    if (t == 0) {
        float tot = 0.f;
#pragma unroll
        for (int i = 0; i < 8; i++) tot += red[i];
        denom[b] = tot;
    }
}

// ---------------- launch ----------------
extern "C" void kernel_launch(void* const* d_in, const int* in_sizes, int n_in,
                              void* d_out, int out_size)
{
    const float* x    = (const float*)d_in[0];
    const float* mask = (const float*)d_in[1];
    const float* Wq   = (const float*)d_in[2];
    const float* bq   = (const float*)d_in[3];
    const float* Wk   = (const float*)d_in[4];
    const float* bk   = (const float*)d_in[5];
    const float* Wv   = (const float*)d_in[6];
    const float* bv   = (const float*)d_in[7];
    float* out = (float*)d_out;

    __half *xh, *Wc, *QKV, *Eh, *Af;
    float *bc, *rs, *dn;
    cudaGetSymbolAddress((void**)&xh, g_xh);
    cudaGetSymbolAddress((void**)&Wc, g_Wc);
    cudaGetSymbolAddress((void**)&bc, g_bc);
    cudaGetSymbolAddress((void**)&QKV, g_QKV);
    cudaGetSymbolAddress((void**)&Eh, g_Eh);
    cudaGetSymbolAddress((void**)&Af, g_Af);
    cudaGetSymbolAddress((void**)&rs, g_rowsum);
    cudaGetSymbolAddress((void**)&dn, g_denom);

    const __half* Qh = QKV;
    const __half* Kh = QKV + (size_t)MPROJ * Hd;
    const __half* Vh = QKV + 2 * (size_t)MPROJ * Hd;

    const uint32_t DYN_N = NSTG * (A_TILE + B_TILE_N);
    const uint32_t DYN_T = NSTG * (A_TILE + B_TILE_T);
    cudaFuncSetAttribute(gemm_f16<0>, cudaFuncAttributeMaxDynamicSharedMemorySize, DYN_N);
    cudaFuncSetAttribute(gemm_f16<1>, cudaFuncAttributeMaxDynamicSharedMemorySize, DYN_T);

    // 0) conversions
    convert_f16<<<(MPROJ * Hd / 4 + 255) / 256, 256>>>(x, xh, MPROJ * Hd / 4);
    convert_w<<<dim3(Hd * Hd / 4 / 256, 1, 3), 256>>>(Wq, Wk, Wv, bq, bk, bv, Wc, bc);

    // 1) Q/K/V projections in ONE launch
    dim3 gp(Hd / 128, MPROJ / 128, 3);
    gemm_f16<0><<<gp, NTHR, DYN_N>>>(xh, 0, Wc, (size_t)Hd * Hd,
                                     Hd, Hd, 1.0f, bc, Hd, nullptr,
                                     1, nullptr, QKV, (size_t)MPROJ * Hd, Hd);

    // 2) energy  per batch M=N=1024 K=512 -> fp16 E
    dim3 ge(Sq / 128, Sq / 128, Bt);
    gemm_f16<0><<<ge, NTHR, DYN_N>>>(Qh, (size_t)Sq * Hd, Kh, (size_t)Sq * Hd,
                                     Hd, Hd, 1.0f / sqrtf((float)Hd), nullptr, 0, nullptr,
                                     1, nullptr, (__half*)Eh, (size_t)Sq * Sq, Sq);

    // 3) softmax + mask -> A fp16 + rowsums
    softmax_mask<<<MPROJ, 256>>>(mask, Eh, Af, rs);
    reduce_denom<<<Bt, 256>>>(rs, dn);

    // 4) out = (A @ V) / denom   per batch M=1024 N=512 K=1024 (TRANSB V)
    dim3 go(Hd / 128, Sq / 128, Bt);
    gemm_f16<1><<<go, NTHR, DYN_T>>>(Af, (size_t)Sq * Sq, Vh, (size_t)Sq * Hd,
                                     Sq, Hd, 1.0f, nullptr, 0, dn,
                                     2, out, nullptr, (size_t)Sq * Hd, Hd);
}

// round 17
// speedup vs baseline: 6.2917x; 1.0041x over previous
#include <cuda_runtime.h>
#include <cuda_fp16.h>
#include <math.h>
#include <stdint.h>

#define Bt 32
#define Sq 1024
#define Hd 512
#define MPROJ (Bt * Sq)

// ---------------- helpers ----------------
__device__ __forceinline__ uint32_t smem_u32(const void* p) {
    uint32_t a;
    asm("{ .reg .u64 t; cvta.to.shared.u64 t, %1; cvt.u32.u64 %0, t; }" : "=r"(a) : "l"(p));
    return a;
}
__device__ __forceinline__ void cp16(uint32_t dst, const void* src) {
    asm volatile("cp.async.cg.shared.global [%0], [%1], 16;" :: "r"(dst), "l"(src));
}
__device__ __forceinline__ void mma16816(float* d, const uint32_t* a, const uint32_t* b) {
    asm volatile(
        "mma.sync.aligned.m16n8k16.row.col.f32.f16.f16.f32 "
        "{%0,%1,%2,%3}, {%4,%5,%6,%7}, {%8,%9}, {%0,%1,%2,%3};"
        : "+f"(d[0]), "+f"(d[1]), "+f"(d[2]), "+f"(d[3])
        : "r"(a[0]), "r"(a[1]), "r"(a[2]), "r"(a[3]), "r"(b[0]), "r"(b[1]));
}
__device__ __forceinline__ void ldsm4(uint32_t addr, uint32_t* r) {
    asm volatile("ldmatrix.sync.aligned.m8n8.x4.shared.b16 {%0,%1,%2,%3}, [%4];"
                 : "=r"(r[0]), "=r"(r[1]), "=r"(r[2]), "=r"(r[3]) : "r"(addr));
}
__device__ __forceinline__ void ldsm4t(uint32_t addr, uint32_t* r) {
    asm volatile("ldmatrix.sync.aligned.m8n8.x4.trans.shared.b16 {%0,%1,%2,%3}, [%4];"
                 : "=r"(r[0]), "=r"(r[1]), "=r"(r[2]), "=r"(r[3]) : "r"(addr));
}

// ---------------- scratch (device globals) ----------------
__device__ __half g_xh[(size_t)MPROJ * Hd];
__device__ __half g_Wc[3 * Hd * Hd];
__device__ float  g_bc[3 * Hd];
__device__ __half g_QKV[3 * (size_t)MPROJ * Hd];
__device__ __half g_Eh[(size_t)Bt * Sq * Sq];
__device__ __half g_Af[(size_t)Bt * Sq * Sq];
__device__ float g_rowsum[MPROJ];
__device__ float g_denom[Bt];

// ---------------- fp16 single-pass HMMA GEMM ----------------
// Tile: BM=128, BN=128, BK=64. 4 warps (128 thr), warp tile 64x64. 2 CTAs/SM.
// 3-stage cp.async; fragment double-buffer across ks.
#define A_TILE 18432u                 // 128 * 144
#define B_TILE_N 18432u               // 128 * 144
#define B_TILE_T 17408u               // 64 * 272
#define NSTG 3
#define NTHR 128

template <int TRANSB>
__device__ __forceinline__ void stage_chunk(
    uint32_t sbase, int t,
    const __half* __restrict__ pA, const __half* __restrict__ pB,
    int K, int ldB, int bn, int k0)
{
#pragma unroll
    for (int it = 0; it < 8; ++it) {
        const int within = (it << 7) + t;          // 0..1023
        const int row = within >> 3, ch = within & 7;
        cp16(sbase + (uint32_t)row * 144u + (ch << 4),
             pA + (size_t)row * K + k0 + (ch << 3));
    }
    if (TRANSB) {
#pragma unroll
        for (int it = 0; it < 8; ++it) {
            const int within = (it << 7) + t;
            const int row = within >> 4, ch = within & 15;
            cp16(sbase + A_TILE + (uint32_t)row * 272u + (ch << 4),
                 pB + (size_t)(k0 + row) * ldB + bn + (ch << 3));
        }
    } else {
#pragma unroll
        for (int it = 0; it < 8; ++it) {
            const int within = (it << 7) + t;
            const int row = within >> 3, ch = within & 7;
            cp16(sbase + A_TILE + (uint32_t)row * 144u + (ch << 4),
                 pB + (size_t)(bn + row) * ldB + k0 + (ch << 3));
        }
    }
}

// load all fragments for one ks slice (12 ldsm)
template <int TRANSB>
__device__ __forceinline__ void load_frags(
    uint32_t aA, uint32_t aB, int ks, uint32_t ah[4][4], uint32_t bh[8][2])
{
#pragma unroll
    for (int i = 0; i < 4; ++i)
        ldsm4(aA + (uint32_t)(i << 4) * 144u + ((uint32_t)ks << 5), ah[i]);
    if (TRANSB) {
#pragma unroll
        for (int jp = 0; jp < 4; ++jp)
            ldsm4t(aB + ((uint32_t)jp << 5) + (uint32_t)ks * (16u * 272u),
                   &bh[jp << 1][0]);
    } else {
#pragma unroll
        for (int jp = 0; jp < 4; ++jp)
            ldsm4(aB + (uint32_t)(jp << 4) * 144u + ((uint32_t)ks << 5),
                  &bh[jp << 1][0]);
    }
}

template <int TRANSB>
__global__ void __launch_bounds__(NTHR, 2) gemm_f16(
    const __half* __restrict__ A, size_t sAz,
    const __half* __restrict__ B, size_t sBz,
    int K, int ldB, float alpha, const float* __restrict__ bias, int biasz,
    const float* __restrict__ denom,
    int mode,  // 0: fp32 out (*alpha + bias), 1: fp16 out (*alpha + bias), 2: fp32 * (1/denom[z])
    float* __restrict__ Cf, __half* __restrict__ Ch,
    size_t sCz, int ldc)
{
    extern __shared__ __align__(16) char dyn[];
    const uint32_t STG = A_TILE + (TRANSB ? B_TILE_T : B_TILE_N);
    const int t = threadIdx.x;
    const int bm = blockIdx.y << 7;
    const int bn = blockIdx.x << 7;
    const int z = blockIdx.z;

    const __half* pA = A + (size_t)z * sAz + (size_t)bm * K;
    const __half* pB = B + (size_t)z * sBz;

    const uint32_t sb = smem_u32(dyn);

    const int lane = t & 31, warp = t >> 5;
    const int wm = (warp & 1) << 6;
    const int wn = (warp >> 1) << 6;
    const int g = lane >> 2, q = lane & 3;

    const uint32_t aoff = (uint32_t)(lane & 15) * 144u + (uint32_t)(lane >> 4) * 16u;
    const uint32_t boff_n = ((uint32_t)((lane & 7) + ((lane >> 4) & 1) * 8)) * 144u
                          + ((uint32_t)((lane >> 3) & 1)) * 16u;
    const uint32_t boff_t = ((uint32_t)((lane & 7) + ((lane >> 3) & 1) * 8)) * 272u
                          + ((uint32_t)((lane >> 4) & 1)) * 16u;

    float acc[4][8][4];
#pragma unroll
    for (int i = 0; i < 4; i++)
#pragma unroll
        for (int j = 0; j < 8; j++)
#pragma unroll
            for (int k = 0; k < 4; k++) acc[i][j][k] = 0.f;

    const int NC = K >> 6;

#pragma unroll
    for (int s = 0; s < NSTG - 1; ++s) {
        stage_chunk<TRANSB>(sb + (uint32_t)s * STG, t, pA, pB, K, ldB, bn, s << 6);
        asm volatile("cp.async.commit_group;");
    }

    uint32_t ah[2][4][4], bh[2][8][2];

    for (int c = 0; c < NC; ++c) {
        asm volatile("cp.async.wait_group %0;" :: "n"(NSTG - 2) : "memory");
        __syncthreads();

        const uint32_t buf = sb + (uint32_t)(c % NSTG) * STG;
        const uint32_t aA = buf + (uint32_t)wm * 144u + aoff;
        const uint32_t aB = TRANSB
            ? (buf + A_TILE + (uint32_t)wn * 2u + boff_t)
            : (buf + A_TILE + (uint32_t)wn * 144u + boff_n);

        // (1) fragments for ks=0 FIRST — tensor work starts right after barrier
        load_frags<TRANSB>(aA, aB, 0, ah[0], bh[0]);

        // (2) THEN issue next chunk's staging burst
        const int nxt = c + NSTG - 1;
        if (nxt < NC)
            stage_chunk<TRANSB>(sb + (uint32_t)(nxt % NSTG) * STG, t, pA, pB, K, ldB, bn, nxt << 6);
        asm volatile("cp.async.commit_group;");

        // (3) ks loop with fragment double-buffer: ldsm for ks+1 issued before mma of ks
#pragma unroll
        for (int ks = 0; ks < 4; ++ks) {
            const int cur = ks & 1;
            if (ks < 3)
                load_frags<TRANSB>(aA, aB, ks + 1, ah[cur ^ 1], bh[cur ^ 1]);
#pragma unroll
            for (int i = 0; i < 4; ++i)
#pragma unroll
                for (int j = 0; j < 8; ++j)
                    mma16816(acc[i][j], ah[cur][i], bh[cur][j]);
        }
    }

    // ---- epilogue ----
    const float sc = (mode == 2) ? (1.0f / denom[z]) : alpha;
    const size_t zoff = (size_t)z * sCz;
    const float* bz = bias ? (bias + (size_t)z * biasz) : nullptr;
#pragma unroll
    for (int i = 0; i < 4; ++i) {
#pragma unroll
        for (int j = 0; j < 8; ++j) {
            const int r = bm + wm + (i << 4) + g;
            const int cix = bn + wn + (j << 3) + (q << 1);
            float v0 = acc[i][j][0] * sc, v1 = acc[i][j][1] * sc;
            float v2 = acc[i][j][2] * sc, v3 = acc[i][j][3] * sc;
            if (bz && mode != 2) {
                const float b0 = bz[cix], b1 = bz[cix + 1];
                v0 += b0; v1 += b1; v2 += b0; v3 += b1;
            }
            const size_t o0 = zoff + (size_t)r * ldc + cix;
            const size_t o1 = zoff + (size_t)(r + 8) * ldc + cix;
            if (mode == 1) {
                *(__half2*)(Ch + o0) = __floats2half2_rn(v0, v1);
                *(__half2*)(Ch + o1) = __floats2half2_rn(v2, v3);
            } else {
                float2 f0; f0.x = v0; f0.y = v1;
                float2 f1; f1.x = v2; f1.y = v3;
                *(float2*)(Cf + o0) = f0;
                *(float2*)(Cf + o1) = f1;
            }
        }
    }
}

// ---------------- aux kernels ----------------
__global__ __launch_bounds__(256) void convert_f16(
    const float* __restrict__ src, __half* __restrict__ dst, int n4)
{
    int i = blockIdx.x * 256 + threadIdx.x;
    if (i >= n4) return;
    float4 v = ((const float4*)src)[i];
    ((__half2*)dst)[2 * i]     = __floats2half2_rn(v.x, v.y);
    ((__half2*)dst)[2 * i + 1] = __floats2half2_rn(v.z, v.w);
}

__global__ __launch_bounds__(256) void convert_w(
    const float* __restrict__ Wq, const float* __restrict__ Wk,
    const float* __restrict__ Wv,
    const float* __restrict__ bq, const float* __restrict__ bk,
    const float* __restrict__ bv,
    __half* __restrict__ Wc, float* __restrict__ bc)
{
    const int z = blockIdx.z;
    const float* src = (z == 0) ? Wq : (z == 1) ? Wk : Wv;
    __half* dst = Wc + (size_t)z * Hd * Hd;
    int i = blockIdx.x * 256 + threadIdx.x;
    float4 v = ((const float4*)src)[i];
    ((__half2*)dst)[2 * i]     = __floats2half2_rn(v.x, v.y);
    ((__half2*)dst)[2 * i + 1] = __floats2half2_rn(v.z, v.w);
    if (blockIdx.x == 0 && threadIdx.x < Hd / 2) {
        const float* bs = (z == 0) ? bq : (z == 1) ? bk : bv;
        ((float2*)(bc + z * Hd))[threadIdx.x] = ((const float2*)bs)[threadIdx.x];
    }
}

__global__ __launch_bounds__(256) void softmax_mask(
    const float* __restrict__ mask, const __half* __restrict__ Eh,
    __half* __restrict__ Af, float* __restrict__ rowsum)
{
    const int row = blockIdx.x;
    const size_t off = (size_t)row * Sq;
    const int t = threadIdx.x;
    __shared__ float red[8];

    float4 mk = ((const float4*)(mask + off))[t];
    float2 raw = ((const float2*)(Eh + off))[t];
    __half2 h01 = *(__half2*)&raw.x;
    __half2 h23 = *(__half2*)&raw.y;
    float2 f01 = __half22float2(h01), f23 = __half22float2(h23);
    float4 v; v.x = f01.x; v.y = f01.y; v.z = f23.x; v.w = f23.y;

    float m = fmaxf(fmaxf(v.x, v.y), fmaxf(v.z, v.w));
#pragma unroll
    for (int o = 16; o; o >>= 1) m = fmaxf(m, __shfl_xor_sync(0xffffffffu, m, o));
    if ((t & 31) == 0) red[t >> 5] = m;
    __syncthreads();
    m = red[0];
#pragma unroll
    for (int i = 1; i < 8; i++) m = fmaxf(m, red[i]);
    __syncthreads();

    float e0 = expf(v.x - m), e1 = expf(v.y - m);
    float e2 = expf(v.z - m), e3 = expf(v.w - m);
    float s = e0 + e1 + e2 + e3;
#pragma unroll
    for (int o = 16; o; o >>= 1) s += __shfl_xor_sync(0xffffffffu, s, o);
    if ((t & 31) == 0) red[t >> 5] = s;
    __syncthreads();
    float stot = red[0];
#pragma unroll
    for (int i = 1; i < 8; i++) stot += red[i];
    __syncthreads();

    const float inv = 1.0f / stot;
    float a0 = e0 * inv * mk.x, a1 = e1 * inv * mk.y;
    float a2 = e2 * inv * mk.z, a3 = e3 * inv * mk.w;

    ((__half2*)(Af + off))[2 * t]     = __floats2half2_rn(a0, a1);
    ((__half2*)(Af + off))[2 * t + 1] = __floats2half2_rn(a2, a3);

    float rs = a0 + a1 + a2 + a3;
#pragma unroll
    for (int o = 16; o; o >>= 1) rs += __shfl_xor_sync(0xffffffffu, rs, o);
    if ((t & 31) == 0) red[t >> 5] = rs;
    __syncthreads();
    if (t == 0) {
        float tot = 0.f;
#pragma unroll
        for (int i = 0; i < 8; i++) tot += red[i];
        rowsum[row] = tot;
    }
}

__global__ __launch_bounds__(256) void reduce_denom(
    const float* __restrict__ rowsum, float* __restrict__ denom)
{
    const int b = blockIdx.x;
    const int t = threadIdx.x;
    __shared__ float red[8];
    float s = 0.f;
    for (int i = t; i < Sq; i += 256) s += rowsum[(size_t)b * Sq + i];
#pragma unroll
    for (int o = 16; o; o >>= 1) s += __shfl_xor_sync(0xffffffffu, s, o);
    if ((t & 31) == 0) red[t >> 5] = s;
    __syncthreads();
    if (t == 0) {
        float tot = 0.f;
#pragma unroll
        for (int i = 0; i < 8; i++) tot += red[i];
        denom[b] = tot;
    }
}

// ---------------- launch ----------------
extern "C" void kernel_launch(void* const* d_in, const int* in_sizes, int n_in,
                              void* d_out, int out_size)
{
    const float* x    = (const float*)d_in[0];
    const float* mask = (const float*)d_in[1];
    const float* Wq   = (const float*)d_in[2];
    const float* bq   = (const float*)d_in[3];
    const float* Wk   = (const float*)d_in[4];
    const float* bk   = (const float*)d_in[5];
    const float* Wv   = (const float*)d_in[6];
    const float* bv   = (const float*)d_in[7];
    float* out = (float*)d_out;

    __half *xh, *Wc, *QKV, *Eh, *Af;
    float *bc, *rs, *dn;
    cudaGetSymbolAddress((void**)&xh, g_xh);
    cudaGetSymbolAddress((void**)&Wc, g_Wc);
    cudaGetSymbolAddress((void**)&bc, g_bc);
    cudaGetSymbolAddress((void**)&QKV, g_QKV);
    cudaGetSymbolAddress((void**)&Eh, g_Eh);
    cudaGetSymbolAddress((void**)&Af, g_Af);
    cudaGetSymbolAddress((void**)&rs, g_rowsum);
    cudaGetSymbolAddress((void**)&dn, g_denom);

    const __half* Qh = QKV;
    const __half* Kh = QKV + (size_t)MPROJ * Hd;
    const __half* Vh = QKV + 2 * (size_t)MPROJ * Hd;

    const uint32_t DYN_N = NSTG * (A_TILE + B_TILE_N);
    const uint32_t DYN_T = NSTG * (A_TILE + B_TILE_T);
    cudaFuncSetAttribute(gemm_f16<0>, cudaFuncAttributeMaxDynamicSharedMemorySize, DYN_N);
    cudaFuncSetAttribute(gemm_f16<1>, cudaFuncAttributeMaxDynamicSharedMemorySize, DYN_T);

    // 0) conversions
    convert_f16<<<(MPROJ * Hd / 4 + 255) / 256, 256>>>(x, xh, MPROJ * Hd / 4);
    convert_w<<<dim3(Hd * Hd / 4 / 256, 1, 3), 256>>>(Wq, Wk, Wv, bq, bk, bv, Wc, bc);

    // 1) Q/K/V projections in ONE launch
    dim3 gp(Hd / 128, MPROJ / 128, 3);
    gemm_f16<0><<<gp, NTHR, DYN_N>>>(xh, 0, Wc, (size_t)Hd * Hd,
                                     Hd, Hd, 1.0f, bc, Hd, nullptr,
                                     1, nullptr, QKV, (size_t)MPROJ * Hd, Hd);

    // 2) energy  per batch M=N=1024 K=512 -> fp16 E
    dim3 ge(Sq / 128, Sq / 128, Bt);
    gemm_f16<0><<<ge, NTHR, DYN_N>>>(Qh, (size_t)Sq * Hd, Kh, (size_t)Sq * Hd,
                                     Hd, Hd, 1.0f / sqrtf((float)Hd), nullptr, 0, nullptr,
                                     1, nullptr, (__half*)Eh, (size_t)Sq * Sq, Sq);

    // 3) softmax + mask -> A fp16 + rowsums
    softmax_mask<<<MPROJ, 256>>>(mask, Eh, Af, rs);
    reduce_denom<<<Bt, 256>>>(rs, dn);

    // 4) out = (A @ V) / denom   per batch M=1024 N=512 K=1024 (TRANSB V)
    dim3 go(Hd / 128, Sq / 128, Bt);
    gemm_f16<1><<<go, NTHR, DYN_T>>>(Af, (size_t)Sq * Sq, Vh, (size_t)Sq * Hd,
                                     Sq, Hd, 1.0f, nullptr, 0, dn,
                                     2, out, nullptr, (size_t)Sq * Hd, Hd);
}